// round 6
// baseline (speedup 1.0000x reference)
#include <cuda_runtime.h>
#include <cuda_bf16.h>
#include <math.h>

#define B_   4
#define L_   2048
#define D_   512
#define S_   256
#define NL_  6
#define H_   8
#define DH_  64
#define WIN_ 256

// ---------------- scratch (device globals; no allocation) ----------------
__device__ float g_U[B_*L_*S_];            // mamba u (fp32)
__device__ float g_X[B_*L_*D_];            // out-proj fp32 scratch
__device__ float g_HT[B_*S_];
__device__ float g_STATE[B_*D_];
__device__ float g_PART[64][B_][S_];

__device__ __nv_bfloat16 g_Xh[B_*L_*D_],    g_Xl[B_*L_*D_];     // conv output
__device__ __nv_bfloat16 g_SEQh[B_*L_*D_],  g_SEQl[B_*L_*D_];   // ln output (attn input)
__device__ __nv_bfloat16 g_QKVh[B_*L_*3*D_], g_QKVl[B_*L_*3*D_];
__device__ __nv_bfloat16 g_ATTh[B_*L_*D_],  g_ATTl[B_*L_*D_];
__device__ __nv_bfloat16 g_Wxh[NL_*S_*D_],  g_Wxl[NL_*S_*D_];   // [S][D] (transposed)
__device__ __nv_bfloat16 g_Wqkvh[3*D_*D_],  g_Wqkvl[3*D_*D_];   // [3D][D]
__device__ __nv_bfloat16 g_Woh[D_*D_],      g_Wol[D_*D_];       // [D][D]

// ---------------- helpers ----------------
__device__ __forceinline__ void cvt2(float x, __nv_bfloat16& h, __nv_bfloat16& l) {
    h = __float2bfloat16(x);
    l = __float2bfloat16(x - __bfloat162float(h));
}
__device__ __forceinline__ void ldsm4(unsigned& r0, unsigned& r1, unsigned& r2, unsigned& r3, unsigned addr) {
    asm volatile("ldmatrix.sync.aligned.m8n8.x4.shared.b16 {%0,%1,%2,%3},[%4];"
                 : "=r"(r0), "=r"(r1), "=r"(r2), "=r"(r3) : "r"(addr));
}
__device__ __forceinline__ void ldsm4t(unsigned& r0, unsigned& r1, unsigned& r2, unsigned& r3, unsigned addr) {
    asm volatile("ldmatrix.sync.aligned.m8n8.x4.trans.shared.b16 {%0,%1,%2,%3},[%4];"
                 : "=r"(r0), "=r"(r1), "=r"(r2), "=r"(r3) : "r"(addr));
}
__device__ __forceinline__ void mma16816(float* c, const unsigned* a, const unsigned* b) {
    asm volatile("mma.sync.aligned.m16n8k16.row.col.f32.bf16.bf16.f32 "
                 "{%0,%1,%2,%3},{%4,%5,%6,%7},{%8,%9},{%0,%1,%2,%3};"
                 : "+f"(c[0]), "+f"(c[1]), "+f"(c[2]), "+f"(c[3])
                 : "r"(a[0]), "r"(a[1]), "r"(a[2]), "r"(a[3]), "r"(b[0]), "r"(b[1]));
}
__device__ __forceinline__ unsigned pack_bf16x2(float x, float y) {
    __nv_bfloat162 p;
    p.x = __float2bfloat16(x);
    p.y = __float2bfloat16(y);
    return *(unsigned*)&p;
}
__device__ __forceinline__ void cpa16(unsigned d, const void* s) {
    asm volatile("cp.async.cg.shared.global [%0],[%1],16;" :: "r"(d), "l"(s));
}
__device__ __forceinline__ void cpa_commit() {
    asm volatile("cp.async.commit_group;");
}
template <int N>
__device__ __forceinline__ void cpa_wait() {
    asm volatile("cp.async.wait_group %0;" :: "n"(N));
}

// ---------------- misc small kernels ----------------
__global__ void zero_state_kernel() {
    int t = blockIdx.x * blockDim.x + threadIdx.x;
    if (t < B_ * D_) g_STATE[t] = 0.f;
}

// W[K][N] fp32 -> Wh/Wl[N][K] bf16 (transpose)
__global__ void cvt_weight_T(const float* __restrict__ W,
                             __nv_bfloat16* __restrict__ Wh, __nv_bfloat16* __restrict__ Wl,
                             int N, int K) {
    int t = blockIdx.x * 256 + threadIdx.x;
    if (t >= N * K) return;
    int n = t / K, k = t - n * K;
    __nv_bfloat16 h, l;
    cvt2(W[(size_t)k * N + n], h, l);
    Wh[t] = h; Wl[t] = l;
}
// W[N][K] fp32 -> Wh/Wl[N][K]
__global__ void cvt_weight(const float* __restrict__ W,
                           __nv_bfloat16* __restrict__ Wh, __nv_bfloat16* __restrict__ Wl,
                           int NK) {
    int t = blockIdx.x * 256 + threadIdx.x;
    if (t >= NK) return;
    __nv_bfloat16 h, l;
    cvt2(W[t], h, l);
    Wh[t] = h; Wl[t] = l;
}

// ---------------- conv (k=3, causal) + SiLU -> bf16 hi/lo ----------------
__global__ void conv_silu_kernel(const float* __restrict__ seq,
                                 const float* __restrict__ cw) {
    int row = blockIdx.x;
    int l = row & (L_ - 1);
    int t = threadIdx.x;             // 128
    float4 z = make_float4(0.f, 0.f, 0.f, 0.f);
    float4 a0 = (l >= 2) ? ((const float4*)(seq + (size_t)(row - 2) * D_))[t] : z;
    float4 a1 = (l >= 1) ? ((const float4*)(seq + (size_t)(row - 1) * D_))[t] : z;
    float4 a2 = ((const float4*)(seq + (size_t)row * D_))[t];
    float4 w0 = ((const float4*)(cw        ))[t];
    float4 w1 = ((const float4*)(cw +   D_ ))[t];
    float4 w2 = ((const float4*)(cw + 2*D_ ))[t];
    float4 x;
    x.x = w0.x*a0.x + w1.x*a1.x + w2.x*a2.x;
    x.y = w0.y*a0.y + w1.y*a1.y + w2.y*a2.y;
    x.z = w0.z*a0.z + w1.z*a1.z + w2.z*a2.z;
    x.w = w0.w*a0.w + w1.w*a1.w + w2.w*a2.w;
    x.x = x.x / (1.f + __expf(-x.x));
    x.y = x.y / (1.f + __expf(-x.y));
    x.z = x.z / (1.f + __expf(-x.z));
    x.w = x.w / (1.f + __expf(-x.w));
    __nv_bfloat16 h0, l0, h1, l1, h2, l2, h3, l3;
    cvt2(x.x, h0, l0); cvt2(x.y, h1, l1); cvt2(x.z, h2, l2); cvt2(x.w, h3, l3);
    size_t o = (size_t)row * D_ + t * 4;
    __nv_bfloat162 p;
    p.x = h0; p.y = h1; *(__nv_bfloat162*)&g_Xh[o] = p;
    p.x = h2; p.y = h3; *(__nv_bfloat162*)&g_Xh[o + 2] = p;
    p.x = l0; p.y = l1; *(__nv_bfloat162*)&g_Xl[o] = p;
    p.x = l2; p.y = l3; *(__nv_bfloat162*)&g_Xl[o + 2] = p;
}

// ---------------- cp.async double-buffered bf16x3 GEMM ----------------
// A hi/lo [M][K] bf16, B hi/lo [N][K] bf16.  C fp32 (or Ch/Cl bf16 split).
#define GSTR 40
#define G_AH 0
#define G_AL (128*GSTR)
#define G_BH (256*GSTR)
#define G_BL (320*GSTR)
#define G_STAGE (384*GSTR)
extern __shared__ __nv_bfloat16 sg[];

__global__ void __launch_bounds__(256) mma_gemm2(const __nv_bfloat16* __restrict__ Ahg,
                                                 const __nv_bfloat16* __restrict__ Alg,
                                                 const __nv_bfloat16* __restrict__ Bhg,
                                                 const __nv_bfloat16* __restrict__ Blg,
                                                 const float* __restrict__ bias,
                                                 float* __restrict__ C,
                                                 __nv_bfloat16* __restrict__ Ch,
                                                 __nv_bfloat16* __restrict__ Cl,
                                                 int M, int N, int K) {
    int bm = blockIdx.y * 128, bn = blockIdx.x * 64;
    int tid = threadIdx.x;
    int lane = tid & 31, wid = tid >> 5;
    int wm = (wid & 3) * 32;
    int wn = (wid >> 2) * 32;

    unsigned sbase = (unsigned)__cvta_generic_to_shared(sg);

    float acc[2][4][4];
#pragma unroll
    for (int i = 0; i < 2; i++)
#pragma unroll
        for (int j = 0; j < 4; j++)
#pragma unroll
            for (int k = 0; k < 4; k++) acc[i][j][k] = 0.f;

    int nk = K >> 5;
    // issue stage for k-tile kt into buffer (kt&1)
    auto issue = [&](int kt) {
        unsigned base = sbase + (unsigned)((kt & 1) * G_STAGE) * 2u;
        int k0 = kt << 5;
#pragma unroll
        for (int j = 0; j < 2; j++) {
            int ch = tid + 256 * j;
            int r = ch >> 2, c = (ch & 3) * 8;
            unsigned doff = (unsigned)(r * GSTR + c) * 2u;
            cpa16(base + doff,            Ahg + (size_t)(bm + r) * K + k0 + c);
            cpa16(base + G_AL * 2 + doff, Alg + (size_t)(bm + r) * K + k0 + c);
        }
        {
            int r = tid >> 2, c = (tid & 3) * 8;
            unsigned doff = (unsigned)(r * GSTR + c) * 2u;
            cpa16(base + G_BH * 2 + doff, Bhg + (size_t)(bn + r) * K + k0 + c);
            cpa16(base + G_BL * 2 + doff, Blg + (size_t)(bn + r) * K + k0 + c);
        }
        cpa_commit();
    };

    issue(0);
    for (int kt = 0; kt < nk; kt++) {
        if (kt + 1 < nk) { issue(kt + 1); cpa_wait<1>(); }
        else             { cpa_wait<0>(); }
        __syncthreads();

        unsigned base = sbase + (unsigned)((kt & 1) * G_STAGE) * 2u;
#pragma unroll
        for (int ks = 0; ks < 2; ks++) {
            unsigned afh[2][4], afl[2][4], bfh[4][2], bfl[4][2];
#pragma unroll
            for (int mi = 0; mi < 2; mi++) {
                int row = wm + mi * 16 + (lane & 15);
                unsigned off = (unsigned)(row * GSTR + ks * 16 + (lane >> 4) * 8) * 2u;
                ldsm4(afh[mi][0], afh[mi][1], afh[mi][2], afh[mi][3], base + off);
                ldsm4(afl[mi][0], afl[mi][1], afl[mi][2], afl[mi][3], base + G_AL * 2 + off);
            }
#pragma unroll
            for (int nh = 0; nh < 2; nh++) {
                int row = wn + nh * 16 + (lane & 15);
                unsigned off = (unsigned)(row * GSTR + ks * 16 + (lane >> 4) * 8) * 2u;
                unsigned r0, r1, r2, r3;
                ldsm4(r0, r1, r2, r3, base + G_BH * 2 + off);
                bfh[nh*2+0][0] = r0; bfh[nh*2+0][1] = r2;
                bfh[nh*2+1][0] = r1; bfh[nh*2+1][1] = r3;
                ldsm4(r0, r1, r2, r3, base + G_BL * 2 + off);
                bfl[nh*2+0][0] = r0; bfl[nh*2+0][1] = r2;
                bfl[nh*2+1][0] = r1; bfl[nh*2+1][1] = r3;
            }
#pragma unroll
            for (int mi = 0; mi < 2; mi++)
#pragma unroll
                for (int ni = 0; ni < 4; ni++) {
                    mma16816(acc[mi][ni], afh[mi], bfh[ni]);
                    mma16816(acc[mi][ni], afh[mi], bfl[ni]);
                    mma16816(acc[mi][ni], afl[mi], bfh[ni]);
                }
        }
        __syncthreads();
    }

#pragma unroll
    for (int mi = 0; mi < 2; mi++)
#pragma unroll
        for (int ni = 0; ni < 4; ni++) {
            int r = bm + wm + mi * 16 + (lane >> 2);
            int c = bn + wn + ni * 8 + (lane & 3) * 2;
            float b0 = bias ? bias[c] : 0.f;
            float b1 = bias ? bias[c + 1] : 0.f;
            float v00 = acc[mi][ni][0] + b0, v01 = acc[mi][ni][1] + b1;
            float v10 = acc[mi][ni][2] + b0, v11 = acc[mi][ni][3] + b1;
            if (Ch) {
                __nv_bfloat16 h, l;
                __nv_bfloat162 ph, pl;
                cvt2(v00, h, l); ph.x = h; pl.x = l;
                cvt2(v01, h, l); ph.y = h; pl.y = l;
                *(__nv_bfloat162*)&Ch[(size_t)r * N + c] = ph;
                *(__nv_bfloat162*)&Cl[(size_t)r * N + c] = pl;
                cvt2(v10, h, l); ph.x = h; pl.x = l;
                cvt2(v11, h, l); ph.y = h; pl.y = l;
                *(__nv_bfloat162*)&Ch[(size_t)(r + 8) * N + c] = ph;
                *(__nv_bfloat162*)&Cl[(size_t)(r + 8) * N + c] = pl;
            } else {
                C[(size_t)r * N + c]           = v00;
                C[(size_t)r * N + c + 1]       = v01;
                C[(size_t)(r + 8) * N + c]     = v10;
                C[(size_t)(r + 8) * N + c + 1] = v11;
            }
        }
}

// ---------------- ssm chunked Horner with decay skip ----------------
__global__ void ht_part_kernel(const float* __restrict__ Aparam) {
    int b = blockIdx.x, c = blockIdx.y;   // 64 chunks of 32
    int s = threadIdx.x;                  // 256
    float a = 1.f / (1.f + expf(-Aparam[s]));
    float wt = powf(a, (float)(32 * (63 - c)));
    float wmax = wt;
    for (int off = 16; off; off >>= 1)
        wmax = fmaxf(wmax, __shfl_xor_sync(0xffffffffu, wmax, off));
    if (wmax < 1e-28f) { g_PART[c][b][s] = 0.f; return; }
    const float* base = g_U + ((size_t)(b * L_) + c * 32) * S_ + s;
    float p = 0.f;
#pragma unroll
    for (int j = 0; j < 32; j++) p = p * a + base[(size_t)j * S_];
    g_PART[c][b][s] = p * wt;
}

__global__ void ht_combine_kernel(const float* __restrict__ Aparam,
                                  const float* __restrict__ Wh) {
    int b = blockIdx.x;
    int s = threadIdx.x;   // 256
    float a = 1.f / (1.f + expf(-Aparam[s]));
    float h0 = 0.f;
#pragma unroll 8
    for (int d = 0; d < D_; d++) h0 += g_STATE[b * D_ + d] * Wh[(size_t)d * S_ + s];
    float sum = 0.f;
#pragma unroll
    for (int c = 0; c < 64; c++) sum += g_PART[c][b][s];
    g_HT[b * S_ + s] = powf(a, (float)L_) * h0 + sum;
}

__global__ void stateout_kernel(const float* __restrict__ Wout) {
    __shared__ float ht[S_];
    int b = blockIdx.x;
    int d = threadIdx.x;   // 512
    if (d < S_) ht[d] = g_HT[b * S_ + d];
    __syncthreads();
    float acc = 0.f;
#pragma unroll 8
    for (int s = 0; s < S_; s++) acc += ht[s] * Wout[(size_t)s * D_ + d];
    g_STATE[b * D_ + d] = acc;
}

// ---------------- residual + LayerNorm (optional bf16 split output) ------
__global__ void ln_kernel(const float* __restrict__ seq, const float* __restrict__ add,
                          const float* __restrict__ gamma, const float* __restrict__ beta,
                          float* __restrict__ out, int bcast, int writebf) {
    __shared__ float red[4];
    __shared__ float stat;
    int row = blockIdx.x;
    int b = row >> 11;
    int t = threadIdx.x;   // 128
    float4 x = ((const float4*)(seq + (size_t)row * D_))[t];
    const float* ap = bcast ? (g_STATE + (size_t)b * D_) : (add + (size_t)row * D_);
    float4 a4 = ((const float4*)ap)[t];
    x.x += a4.x; x.y += a4.y; x.z += a4.z; x.w += a4.w;

    float sum = x.x + x.y + x.z + x.w;
    for (int off = 16; off; off >>= 1) sum += __shfl_xor_sync(0xffffffffu, sum, off);
    if ((t & 31) == 0) red[t >> 5] = sum;
    __syncthreads();
    if (t == 0) stat = (red[0] + red[1] + red[2] + red[3]) * (1.f / D_);
    __syncthreads();
    float mu = stat;
    float d0 = x.x - mu, d1 = x.y - mu, d2 = x.z - mu, d3 = x.w - mu;
    float sq = d0*d0 + d1*d1 + d2*d2 + d3*d3;
    for (int off = 16; off; off >>= 1) sq += __shfl_xor_sync(0xffffffffu, sq, off);
    if ((t & 31) == 0) red[t >> 5] = sq;
    __syncthreads();
    if (t == 0) stat = rsqrtf((red[0] + red[1] + red[2] + red[3]) * (1.f / D_) + 1e-5f);
    __syncthreads();
    float rs = stat;
    float4 g = ((const float4*)gamma)[t], be = ((const float4*)beta)[t];
    float4 y;
    y.x = d0 * rs * g.x + be.x;
    y.y = d1 * rs * g.y + be.y;
    y.z = d2 * rs * g.z + be.z;
    y.w = d3 * rs * g.w + be.w;
    ((float4*)(out + (size_t)row * D_))[t] = y;
    if (writebf) {
        __nv_bfloat16 h0, l0, h1, l1, h2, l2, h3, l3;
        cvt2(y.x, h0, l0); cvt2(y.y, h1, l1); cvt2(y.z, h2, l2); cvt2(y.w, h3, l3);
        size_t o = (size_t)row * D_ + t * 4;
        __nv_bfloat162 p;
        p.x = h0; p.y = h1; *(__nv_bfloat162*)&g_SEQh[o] = p;
        p.x = h2; p.y = h3; *(__nv_bfloat162*)&g_SEQh[o + 2] = p;
        p.x = l0; p.y = l1; *(__nv_bfloat162*)&g_SEQl[o] = p;
        p.x = l2; p.y = l3; *(__nv_bfloat162*)&g_SEQl[o + 2] = p;
    }
}

// ---------------- banded flash attention, bf16x3 MMA, pre-split QKV ------
#define ATT_STR 72
extern __shared__ __nv_bfloat16 s_att[];

__global__ void __launch_bounds__(128) attn_mma_kernel() {
    __nv_bfloat16* Qh = s_att;
    __nv_bfloat16* Ql = Qh + 64 * ATT_STR;
    __nv_bfloat16* Kh = Ql + 64 * ATT_STR;
    __nv_bfloat16* Kl = Kh + 64 * ATT_STR;
    __nv_bfloat16* Vh = Kl + 64 * ATT_STR;
    __nv_bfloat16* Vl = Vh + 64 * ATT_STR;

    int b = blockIdx.z, h = blockIdx.y, q0 = blockIdx.x * 64;
    int tid = threadIdx.x, lane = tid & 31, w = tid >> 5;

    unsigned sQh = (unsigned)__cvta_generic_to_shared(Qh);
    unsigned sQl = (unsigned)__cvta_generic_to_shared(Ql);
    unsigned sKh = (unsigned)__cvta_generic_to_shared(Kh);
    unsigned sKl = (unsigned)__cvta_generic_to_shared(Kl);
    unsigned sVh = (unsigned)__cvta_generic_to_shared(Vh);
    unsigned sVl = (unsigned)__cvta_generic_to_shared(Vl);

    // load Q tile 64x64 (bf16 hi/lo, 16B chunks)
#pragma unroll
    for (int j = 0; j < 4; j++) {
        int idx = tid + 128 * j;
        int r = idx >> 3, c = (idx & 7) * 8;
        size_t src = (size_t)(b * L_ + q0 + r) * (3 * D_) + h * DH_ + c;
        *(uint4*)&Qh[r * ATT_STR + c] = *(const uint4*)(g_QKVh + src);
        *(uint4*)&Ql[r * ATT_STR + c] = *(const uint4*)(g_QKVl + src);
    }

    float m0 = -1e30f, m1 = -1e30f, l0s = 0.f, l1s = 0.f;
    float o[8][4];
#pragma unroll
    for (int j = 0; j < 8; j++)
#pragma unroll
        for (int r = 0; r < 4; r++) o[j][r] = 0.f;

    int qrow0 = 16 * w + (lane >> 2);
    int kstart = q0 - WIN_; if (kstart < 0) kstart = 0;
    int kend = q0 + 64 + WIN_; if (kend > L_) kend = L_;

    for (int k0 = kstart; k0 < kend; k0 += 64) {
        __syncthreads();
#pragma unroll
        for (int j = 0; j < 4; j++) {
            int idx = tid + 128 * j;
            int r = idx >> 3, c = (idx & 7) * 8;
            size_t base = (size_t)(b * L_ + k0 + r) * (3 * D_) + h * DH_ + c;
            *(uint4*)&Kh[r * ATT_STR + c] = *(const uint4*)(g_QKVh + base + D_);
            *(uint4*)&Kl[r * ATT_STR + c] = *(const uint4*)(g_QKVl + base + D_);
            *(uint4*)&Vh[r * ATT_STR + c] = *(const uint4*)(g_QKVh + base + 2 * D_);
            *(uint4*)&Vl[r * ATT_STR + c] = *(const uint4*)(g_QKVl + base + 2 * D_);
        }
        __syncthreads();

        float sc[8][4];
#pragma unroll
        for (int j = 0; j < 8; j++)
#pragma unroll
            for (int r = 0; r < 4; r++) sc[j][r] = 0.f;

#pragma unroll
        for (int kk = 0; kk < 4; kk++) {
            unsigned aqh[4], aql[4];
            int qrow = 16 * w + (lane & 15);
            unsigned qoff = (unsigned)(qrow * ATT_STR + kk * 16 + (lane >> 4) * 8) * 2u;
            ldsm4(aqh[0], aqh[1], aqh[2], aqh[3], sQh + qoff);
            ldsm4(aql[0], aql[1], aql[2], aql[3], sQl + qoff);
#pragma unroll
            for (int nh = 0; nh < 4; nh++) {
                int krow = nh * 16 + (lane & 15);
                unsigned koff = (unsigned)(krow * ATT_STR + kk * 16 + (lane >> 4) * 8) * 2u;
                unsigned r0, r1, r2, r3;
                unsigned bh0[2], bh1[2], bl0[2], bl1[2];
                ldsm4(r0, r1, r2, r3, sKh + koff);
                bh0[0] = r0; bh0[1] = r2; bh1[0] = r1; bh1[1] = r3;
                ldsm4(r0, r1, r2, r3, sKl + koff);
                bl0[0] = r0; bl0[1] = r2; bl1[0] = r1; bl1[1] = r3;
                mma16816(sc[2*nh],   aqh, bh0);
                mma16816(sc[2*nh],   aql, bh0);
                mma16816(sc[2*nh],   aqh, bl0);
                mma16816(sc[2*nh+1], aqh, bh1);
                mma16816(sc[2*nh+1], aql, bh1);
                mma16816(sc[2*nh+1], aqh, bl1);
            }
        }

        int q_a = q0 + qrow0, q_b = q_a + 8;
#pragma unroll
        for (int j = 0; j < 8; j++) {
#pragma unroll
            for (int r = 0; r < 4; r++) {
                int k = k0 + j * 8 + (lane & 3) * 2 + (r & 1);
                int q = (r < 2) ? q_a : q_b;
                int dlt = q - k; if (dlt < 0) dlt = -dlt;
                sc[j][r] = (dlt <= WIN_) ? sc[j][r] * 0.125f : -1e30f;
            }
        }
        float mx0 = -1e30f, mx1 = -1e30f;
#pragma unroll
        for (int j = 0; j < 8; j++) {
            mx0 = fmaxf(mx0, fmaxf(sc[j][0], sc[j][1]));
            mx1 = fmaxf(mx1, fmaxf(sc[j][2], sc[j][3]));
        }
        for (int off = 1; off < 4; off <<= 1) {
            mx0 = fmaxf(mx0, __shfl_xor_sync(0xffffffffu, mx0, off));
            mx1 = fmaxf(mx1, __shfl_xor_sync(0xffffffffu, mx1, off));
        }
        float mn0 = fmaxf(m0, mx0), mn1 = fmaxf(m1, mx1);
        float c0 = __expf(m0 - mn0), c1 = __expf(m1 - mn1);
        float rs0 = 0.f, rs1 = 0.f;
#pragma unroll
        for (int j = 0; j < 8; j++) {
            sc[j][0] = __expf(sc[j][0] - mn0);
            sc[j][1] = __expf(sc[j][1] - mn0);
            sc[j][2] = __expf(sc[j][2] - mn1);
            sc[j][3] = __expf(sc[j][3] - mn1);
            rs0 += sc[j][0] + sc[j][1];
            rs1 += sc[j][2] + sc[j][3];
        }
        for (int off = 1; off < 4; off <<= 1) {
            rs0 += __shfl_xor_sync(0xffffffffu, rs0, off);
            rs1 += __shfl_xor_sync(0xffffffffu, rs1, off);
        }
        l0s = l0s * c0 + rs0;
        l1s = l1s * c1 + rs1;
        m0 = mn0; m1 = mn1;
#pragma unroll
        for (int j = 0; j < 8; j++) {
            o[j][0] *= c0; o[j][1] *= c0;
            o[j][2] *= c1; o[j][3] *= c1;
        }

#pragma unroll
        for (int kc = 0; kc < 4; kc++) {
            unsigned ph[4], pl[4];
            {
                float x0 = sc[2*kc][0],   x1 = sc[2*kc][1];
                float x2 = sc[2*kc][2],   x3 = sc[2*kc][3];
                float y0 = sc[2*kc+1][0], y1 = sc[2*kc+1][1];
                float y2 = sc[2*kc+1][2], y3 = sc[2*kc+1][3];
                ph[0] = pack_bf16x2(x0, x1);
                ph[1] = pack_bf16x2(x2, x3);
                ph[2] = pack_bf16x2(y0, y1);
                ph[3] = pack_bf16x2(y2, y3);
                pl[0] = pack_bf16x2(x0 - __bfloat162float(__float2bfloat16(x0)),
                                    x1 - __bfloat162float(__float2bfloat16(x1)));
                pl[1] = pack_bf16x2(x2 - __bfloat162float(__float2bfloat16(x2)),
                                    x3 - __bfloat162float(__float2bfloat16(x3)));
                pl[2] = pack_bf16x2(y0 - __bfloat162float(__float2bfloat16(y0)),
                                    y1 - __bfloat162float(__float2bfloat16(y1)));
                pl[3] = pack_bf16x2(y2 - __bfloat162float(__float2bfloat16(y2)),
                                    y3 - __bfloat162float(__float2bfloat16(y3)));
            }
#pragma unroll
            for (int nh = 0; nh < 4; nh++) {
                int vrow = kc * 16 + (lane & 15);
                unsigned voff = (unsigned)(vrow * ATT_STR + nh * 16 + (lane >> 4) * 8) * 2u;
                unsigned r0, r1, r2, r3;
                unsigned bh0[2], bh1[2], bl0[2], bl1[2];
                ldsm4t(r0, r1, r2, r3, sVh + voff);
                bh0[0] = r0; bh0[1] = r1; bh1[0] = r2; bh1[1] = r3;
                ldsm4t(r0, r1, r2, r3, sVl + voff);
                bl0[0] = r0; bl0[1] = r1; bl1[0] = r2; bl1[1] = r3;
                mma16816(o[2*nh],   ph, bh0);
                mma16816(o[2*nh],   pl, bh0);
                mma16816(o[2*nh],   ph, bl0);
                mma16816(o[2*nh+1], ph, bh1);
                mma16816(o[2*nh+1], pl, bh1);
                mma16816(o[2*nh+1], ph, bl1);
            }
        }
    }

    // epilogue -> ATT hi/lo
    float inv0 = 1.f / l0s, inv1 = 1.f / l1s;
    int qa = b * L_ + q0 + qrow0;
#pragma unroll
    for (int j = 0; j < 8; j++) {
        int c = h * DH_ + j * 8 + (lane & 3) * 2;
        float v00 = o[j][0] * inv0, v01 = o[j][1] * inv0;
        float v10 = o[j][2] * inv1, v11 = o[j][3] * inv1;
        __nv_bfloat16 hh, ll;
        __nv_bfloat162 ph, pl;
        cvt2(v00, hh, ll); ph.x = hh; pl.x = ll;
        cvt2(v01, hh, ll); ph.y = hh; pl.y = ll;
        *(__nv_bfloat162*)&g_ATTh[(size_t)qa * D_ + c] = ph;
        *(__nv_bfloat162*)&g_ATTl[(size_t)qa * D_ + c] = pl;
        cvt2(v10, hh, ll); ph.x = hh; pl.x = ll;
        cvt2(v11, hh, ll); ph.y = hh; pl.y = ll;
        *(__nv_bfloat162*)&g_ATTh[(size_t)(qa + 8) * D_ + c] = ph;
        *(__nv_bfloat162*)&g_ATTl[(size_t)(qa + 8) * D_ + c] = pl;
    }
}

// ---------------- launcher ----------------
extern "C" void kernel_launch(void* const* d_in, const int* in_sizes, int n_in,
                              void* d_out, int out_size) {
    const float* context = (const float*)d_in[0];
    const float* conv_w  = (const float*)d_in[1];
    const float* Wx      = (const float*)d_in[2];
    const float* Wh      = (const float*)d_in[3];
    const float* Wout    = (const float*)d_in[4];
    const float* Aparam  = (const float*)d_in[5];
    const float* gm      = (const float*)d_in[6];
    const float* bm      = (const float*)d_in[7];
    const float* ga      = (const float*)d_in[8];
    const float* ba      = (const float*)d_in[9];
    const float* Wqkv    = (const float*)d_in[10];
    const float* bqkv    = (const float*)d_in[11];
    const float* Wo      = (const float*)d_in[12];
    const float* bo      = (const float*)d_in[13];
    float* out = (float*)d_out;

    static bool init = false;
    static void *pU, *pX;
    static void *pXh, *pXl, *pSEQh, *pSEQl, *pQKVh, *pQKVl, *pATTh, *pATTl;
    static void *pWxh, *pWxl, *pWqkvh, *pWqkvl, *pWoh, *pWol;
    if (!init) {
        cudaGetSymbolAddress(&pU, g_U);
        cudaGetSymbolAddress(&pX, g_X);
        cudaGetSymbolAddress(&pXh, g_Xh);     cudaGetSymbolAddress(&pXl, g_Xl);
        cudaGetSymbolAddress(&pSEQh, g_SEQh); cudaGetSymbolAddress(&pSEQl, g_SEQl);
        cudaGetSymbolAddress(&pQKVh, g_QKVh); cudaGetSymbolAddress(&pQKVl, g_QKVl);
        cudaGetSymbolAddress(&pATTh, g_ATTh); cudaGetSymbolAddress(&pATTl, g_ATTl);
        cudaGetSymbolAddress(&pWxh, g_Wxh);   cudaGetSymbolAddress(&pWxl, g_Wxl);
        cudaGetSymbolAddress(&pWqkvh, g_Wqkvh); cudaGetSymbolAddress(&pWqkvl, g_Wqkvl);
        cudaGetSymbolAddress(&pWoh, g_Woh);   cudaGetSymbolAddress(&pWol, g_Wol);
        cudaFuncSetAttribute(attn_mma_kernel,
                             cudaFuncAttributeMaxDynamicSharedMemorySize,
                             6 * 64 * ATT_STR * (int)sizeof(__nv_bfloat16));
        cudaFuncSetAttribute(mma_gemm2,
                             cudaFuncAttributeMaxDynamicSharedMemorySize,
                             2 * G_STAGE * (int)sizeof(__nv_bfloat16));
        init = true;
    }
    const int GEMM_SMEM = 2 * G_STAGE * (int)sizeof(__nv_bfloat16);
    const int ATT_SMEM  = 6 * 64 * ATT_STR * (int)sizeof(__nv_bfloat16);

    zero_state_kernel<<<(B_ * D_ + 255) / 256, 256>>>();

    // weight conversions (once per launch)
    for (int i = 0; i < NL_; i++)
        cvt_weight_T<<<(S_ * D_ + 255) / 256, 256>>>(
            Wx + (size_t)i * D_ * S_,
            (__nv_bfloat16*)pWxh + (size_t)i * S_ * D_,
            (__nv_bfloat16*)pWxl + (size_t)i * S_ * D_, S_, D_);
    cvt_weight<<<(3 * D_ * D_ + 255) / 256, 256>>>(Wqkv, (__nv_bfloat16*)pWqkvh,
                                                   (__nv_bfloat16*)pWqkvl, 3 * D_ * D_);
    cvt_weight<<<(D_ * D_ + 255) / 256, 256>>>(Wo, (__nv_bfloat16*)pWoh,
                                               (__nv_bfloat16*)pWol, D_ * D_);

    for (int i = 0; i < NL_; i++) {
        const float* seqin = (i == 0) ? context : out;
        conv_silu_kernel<<<B_ * L_, 128>>>(seqin, conv_w + (size_t)i * 3 * D_);
        mma_gemm2<<<dim3(S_ / 64, B_ * L_ / 128), 256, GEMM_SMEM>>>(
            (const __nv_bfloat16*)pXh, (const __nv_bfloat16*)pXl,
            (const __nv_bfloat16*)pWxh + (size_t)i * S_ * D_,
            (const __nv_bfloat16*)pWxl + (size_t)i * S_ * D_,
            nullptr, (float*)pU, nullptr, nullptr, B_ * L_, S_, D_);
        ht_part_kernel<<<dim3(B_, 64), 256>>>(Aparam + (size_t)i * S_);
        ht_combine_kernel<<<B_, 256>>>(Aparam + (size_t)i * S_, Wh + (size_t)i * D_ * S_);
        stateout_kernel<<<B_, D_>>>(Wout + (size_t)i * S_ * D_);
        ln_kernel<<<B_ * L_, 128>>>(seqin, nullptr, gm, bm, out, 1,
                                    ((i + 1) % 4) == 0 ? 1 : 0);

        if (((i + 1) % 4) == 0) {
            mma_gemm2<<<dim3(3 * D_ / 64, B_ * L_ / 128), 256, GEMM_SMEM>>>(
                (const __nv_bfloat16*)pSEQh, (const __nv_bfloat16*)pSEQl,
                (const __nv_bfloat16*)pWqkvh, (const __nv_bfloat16*)pWqkvl,
                bqkv, nullptr, (__nv_bfloat16*)pQKVh, (__nv_bfloat16*)pQKVl,
                B_ * L_, 3 * D_, D_);
            attn_mma_kernel<<<dim3(L_ / 64, H_, B_), 128, ATT_SMEM>>>();
            mma_gemm2<<<dim3(D_ / 64, B_ * L_ / 128), 256, GEMM_SMEM>>>(
                (const __nv_bfloat16*)pATTh, (const __nv_bfloat16*)pATTl,
                (const __nv_bfloat16*)pWoh, (const __nv_bfloat16*)pWol,
                bo, (float*)pX, nullptr, nullptr, B_ * L_, D_, D_);
            ln_kernel<<<B_ * L_, 128>>>(out, (const float*)pX, ga, ba, out, 0, 0);
        }
    }
}

// round 8
// speedup vs baseline: 1.3919x; 1.3919x over previous
#include <cuda_runtime.h>
#include <cuda_fp16.h>
#include <math.h>

#define B_   4
#define L_   2048
#define D_   512
#define S_   256
#define NL_  6
#define H_   8
#define DH_  64
#define WIN_ 256

// ---------------- scratch (device globals; no allocation) ----------------
__device__ float g_X[B_*L_*D_];        // conv+silu output / proj scratch
__device__ float g_U[B_*L_*S_];        // mamba u
__device__ float g_QKV[B_*L_*3*D_];    // qkv
__device__ float g_ATT[B_*L_*D_];      // attention context
__device__ float g_HT[B_*S_];
__device__ float g_STATE[B_*D_];
__device__ float g_PART[64][B_][S_];

// ---------------- helpers ----------------
__device__ __forceinline__ void ldsm4(unsigned& r0, unsigned& r1, unsigned& r2, unsigned& r3, unsigned addr) {
    asm volatile("ldmatrix.sync.aligned.m8n8.x4.shared.b16 {%0,%1,%2,%3},[%4];"
                 : "=r"(r0), "=r"(r1), "=r"(r2), "=r"(r3) : "r"(addr));
}
__device__ __forceinline__ void ldsm4t(unsigned& r0, unsigned& r1, unsigned& r2, unsigned& r3, unsigned addr) {
    asm volatile("ldmatrix.sync.aligned.m8n8.x4.trans.shared.b16 {%0,%1,%2,%3},[%4];"
                 : "=r"(r0), "=r"(r1), "=r"(r2), "=r"(r3) : "r"(addr));
}
__device__ __forceinline__ void mma16816(float* c, const unsigned* a, const unsigned* b) {
    asm volatile("mma.sync.aligned.m16n8k16.row.col.f32.f16.f16.f32 "
                 "{%0,%1,%2,%3},{%4,%5,%6,%7},{%8,%9},{%0,%1,%2,%3};"
                 : "+f"(c[0]), "+f"(c[1]), "+f"(c[2]), "+f"(c[3])
                 : "r"(a[0]), "r"(a[1]), "r"(a[2]), "r"(a[3]), "r"(b[0]), "r"(b[1]));
}

// ---------------- zero state ----------------
__global__ void zero_state_kernel() {
    int t = blockIdx.x * blockDim.x + threadIdx.x;
    if (t < B_ * D_) g_STATE[t] = 0.f;
}

// ---------------- conv (k=3, causal) + SiLU ----------------
__global__ void conv_silu_kernel(const float* __restrict__ seq,
                                 const float* __restrict__ cw) {
    int row = blockIdx.x;            // b*L + l
    int l = row & (L_ - 1);
    int t = threadIdx.x;             // 128 threads, float4 each
    float4 z = make_float4(0.f, 0.f, 0.f, 0.f);
    float4 a0 = (l >= 2) ? ((const float4*)(seq + (size_t)(row - 2) * D_))[t] : z;
    float4 a1 = (l >= 1) ? ((const float4*)(seq + (size_t)(row - 1) * D_))[t] : z;
    float4 a2 = ((const float4*)(seq + (size_t)row * D_))[t];
    float4 w0 = ((const float4*)(cw        ))[t];
    float4 w1 = ((const float4*)(cw +   D_ ))[t];
    float4 w2 = ((const float4*)(cw + 2*D_ ))[t];
    float4 x;
    x.x = w0.x*a0.x + w1.x*a1.x + w2.x*a2.x;
    x.y = w0.y*a0.y + w1.y*a1.y + w2.y*a2.y;
    x.z = w0.z*a0.z + w1.z*a1.z + w2.z*a2.z;
    x.w = w0.w*a0.w + w1.w*a1.w + w2.w*a2.w;
    x.x = x.x / (1.f + __expf(-x.x));
    x.y = x.y / (1.f + __expf(-x.y));
    x.z = x.z / (1.f + __expf(-x.z));
    x.w = x.w / (1.f + __expf(-x.w));
    ((float4*)(g_X + (size_t)row * D_))[t] = x;
}

// ---------------- fp16 tensor-core GEMM with register prefetch ----------
// C[M,N] = A[M,K] * B (+bias), fp32 in/out, single fp16 MMA internally.
// TB=0: B is [K,N] row-major.  TB=1: B is [N,K] row-major.
template <int TB>
__global__ void __launch_bounds__(256) mma_gemm(const float* __restrict__ A,
                                                const float* __restrict__ Bm,
                                                const float* __restrict__ bias,
                                                float* __restrict__ C,
                                                int M, int N, int K) {
    __shared__ __half Ah[128][40];
    constexpr int BROWS = TB ? 64 : 32;
    constexpr int BSTR  = TB ? 40 : 72;
    __shared__ __half Bh[BROWS][BSTR];

    int bm = blockIdx.y * 128, bn = blockIdx.x * 64;
    int tid = threadIdx.x;
    int lane = tid & 31, wid = tid >> 5;
    int wm = (wid & 3) * 32;
    int wn = (wid >> 2) * 32;

    float acc[2][4][4];
#pragma unroll
    for (int i = 0; i < 2; i++)
#pragma unroll
        for (int j = 0; j < 4; j++)
#pragma unroll
            for (int k = 0; k < 4; k++) acc[i][j][k] = 0.f;

    unsigned sAh = (unsigned)__cvta_generic_to_shared(&Ah[0][0]);
    unsigned sBh = (unsigned)__cvta_generic_to_shared(&Bh[0][0]);

    float4 ra[4], rb[2];
    // prologue load k0 = 0
#pragma unroll
    for (int j = 0; j < 4; j++) {
        int idx = tid + 256 * j;
        int r = idx >> 3, c4 = (idx & 7) * 4;
        ra[j] = *(const float4*)(A + (size_t)(bm + r) * K + c4);
    }
    if (TB == 1) {
#pragma unroll
        for (int j = 0; j < 2; j++) {
            int idx = tid + 256 * j;
            int r = idx >> 3, c4 = (idx & 7) * 4;
            rb[j] = *(const float4*)(Bm + (size_t)(bn + r) * K + c4);
        }
    } else {
#pragma unroll
        for (int j = 0; j < 2; j++) {
            int idx = tid + 256 * j;
            int r = idx >> 4, c4 = (idx & 15) * 4;
            rb[j] = *(const float4*)(Bm + (size_t)r * N + bn + c4);
        }
    }

    for (int k0 = 0; k0 < K; k0 += 32) {
        // store staged regs to smem (fp32 -> fp16)
#pragma unroll
        for (int j = 0; j < 4; j++) {
            int idx = tid + 256 * j;
            int r = idx >> 3, c4 = (idx & 7) * 4;
            *(__half2*)&Ah[r][c4]     = __floats2half2_rn(ra[j].x, ra[j].y);
            *(__half2*)&Ah[r][c4 + 2] = __floats2half2_rn(ra[j].z, ra[j].w);
        }
#pragma unroll
        for (int j = 0; j < 2; j++) {
            int idx = tid + 256 * j;
            int r = TB ? (idx >> 3) : (idx >> 4);
            int c4 = TB ? (idx & 7) * 4 : (idx & 15) * 4;
            *(__half2*)&Bh[r][c4]     = __floats2half2_rn(rb[j].x, rb[j].y);
            *(__half2*)&Bh[r][c4 + 2] = __floats2half2_rn(rb[j].z, rb[j].w);
        }
        __syncthreads();

        // prefetch next tile while MMAs run
        int kn = k0 + 32;
        if (kn < K) {
#pragma unroll
            for (int j = 0; j < 4; j++) {
                int idx = tid + 256 * j;
                int r = idx >> 3, c4 = (idx & 7) * 4;
                ra[j] = *(const float4*)(A + (size_t)(bm + r) * K + kn + c4);
            }
            if (TB == 1) {
#pragma unroll
                for (int j = 0; j < 2; j++) {
                    int idx = tid + 256 * j;
                    int r = idx >> 3, c4 = (idx & 7) * 4;
                    rb[j] = *(const float4*)(Bm + (size_t)(bn + r) * K + kn + c4);
                }
            } else {
#pragma unroll
                for (int j = 0; j < 2; j++) {
                    int idx = tid + 256 * j;
                    int r = idx >> 4, c4 = (idx & 15) * 4;
                    rb[j] = *(const float4*)(Bm + (size_t)(kn + r) * N + bn + c4);
                }
            }
        }

#pragma unroll
        for (int ks = 0; ks < 2; ks++) {
            unsigned afh[2][4], bfh[4][2];
#pragma unroll
            for (int mi = 0; mi < 2; mi++) {
                int row = wm + mi * 16 + (lane & 15);
                unsigned off = (unsigned)(row * 40 + ks * 16 + (lane >> 4) * 8) * 2u;
                ldsm4(afh[mi][0], afh[mi][1], afh[mi][2], afh[mi][3], sAh + off);
            }
            if (TB == 1) {
#pragma unroll
                for (int nh = 0; nh < 2; nh++) {
                    int row = wn + nh * 16 + (lane & 15);
                    unsigned off = (unsigned)(row * BSTR + ks * 16 + (lane >> 4) * 8) * 2u;
                    unsigned r0, r1, r2, r3;
                    ldsm4(r0, r1, r2, r3, sBh + off);
                    bfh[nh*2+0][0] = r0; bfh[nh*2+0][1] = r2;
                    bfh[nh*2+1][0] = r1; bfh[nh*2+1][1] = r3;
                }
            } else {
#pragma unroll
                for (int nh = 0; nh < 2; nh++) {
                    int row = ks * 16 + (lane & 15);
                    unsigned off = (unsigned)(row * BSTR + wn + nh * 16 + (lane >> 4) * 8) * 2u;
                    unsigned r0, r1, r2, r3;
                    ldsm4t(r0, r1, r2, r3, sBh + off);
                    bfh[nh*2+0][0] = r0; bfh[nh*2+0][1] = r1;
                    bfh[nh*2+1][0] = r2; bfh[nh*2+1][1] = r3;
                }
            }
#pragma unroll
            for (int mi = 0; mi < 2; mi++)
#pragma unroll
                for (int ni = 0; ni < 4; ni++)
                    mma16816(acc[mi][ni], afh[mi], bfh[ni]);
        }
        __syncthreads();
    }

#pragma unroll
    for (int mi = 0; mi < 2; mi++)
#pragma unroll
        for (int ni = 0; ni < 4; ni++) {
            int r = bm + wm + mi * 16 + (lane >> 2);
            int c = bn + wn + ni * 8 + (lane & 3) * 2;
            float b0 = bias ? bias[c] : 0.f;
            float b1 = bias ? bias[c + 1] : 0.f;
            C[(size_t)r * N + c]           = acc[mi][ni][0] + b0;
            C[(size_t)r * N + c + 1]       = acc[mi][ni][1] + b1;
            C[(size_t)(r + 8) * N + c]     = acc[mi][ni][2] + b0;
            C[(size_t)(r + 8) * N + c + 1] = acc[mi][ni][3] + b1;
        }
}

// ---------------- ssm chunked Horner with decay skip ----------------
__global__ void ht_part_kernel(const float* __restrict__ Aparam) {
    int b = blockIdx.x, c = blockIdx.y;   // 64 chunks of 32
    int s = threadIdx.x;                  // 256
    float a = 1.f / (1.f + expf(-Aparam[s]));
    float wt = powf(a, (float)(32 * (63 - c)));
    float wmax = wt;
    for (int off = 16; off; off >>= 1)
        wmax = fmaxf(wmax, __shfl_xor_sync(0xffffffffu, wmax, off));
    if (wmax < 1e-28f) { g_PART[c][b][s] = 0.f; return; }
    const float* base = g_U + ((size_t)(b * L_) + c * 32) * S_ + s;
    float p = 0.f;
#pragma unroll
    for (int j = 0; j < 32; j++) p = p * a + base[(size_t)j * S_];
    g_PART[c][b][s] = p * wt;
}

__global__ void ht_combine_kernel(const float* __restrict__ Aparam,
                                  const float* __restrict__ Wh) {
    int b = blockIdx.x;
    int s = threadIdx.x;   // 256
    float a = 1.f / (1.f + expf(-Aparam[s]));
    float h0 = 0.f;
#pragma unroll 8
    for (int d = 0; d < D_; d++) h0 += g_STATE[b * D_ + d] * Wh[(size_t)d * S_ + s];
    float sum = 0.f;
#pragma unroll
    for (int c = 0; c < 64; c++) sum += g_PART[c][b][s];
    g_HT[b * S_ + s] = powf(a, (float)L_) * h0 + sum;
}

__global__ void stateout_kernel(const float* __restrict__ Wout) {
    __shared__ float ht[S_];
    int b = blockIdx.x;
    int d = threadIdx.x;   // 512
    if (d < S_) ht[d] = g_HT[b * S_ + d];
    __syncthreads();
    float acc = 0.f;
#pragma unroll 8
    for (int s = 0; s < S_; s++) acc += ht[s] * Wout[(size_t)s * D_ + d];
    g_STATE[b * D_ + d] = acc;
}

// ---------------- residual + LayerNorm ----------------
__global__ void ln_kernel(const float* __restrict__ seq, const float* __restrict__ add,
                          const float* __restrict__ gamma, const float* __restrict__ beta,
                          float* __restrict__ out, int bcast) {
    __shared__ float red[4];
    __shared__ float stat;
    int row = blockIdx.x;
    int b = row >> 11;
    int t = threadIdx.x;   // 128
    float4 x = ((const float4*)(seq + (size_t)row * D_))[t];
    const float* ap = bcast ? (g_STATE + (size_t)b * D_) : (add + (size_t)row * D_);
    float4 a4 = ((const float4*)ap)[t];
    x.x += a4.x; x.y += a4.y; x.z += a4.z; x.w += a4.w;

    float sum = x.x + x.y + x.z + x.w;
    for (int off = 16; off; off >>= 1) sum += __shfl_xor_sync(0xffffffffu, sum, off);
    if ((t & 31) == 0) red[t >> 5] = sum;
    __syncthreads();
    if (t == 0) stat = (red[0] + red[1] + red[2] + red[3]) * (1.f / D_);
    __syncthreads();
    float mu = stat;
    float d0 = x.x - mu, d1 = x.y - mu, d2 = x.z - mu, d3 = x.w - mu;
    float sq = d0*d0 + d1*d1 + d2*d2 + d3*d3;
    for (int off = 16; off; off >>= 1) sq += __shfl_xor_sync(0xffffffffu, sq, off);
    if ((t & 31) == 0) red[t >> 5] = sq;
    __syncthreads();
    if (t == 0) stat = rsqrtf((red[0] + red[1] + red[2] + red[3]) * (1.f / D_) + 1e-5f);
    __syncthreads();
    float rs = stat;
    float4 g = ((const float4*)gamma)[t], be = ((const float4*)beta)[t];
    float4 y;
    y.x = d0 * rs * g.x + be.x;
    y.y = d1 * rs * g.y + be.y;
    y.z = d2 * rs * g.z + be.z;
    y.w = d3 * rs * g.w + be.w;
    ((float4*)(out + (size_t)row * D_))[t] = y;
}

// ---------------- banded flash attention, single fp16 MMA ----------------
// block = (qt, h, b), 128 threads (4 warps), 64 queries, k-tiles of 64.
#define ATT_STR 72
extern __shared__ __half s_att[];

__global__ void __launch_bounds__(128) attn_mma_kernel() {
    __half* Qs = s_att;
    __half* Ks = Qs + 64 * ATT_STR;
    __half* Vs = Ks + 64 * ATT_STR;

    int b = blockIdx.z, h = blockIdx.y, q0 = blockIdx.x * 64;
    int tid = threadIdx.x, lane = tid & 31, w = tid >> 5;

    unsigned sQ = (unsigned)__cvta_generic_to_shared(Qs);
    unsigned sK = (unsigned)__cvta_generic_to_shared(Ks);
    unsigned sV = (unsigned)__cvta_generic_to_shared(Vs);

    // load Q tile 64x64 (fp32 -> fp16)
#pragma unroll
    for (int j = 0; j < 8; j++) {
        int idx = tid + 128 * j;
        int r = idx >> 4, c4 = (idx & 15) * 4;
        float4 v = *(const float4*)(g_QKV + (size_t)(b * L_ + q0 + r) * (3 * D_) + h * DH_ + c4);
        *(__half2*)&Qs[r * ATT_STR + c4]     = __floats2half2_rn(v.x, v.y);
        *(__half2*)&Qs[r * ATT_STR + c4 + 2] = __floats2half2_rn(v.z, v.w);
    }

    float m0 = -1e30f, m1 = -1e30f, l0s = 0.f, l1s = 0.f;
    float o[8][4];
#pragma unroll
    for (int j = 0; j < 8; j++)
#pragma unroll
        for (int r = 0; r < 4; r++) o[j][r] = 0.f;

    int qrow0 = 16 * w + (lane >> 2);       // local q row (first)
    int kstart = q0 - WIN_; if (kstart < 0) kstart = 0;
    int kend = q0 + 64 + WIN_; if (kend > L_) kend = L_;

    for (int k0 = kstart; k0 < kend; k0 += 64) {
        __syncthreads();
        // load K,V tiles 64x64 each
#pragma unroll
        for (int j = 0; j < 8; j++) {
            int idx = tid + 128 * j;
            int r = idx >> 4, c4 = (idx & 15) * 4;
            size_t base = (size_t)(b * L_ + k0 + r) * (3 * D_) + h * DH_ + c4;
            float4 kv = *(const float4*)(g_QKV + base + D_);
            float4 vv = *(const float4*)(g_QKV + base + 2 * D_);
            *(__half2*)&Ks[r * ATT_STR + c4]     = __floats2half2_rn(kv.x, kv.y);
            *(__half2*)&Ks[r * ATT_STR + c4 + 2] = __floats2half2_rn(kv.z, kv.w);
            *(__half2*)&Vs[r * ATT_STR + c4]     = __floats2half2_rn(vv.x, vv.y);
            *(__half2*)&Vs[r * ATT_STR + c4 + 2] = __floats2half2_rn(vv.z, vv.w);
        }
        __syncthreads();

        // S = Q K^T, warp handles 16 q rows x 64 keys
        float sc[8][4];
#pragma unroll
        for (int j = 0; j < 8; j++)
#pragma unroll
            for (int r = 0; r < 4; r++) sc[j][r] = 0.f;

#pragma unroll
        for (int kk = 0; kk < 4; kk++) {
            unsigned aq[4];
            int qrow = 16 * w + (lane & 15);
            unsigned qoff = (unsigned)(qrow * ATT_STR + kk * 16 + (lane >> 4) * 8) * 2u;
            ldsm4(aq[0], aq[1], aq[2], aq[3], sQ + qoff);
#pragma unroll
            for (int nh = 0; nh < 4; nh++) {
                int krow = nh * 16 + (lane & 15);
                unsigned koff = (unsigned)(krow * ATT_STR + kk * 16 + (lane >> 4) * 8) * 2u;
                unsigned r0, r1, r2, r3;
                ldsm4(r0, r1, r2, r3, sK + koff);
                unsigned b0[2] = {r0, r2}, b1[2] = {r1, r3};
                mma16816(sc[2*nh],   aq, b0);
                mma16816(sc[2*nh+1], aq, b1);
            }
        }

        // mask + scale
        int q_a = q0 + qrow0, q_b = q_a + 8;
#pragma unroll
        for (int j = 0; j < 8; j++) {
#pragma unroll
            for (int r = 0; r < 4; r++) {
                int k = k0 + j * 8 + (lane & 3) * 2 + (r & 1);
                int q = (r < 2) ? q_a : q_b;
                int dlt = q - k; if (dlt < 0) dlt = -dlt;
                sc[j][r] = (dlt <= WIN_) ? sc[j][r] * 0.125f : -1e30f;
            }
        }
        // row max
        float mx0 = -1e30f, mx1 = -1e30f;
#pragma unroll
        for (int j = 0; j < 8; j++) {
            mx0 = fmaxf(mx0, fmaxf(sc[j][0], sc[j][1]));
            mx1 = fmaxf(mx1, fmaxf(sc[j][2], sc[j][3]));
        }
        for (int off = 1; off < 4; off <<= 1) {
            mx0 = fmaxf(mx0, __shfl_xor_sync(0xffffffffu, mx0, off));
            mx1 = fmaxf(mx1, __shfl_xor_sync(0xffffffffu, mx1, off));
        }
        float mn0 = fmaxf(m0, mx0), mn1 = fmaxf(m1, mx1);
        float c0 = __expf(m0 - mn0), c1 = __expf(m1 - mn1);
        float rs0 = 0.f, rs1 = 0.f;
#pragma unroll
        for (int j = 0; j < 8; j++) {
            sc[j][0] = __expf(sc[j][0] - mn0);
            sc[j][1] = __expf(sc[j][1] - mn0);
            sc[j][2] = __expf(sc[j][2] - mn1);
            sc[j][3] = __expf(sc[j][3] - mn1);
            rs0 += sc[j][0] + sc[j][1];
            rs1 += sc[j][2] + sc[j][3];
        }
        for (int off = 1; off < 4; off <<= 1) {
            rs0 += __shfl_xor_sync(0xffffffffu, rs0, off);
            rs1 += __shfl_xor_sync(0xffffffffu, rs1, off);
        }
        l0s = l0s * c0 + rs0;
        l1s = l1s * c1 + rs1;
        m0 = mn0; m1 = mn1;
#pragma unroll
        for (int j = 0; j < 8; j++) {
            o[j][0] *= c0; o[j][1] *= c0;
            o[j][2] *= c1; o[j][3] *= c1;
        }

        // O += P V
#pragma unroll
        for (int kc = 0; kc < 4; kc++) {
            unsigned ph[4];
            {
                __half2 p0 = __floats2half2_rn(sc[2*kc][0],   sc[2*kc][1]);
                __half2 p1 = __floats2half2_rn(sc[2*kc][2],   sc[2*kc][3]);
                __half2 p2 = __floats2half2_rn(sc[2*kc+1][0], sc[2*kc+1][1]);
                __half2 p3 = __floats2half2_rn(sc[2*kc+1][2], sc[2*kc+1][3]);
                ph[0] = *(unsigned*)&p0;
                ph[1] = *(unsigned*)&p1;
                ph[2] = *(unsigned*)&p2;
                ph[3] = *(unsigned*)&p3;
            }
#pragma unroll
            for (int nh = 0; nh < 4; nh++) {
                int vrow = kc * 16 + (lane & 15);
                unsigned voff = (unsigned)(vrow * ATT_STR + nh * 16 + (lane >> 4) * 8) * 2u;
                unsigned r0, r1, r2, r3;
                ldsm4t(r0, r1, r2, r3, sV + voff);
                unsigned b0[2] = {r0, r1}, b1[2] = {r2, r3};
                mma16816(o[2*nh],   ph, b0);
                mma16816(o[2*nh+1], ph, b1);
            }
        }
    }

    // epilogue
    float inv0 = 1.f / l0s, inv1 = 1.f / l1s;
    int qa = b * L_ + q0 + qrow0;
#pragma unroll
    for (int j = 0; j < 8; j++) {
        int c = h * DH_ + j * 8 + (lane & 3) * 2;
        g_ATT[(size_t)qa * D_ + c]           = o[j][0] * inv0;
        g_ATT[(size_t)qa * D_ + c + 1]       = o[j][1] * inv0;
        g_ATT[(size_t)(qa + 8) * D_ + c]     = o[j][2] * inv1;
        g_ATT[(size_t)(qa + 8) * D_ + c + 1] = o[j][3] * inv1;
    }
}

// ---------------- launcher ----------------
extern "C" void kernel_launch(void* const* d_in, const int* in_sizes, int n_in,
                              void* d_out, int out_size) {
    const float* context = (const float*)d_in[0];
    const float* conv_w  = (const float*)d_in[1];
    const float* Wx      = (const float*)d_in[2];
    const float* Wh      = (const float*)d_in[3];
    const float* Wout    = (const float*)d_in[4];
    const float* Aparam  = (const float*)d_in[5];
    const float* gm      = (const float*)d_in[6];
    const float* bm      = (const float*)d_in[7];
    const float* ga      = (const float*)d_in[8];
    const float* ba      = (const float*)d_in[9];
    const float* Wqkv    = (const float*)d_in[10];
    const float* bqkv    = (const float*)d_in[11];
    const float* Wo      = (const float*)d_in[12];
    const float* bo      = (const float*)d_in[13];
    float* out = (float*)d_out;

    static void *pX = nullptr, *pU = nullptr, *pQKV = nullptr, *pATT = nullptr;
    if (!pX) {
        cudaGetSymbolAddress(&pX, g_X);
        cudaGetSymbolAddress(&pU, g_U);
        cudaGetSymbolAddress(&pQKV, g_QKV);
        cudaGetSymbolAddress(&pATT, g_ATT);
        cudaFuncSetAttribute(attn_mma_kernel,
                             cudaFuncAttributeMaxDynamicSharedMemorySize,
                             3 * 64 * ATT_STR * (int)sizeof(__half));
    }
    const int ATT_SMEM = 3 * 64 * ATT_STR * (int)sizeof(__half);

    zero_state_kernel<<<(B_ * D_ + 255) / 256, 256>>>();

    for (int i = 0; i < NL_; i++) {
        const float* seqin = (i == 0) ? context : out;
        conv_silu_kernel<<<B_ * L_, 128>>>(seqin, conv_w + (size_t)i * 3 * D_);
        mma_gemm<0><<<dim3(S_ / 64, B_ * L_ / 128), 256>>>(
            (const float*)pX, Wx + (size_t)i * D_ * S_, nullptr, (float*)pU,
            B_ * L_, S_, D_);
        ht_part_kernel<<<dim3(B_, 64), 256>>>(Aparam + (size_t)i * S_);
        ht_combine_kernel<<<B_, 256>>>(Aparam + (size_t)i * S_, Wh + (size_t)i * D_ * S_);
        stateout_kernel<<<B_, D_>>>(Wout + (size_t)i * S_ * D_);
        ln_kernel<<<B_ * L_, 128>>>(seqin, nullptr, gm, bm, out, 1);

        if (((i + 1) % 4) == 0) {
            mma_gemm<1><<<dim3(3 * D_ / 64, B_ * L_ / 128), 256>>>(
                out, Wqkv, bqkv, (float*)pQKV, B_ * L_, 3 * D_, D_);
            attn_mma_kernel<<<dim3(L_ / 64, H_, B_), 128, ATT_SMEM>>>();
            mma_gemm<1><<<dim3(D_ / 64, B_ * L_ / 128), 256>>>(
                (const float*)pATT, Wo, bo, (float*)pX, B_ * L_, D_, D_);
            ln_kernel<<<B_ * L_, 128>>>(out, (const float*)pX, ga, ba, out, 0);
        }
    }
}

// round 9
// speedup vs baseline: 1.3997x; 1.0056x over previous
#include <cuda_runtime.h>
#include <cuda_fp16.h>
#include <math.h>

#define B_   4
#define L_   2048
#define D_   512
#define S_   256
#define NL_  6
#define H_   8
#define DH_  64
#define WIN_ 256

// ---------------- scratch (device globals; no allocation) ----------------
__device__ float g_X[B_*L_*D_];         // out-proj fp32 scratch
__device__ float g_U[B_*L_*S_];         // mamba u (fp32)
__device__ float g_HT[B_*S_];
__device__ float g_STATE[B_*D_];
__device__ float g_PART[64][B_][S_];

__device__ __half g_Xh[B_*L_*D_];       // conv+silu output (fp16)
__device__ __half g_SEQh[B_*L_*D_];     // ln output fp16 shadow (attn input)
__device__ __half g_QKVh[B_*L_*3*D_];   // qkv fp16
__device__ __half g_ATTh[B_*L_*D_];     // attention context fp16
__device__ __half g_WxH[NL_*D_*S_];     // [D][S]
__device__ __half g_WqkvH[3*D_*D_];     // [3D][D]
__device__ __half g_WoH[D_*D_];         // [D][D]

// ---------------- helpers ----------------
__device__ __forceinline__ void ldsm4(unsigned& r0, unsigned& r1, unsigned& r2, unsigned& r3, unsigned addr) {
    asm volatile("ldmatrix.sync.aligned.m8n8.x4.shared.b16 {%0,%1,%2,%3},[%4];"
                 : "=r"(r0), "=r"(r1), "=r"(r2), "=r"(r3) : "r"(addr));
}
__device__ __forceinline__ void ldsm4t(unsigned& r0, unsigned& r1, unsigned& r2, unsigned& r3, unsigned addr) {
    asm volatile("ldmatrix.sync.aligned.m8n8.x4.trans.shared.b16 {%0,%1,%2,%3},[%4];"
                 : "=r"(r0), "=r"(r1), "=r"(r2), "=r"(r3) : "r"(addr));
}
__device__ __forceinline__ void mma16816(float* c, const unsigned* a, const unsigned* b) {
    asm volatile("mma.sync.aligned.m16n8k16.row.col.f32.f16.f16.f32 "
                 "{%0,%1,%2,%3},{%4,%5,%6,%7},{%8,%9},{%0,%1,%2,%3};"
                 : "+f"(c[0]), "+f"(c[1]), "+f"(c[2]), "+f"(c[3])
                 : "r"(a[0]), "r"(a[1]), "r"(a[2]), "r"(a[3]), "r"(b[0]), "r"(b[1]));
}
__device__ __forceinline__ void cpa16(unsigned d, const void* s) {
    asm volatile("cp.async.cg.shared.global [%0],[%1],16;" :: "r"(d), "l"(s));
}
__device__ __forceinline__ void cpa_commit() {
    asm volatile("cp.async.commit_group;");
}
template <int N>
__device__ __forceinline__ void cpa_wait() {
    asm volatile("cp.async.wait_group %0;" :: "n"(N));
}

// ---------------- misc small kernels ----------------
__global__ void zero_state_kernel() {
    int t = blockIdx.x * blockDim.x + threadIdx.x;
    if (t < B_ * D_) g_STATE[t] = 0.f;
}
__global__ void cvt_weight(const float* __restrict__ W, __half* __restrict__ Wh, int n) {
    int t = blockIdx.x * 256 + threadIdx.x;
    if (t < n) Wh[t] = __float2half_rn(W[t]);
}

// ---------------- conv (k=3, causal) + SiLU -> fp16 ----------------
__global__ void conv_silu_kernel(const float* __restrict__ seq,
                                 const float* __restrict__ cw) {
    int row = blockIdx.x;
    int l = row & (L_ - 1);
    int t = threadIdx.x;             // 128
    float4 z = make_float4(0.f, 0.f, 0.f, 0.f);
    float4 a0 = (l >= 2) ? ((const float4*)(seq + (size_t)(row - 2) * D_))[t] : z;
    float4 a1 = (l >= 1) ? ((const float4*)(seq + (size_t)(row - 1) * D_))[t] : z;
    float4 a2 = ((const float4*)(seq + (size_t)row * D_))[t];
    float4 w0 = ((const float4*)(cw        ))[t];
    float4 w1 = ((const float4*)(cw +   D_ ))[t];
    float4 w2 = ((const float4*)(cw + 2*D_ ))[t];
    float4 x;
    x.x = w0.x*a0.x + w1.x*a1.x + w2.x*a2.x;
    x.y = w0.y*a0.y + w1.y*a1.y + w2.y*a2.y;
    x.z = w0.z*a0.z + w1.z*a1.z + w2.z*a2.z;
    x.w = w0.w*a0.w + w1.w*a1.w + w2.w*a2.w;
    x.x = x.x / (1.f + __expf(-x.x));
    x.y = x.y / (1.f + __expf(-x.y));
    x.z = x.z / (1.f + __expf(-x.z));
    x.w = x.w / (1.f + __expf(-x.w));
    size_t o = (size_t)row * D_ + t * 4;
    *(__half2*)&g_Xh[o]     = __floats2half2_rn(x.x, x.y);
    *(__half2*)&g_Xh[o + 2] = __floats2half2_rn(x.z, x.w);
}

// ---------------- fp16 cp.async double-buffered GEMM, 128x128 tile ------
// A fp16 [M][K]. TB=0: B fp16 [K][N].  TB=1: B fp16 [N][K].
// C: fp32 (Cf) or fp16 (Ch) output.
template <int TB>
__global__ void __launch_bounds__(256) mma_gemm3(const __half* __restrict__ A,
                                                 const __half* __restrict__ Bm,
                                                 const float* __restrict__ bias,
                                                 float* __restrict__ Cf,
                                                 __half* __restrict__ Ch,
                                                 int M, int N, int K) {
    __shared__ __half Ah[2][128][40];
    constexpr int BR = TB ? 128 : 32;
    constexpr int BSTR = TB ? 40 : 136;
    __shared__ __half Bh[2][BR][BSTR];

    int bm = blockIdx.y * 128, bn = blockIdx.x * 128;
    int tid = threadIdx.x;
    int lane = tid & 31, wid = tid >> 5;
    int wm = (wid & 3) * 32;
    int wn = (wid >> 2) * 64;

    float acc[2][8][4];
#pragma unroll
    for (int i = 0; i < 2; i++)
#pragma unroll
        for (int j = 0; j < 8; j++)
#pragma unroll
            for (int k = 0; k < 4; k++) acc[i][j][k] = 0.f;

    unsigned sA0 = (unsigned)__cvta_generic_to_shared(&Ah[0][0][0]);
    unsigned sA1 = (unsigned)__cvta_generic_to_shared(&Ah[1][0][0]);
    unsigned sB0 = (unsigned)__cvta_generic_to_shared(&Bh[0][0][0]);
    unsigned sB1 = (unsigned)__cvta_generic_to_shared(&Bh[1][0][0]);

    int nk = K >> 5;
    auto issue = [&](int kt) {
        unsigned sa = (kt & 1) ? sA1 : sA0;
        unsigned sb = (kt & 1) ? sB1 : sB0;
        int k0 = kt << 5;
        // A tile 128x32: 512 chunks of 8 halfs
#pragma unroll
        for (int j = 0; j < 2; j++) {
            int ch = tid + 256 * j;
            int r = ch >> 2, c8 = (ch & 3) * 8;
            cpa16(sa + (unsigned)(r * 40 + c8) * 2u,
                  A + (size_t)(bm + r) * K + k0 + c8);
        }
        if (TB == 1) {
#pragma unroll
            for (int j = 0; j < 2; j++) {
                int ch = tid + 256 * j;
                int r = ch >> 2, c8 = (ch & 3) * 8;
                cpa16(sb + (unsigned)(r * 40 + c8) * 2u,
                      Bm + (size_t)(bn + r) * K + k0 + c8);
            }
        } else {
#pragma unroll
            for (int j = 0; j < 2; j++) {
                int ch = tid + 256 * j;
                int r = ch >> 4, c8 = (ch & 15) * 8;
                cpa16(sb + (unsigned)(r * 136 + c8) * 2u,
                      Bm + (size_t)(k0 + r) * N + bn + c8);
            }
        }
        cpa_commit();
    };

    issue(0);
    for (int kt = 0; kt < nk; kt++) {
        if (kt + 1 < nk) { issue(kt + 1); cpa_wait<1>(); }
        else             { cpa_wait<0>(); }
        __syncthreads();

        unsigned sa = (kt & 1) ? sA1 : sA0;
        unsigned sb = (kt & 1) ? sB1 : sB0;
#pragma unroll
        for (int ks = 0; ks < 2; ks++) {
            unsigned af[2][4], bf[8][2];
#pragma unroll
            for (int mi = 0; mi < 2; mi++) {
                int row = wm + mi * 16 + (lane & 15);
                unsigned off = (unsigned)(row * 40 + ks * 16 + (lane >> 4) * 8) * 2u;
                ldsm4(af[mi][0], af[mi][1], af[mi][2], af[mi][3], sa + off);
            }
            if (TB == 1) {
#pragma unroll
                for (int nh = 0; nh < 4; nh++) {
                    int row = wn + nh * 16 + (lane & 15);
                    unsigned off = (unsigned)(row * 40 + ks * 16 + (lane >> 4) * 8) * 2u;
                    unsigned r0, r1, r2, r3;
                    ldsm4(r0, r1, r2, r3, sb + off);
                    bf[nh*2+0][0] = r0; bf[nh*2+0][1] = r2;
                    bf[nh*2+1][0] = r1; bf[nh*2+1][1] = r3;
                }
            } else {
#pragma unroll
                for (int nh = 0; nh < 4; nh++) {
                    int row = ks * 16 + (lane & 15);
                    unsigned off = (unsigned)(row * 136 + wn + nh * 16 + (lane >> 4) * 8) * 2u;
                    unsigned r0, r1, r2, r3;
                    ldsm4t(r0, r1, r2, r3, sb + off);
                    bf[nh*2+0][0] = r0; bf[nh*2+0][1] = r1;
                    bf[nh*2+1][0] = r2; bf[nh*2+1][1] = r3;
                }
            }
#pragma unroll
            for (int mi = 0; mi < 2; mi++)
#pragma unroll
                for (int ni = 0; ni < 8; ni++)
                    mma16816(acc[mi][ni], af[mi], bf[ni]);
        }
        __syncthreads();
    }

#pragma unroll
    for (int mi = 0; mi < 2; mi++)
#pragma unroll
        for (int ni = 0; ni < 8; ni++) {
            int r = bm + wm + mi * 16 + (lane >> 2);
            int c = bn + wn + ni * 8 + (lane & 3) * 2;
            float b0 = bias ? bias[c] : 0.f;
            float b1 = bias ? bias[c + 1] : 0.f;
            float v00 = acc[mi][ni][0] + b0, v01 = acc[mi][ni][1] + b1;
            float v10 = acc[mi][ni][2] + b0, v11 = acc[mi][ni][3] + b1;
            if (Ch) {
                *(__half2*)&Ch[(size_t)r * N + c]       = __floats2half2_rn(v00, v01);
                *(__half2*)&Ch[(size_t)(r + 8) * N + c] = __floats2half2_rn(v10, v11);
            } else {
                Cf[(size_t)r * N + c]           = v00;
                Cf[(size_t)r * N + c + 1]       = v01;
                Cf[(size_t)(r + 8) * N + c]     = v10;
                Cf[(size_t)(r + 8) * N + c + 1] = v11;
            }
        }
}

// ---------------- ssm chunked Horner with decay skip ----------------
__global__ void ht_part_kernel(const float* __restrict__ Aparam) {
    int b = blockIdx.x, c = blockIdx.y;   // 64 chunks of 32
    int s = threadIdx.x;                  // 256
    float a = 1.f / (1.f + expf(-Aparam[s]));
    float wt = powf(a, (float)(32 * (63 - c)));
    float wmax = wt;
    for (int off = 16; off; off >>= 1)
        wmax = fmaxf(wmax, __shfl_xor_sync(0xffffffffu, wmax, off));
    if (wmax < 1e-28f) { g_PART[c][b][s] = 0.f; return; }
    const float* base = g_U + ((size_t)(b * L_) + c * 32) * S_ + s;
    float p = 0.f;
#pragma unroll
    for (int j = 0; j < 32; j++) p = p * a + base[(size_t)j * S_];
    g_PART[c][b][s] = p * wt;
}

__global__ void ht_combine_kernel(const float* __restrict__ Aparam,
                                  const float* __restrict__ Wh) {
    int b = blockIdx.x;
    int s = threadIdx.x;   // 256
    float a = 1.f / (1.f + expf(-Aparam[s]));
    float h0 = 0.f;
#pragma unroll 8
    for (int d = 0; d < D_; d++) h0 += g_STATE[b * D_ + d] * Wh[(size_t)d * S_ + s];
    float sum = 0.f;
#pragma unroll
    for (int c = 0; c < 64; c++) sum += g_PART[c][b][s];
    g_HT[b * S_ + s] = powf(a, (float)L_) * h0 + sum;
}

__global__ void stateout_kernel(const float* __restrict__ Wout) {
    __shared__ float ht[S_];
    int b = blockIdx.x;
    int d = threadIdx.x;   // 512
    if (d < S_) ht[d] = g_HT[b * S_ + d];
    __syncthreads();
    float acc = 0.f;
#pragma unroll 8
    for (int s = 0; s < S_; s++) acc += ht[s] * Wout[(size_t)s * D_ + d];
    g_STATE[b * D_ + d] = acc;
}

// ---------------- residual + LayerNorm (optional fp16 shadow) ------------
__global__ void ln_kernel(const float* __restrict__ seq, const float* __restrict__ add,
                          const float* __restrict__ gamma, const float* __restrict__ beta,
                          float* __restrict__ out, int bcast, int writeh) {
    __shared__ float red[4];
    __shared__ float stat;
    int row = blockIdx.x;
    int b = row >> 11;
    int t = threadIdx.x;   // 128
    float4 x = ((const float4*)(seq + (size_t)row * D_))[t];
    const float* ap = bcast ? (g_STATE + (size_t)b * D_) : (add + (size_t)row * D_);
    float4 a4 = ((const float4*)ap)[t];
    x.x += a4.x; x.y += a4.y; x.z += a4.z; x.w += a4.w;

    float sum = x.x + x.y + x.z + x.w;
    for (int off = 16; off; off >>= 1) sum += __shfl_xor_sync(0xffffffffu, sum, off);
    if ((t & 31) == 0) red[t >> 5] = sum;
    __syncthreads();
    if (t == 0) stat = (red[0] + red[1] + red[2] + red[3]) * (1.f / D_);
    __syncthreads();
    float mu = stat;
    float d0 = x.x - mu, d1 = x.y - mu, d2 = x.z - mu, d3 = x.w - mu;
    float sq = d0*d0 + d1*d1 + d2*d2 + d3*d3;
    for (int off = 16; off; off >>= 1) sq += __shfl_xor_sync(0xffffffffu, sq, off);
    if ((t & 31) == 0) red[t >> 5] = sq;
    __syncthreads();
    if (t == 0) stat = rsqrtf((red[0] + red[1] + red[2] + red[3]) * (1.f / D_) + 1e-5f);
    __syncthreads();
    float rs = stat;
    float4 g = ((const float4*)gamma)[t], be = ((const float4*)beta)[t];
    float4 y;
    y.x = d0 * rs * g.x + be.x;
    y.y = d1 * rs * g.y + be.y;
    y.z = d2 * rs * g.z + be.z;
    y.w = d3 * rs * g.w + be.w;
    ((float4*)(out + (size_t)row * D_))[t] = y;
    if (writeh) {
        size_t o = (size_t)row * D_ + t * 4;
        *(__half2*)&g_SEQh[o]     = __floats2half2_rn(y.x, y.y);
        *(__half2*)&g_SEQh[o + 2] = __floats2half2_rn(y.z, y.w);
    }
}

// ---------------- banded flash attention, fp16 MMA, fp16 I/O ------------
#define ATT_STR 72
extern __shared__ __half s_att[];

__global__ void __launch_bounds__(128) attn_mma_kernel() {
    __half* Qs = s_att;
    __half* Ks = Qs + 64 * ATT_STR;
    __half* Vs = Ks + 64 * ATT_STR;

    int b = blockIdx.z, h = blockIdx.y, q0 = blockIdx.x * 64;
    int tid = threadIdx.x, lane = tid & 31, w = tid >> 5;

    unsigned sQ = (unsigned)__cvta_generic_to_shared(Qs);
    unsigned sK = (unsigned)__cvta_generic_to_shared(Ks);
    unsigned sV = (unsigned)__cvta_generic_to_shared(Vs);

    // load Q tile 64x64 fp16 (8-half chunks)
#pragma unroll
    for (int j = 0; j < 4; j++) {
        int idx = tid + 128 * j;
        int r = idx >> 3, c = (idx & 7) * 8;
        *(uint4*)&Qs[r * ATT_STR + c] =
            *(const uint4*)(g_QKVh + (size_t)(b * L_ + q0 + r) * (3 * D_) + h * DH_ + c);
    }

    float m0 = -1e30f, m1 = -1e30f, l0s = 0.f, l1s = 0.f;
    float o[8][4];
#pragma unroll
    for (int j = 0; j < 8; j++)
#pragma unroll
        for (int r = 0; r < 4; r++) o[j][r] = 0.f;

    int qrow0 = 16 * w + (lane >> 2);
    int kstart = q0 - WIN_; if (kstart < 0) kstart = 0;
    int kend = q0 + 64 + WIN_; if (kend > L_) kend = L_;

    for (int k0 = kstart; k0 < kend; k0 += 64) {
        __syncthreads();
#pragma unroll
        for (int j = 0; j < 4; j++) {
            int idx = tid + 128 * j;
            int r = idx >> 3, c = (idx & 7) * 8;
            size_t base = (size_t)(b * L_ + k0 + r) * (3 * D_) + h * DH_ + c;
            *(uint4*)&Ks[r * ATT_STR + c] = *(const uint4*)(g_QKVh + base + D_);
            *(uint4*)&Vs[r * ATT_STR + c] = *(const uint4*)(g_QKVh + base + 2 * D_);
        }
        __syncthreads();

        float sc[8][4];
#pragma unroll
        for (int j = 0; j < 8; j++)
#pragma unroll
            for (int r = 0; r < 4; r++) sc[j][r] = 0.f;

#pragma unroll
        for (int kk = 0; kk < 4; kk++) {
            unsigned aq[4];
            int qrow = 16 * w + (lane & 15);
            unsigned qoff = (unsigned)(qrow * ATT_STR + kk * 16 + (lane >> 4) * 8) * 2u;
            ldsm4(aq[0], aq[1], aq[2], aq[3], sQ + qoff);
#pragma unroll
            for (int nh = 0; nh < 4; nh++) {
                int krow = nh * 16 + (lane & 15);
                unsigned koff = (unsigned)(krow * ATT_STR + kk * 16 + (lane >> 4) * 8) * 2u;
                unsigned r0, r1, r2, r3;
                ldsm4(r0, r1, r2, r3, sK + koff);
                unsigned b0[2] = {r0, r2}, b1[2] = {r1, r3};
                mma16816(sc[2*nh],   aq, b0);
                mma16816(sc[2*nh+1], aq, b1);
            }
        }

        int q_a = q0 + qrow0, q_b = q_a + 8;
#pragma unroll
        for (int j = 0; j < 8; j++) {
#pragma unroll
            for (int r = 0; r < 4; r++) {
                int k = k0 + j * 8 + (lane & 3) * 2 + (r & 1);
                int q = (r < 2) ? q_a : q_b;
                int dlt = q - k; if (dlt < 0) dlt = -dlt;
                sc[j][r] = (dlt <= WIN_) ? sc[j][r] * 0.125f : -1e30f;
            }
        }
        float mx0 = -1e30f, mx1 = -1e30f;
#pragma unroll
        for (int j = 0; j < 8; j++) {
            mx0 = fmaxf(mx0, fmaxf(sc[j][0], sc[j][1]));
            mx1 = fmaxf(mx1, fmaxf(sc[j][2], sc[j][3]));
        }
        for (int off = 1; off < 4; off <<= 1) {
            mx0 = fmaxf(mx0, __shfl_xor_sync(0xffffffffu, mx0, off));
            mx1 = fmaxf(mx1, __shfl_xor_sync(0xffffffffu, mx1, off));
        }
        float mn0 = fmaxf(m0, mx0), mn1 = fmaxf(m1, mx1);
        float c0 = __expf(m0 - mn0), c1 = __expf(m1 - mn1);
        float rs0 = 0.f, rs1 = 0.f;
#pragma unroll
        for (int j = 0; j < 8; j++) {
            sc[j][0] = __expf(sc[j][0] - mn0);
            sc[j][1] = __expf(sc[j][1] - mn0);
            sc[j][2] = __expf(sc[j][2] - mn1);
            sc[j][3] = __expf(sc[j][3] - mn1);
            rs0 += sc[j][0] + sc[j][1];
            rs1 += sc[j][2] + sc[j][3];
        }
        for (int off = 1; off < 4; off <<= 1) {
            rs0 += __shfl_xor_sync(0xffffffffu, rs0, off);
            rs1 += __shfl_xor_sync(0xffffffffu, rs1, off);
        }
        l0s = l0s * c0 + rs0;
        l1s = l1s * c1 + rs1;
        m0 = mn0; m1 = mn1;
#pragma unroll
        for (int j = 0; j < 8; j++) {
            o[j][0] *= c0; o[j][1] *= c0;
            o[j][2] *= c1; o[j][3] *= c1;
        }

#pragma unroll
        for (int kc = 0; kc < 4; kc++) {
            unsigned ph[4];
            {
                __half2 p0 = __floats2half2_rn(sc[2*kc][0],   sc[2*kc][1]);
                __half2 p1 = __floats2half2_rn(sc[2*kc][2],   sc[2*kc][3]);
                __half2 p2 = __floats2half2_rn(sc[2*kc+1][0], sc[2*kc+1][1]);
                __half2 p3 = __floats2half2_rn(sc[2*kc+1][2], sc[2*kc+1][3]);
                ph[0] = *(unsigned*)&p0;
                ph[1] = *(unsigned*)&p1;
                ph[2] = *(unsigned*)&p2;
                ph[3] = *(unsigned*)&p3;
            }
#pragma unroll
            for (int nh = 0; nh < 4; nh++) {
                int vrow = kc * 16 + (lane & 15);
                unsigned voff = (unsigned)(vrow * ATT_STR + nh * 16 + (lane >> 4) * 8) * 2u;
                unsigned r0, r1, r2, r3;
                ldsm4t(r0, r1, r2, r3, sV + voff);
                unsigned b0[2] = {r0, r1}, b1[2] = {r2, r3};
                mma16816(o[2*nh],   ph, b0);
                mma16816(o[2*nh+1], ph, b1);
            }
        }
    }

    // epilogue -> fp16 ATT
    float inv0 = 1.f / l0s, inv1 = 1.f / l1s;
    int qa = b * L_ + q0 + qrow0;
#pragma unroll
    for (int j = 0; j < 8; j++) {
        int c = h * DH_ + j * 8 + (lane & 3) * 2;
        *(__half2*)&g_ATTh[(size_t)qa * D_ + c] =
            __floats2half2_rn(o[j][0] * inv0, o[j][1] * inv0);
        *(__half2*)&g_ATTh[(size_t)(qa + 8) * D_ + c] =
            __floats2half2_rn(o[j][2] * inv1, o[j][3] * inv1);
    }
}

// ---------------- launcher ----------------
extern "C" void kernel_launch(void* const* d_in, const int* in_sizes, int n_in,
                              void* d_out, int out_size) {
    const float* context = (const float*)d_in[0];
    const float* conv_w  = (const float*)d_in[1];
    const float* Wx      = (const float*)d_in[2];
    const float* Wh      = (const float*)d_in[3];
    const float* Wout    = (const float*)d_in[4];
    const float* Aparam  = (const float*)d_in[5];
    const float* gm      = (const float*)d_in[6];
    const float* bm      = (const float*)d_in[7];
    const float* ga      = (const float*)d_in[8];
    const float* ba      = (const float*)d_in[9];
    const float* Wqkv    = (const float*)d_in[10];
    const float* bqkv    = (const float*)d_in[11];
    const float* Wo      = (const float*)d_in[12];
    const float* bo      = (const float*)d_in[13];
    float* out = (float*)d_out;

    static bool init = false;
    static void *pX, *pU, *pXh, *pSEQh, *pQKVh, *pATTh, *pWxH, *pWqkvH, *pWoH;
    if (!init) {
        cudaGetSymbolAddress(&pX, g_X);
        cudaGetSymbolAddress(&pU, g_U);
        cudaGetSymbolAddress(&pXh, g_Xh);
        cudaGetSymbolAddress(&pSEQh, g_SEQh);
        cudaGetSymbolAddress(&pQKVh, g_QKVh);
        cudaGetSymbolAddress(&pATTh, g_ATTh);
        cudaGetSymbolAddress(&pWxH, g_WxH);
        cudaGetSymbolAddress(&pWqkvH, g_WqkvH);
        cudaGetSymbolAddress(&pWoH, g_WoH);
        cudaFuncSetAttribute(attn_mma_kernel,
                             cudaFuncAttributeMaxDynamicSharedMemorySize,
                             3 * 64 * ATT_STR * (int)sizeof(__half));
        init = true;
    }
    const int ATT_SMEM = 3 * 64 * ATT_STR * (int)sizeof(__half);

    zero_state_kernel<<<(B_ * D_ + 255) / 256, 256>>>();
    cvt_weight<<<(NL_ * D_ * S_ + 255) / 256, 256>>>(Wx, (__half*)pWxH, NL_ * D_ * S_);
    cvt_weight<<<(3 * D_ * D_ + 255) / 256, 256>>>(Wqkv, (__half*)pWqkvH, 3 * D_ * D_);
    cvt_weight<<<(D_ * D_ + 255) / 256, 256>>>(Wo, (__half*)pWoH, D_ * D_);

    for (int i = 0; i < NL_; i++) {
        const float* seqin = (i == 0) ? context : out;
        conv_silu_kernel<<<B_ * L_, 128>>>(seqin, conv_w + (size_t)i * 3 * D_);
        mma_gemm3<0><<<dim3(S_ / 128, B_ * L_ / 128), 256>>>(
            (const __half*)pXh, (const __half*)pWxH + (size_t)i * D_ * S_,
            nullptr, (float*)pU, nullptr, B_ * L_, S_, D_);
        ht_part_kernel<<<dim3(B_, 64), 256>>>(Aparam + (size_t)i * S_);
        ht_combine_kernel<<<B_, 256>>>(Aparam + (size_t)i * S_, Wh + (size_t)i * D_ * S_);
        stateout_kernel<<<B_, D_>>>(Wout + (size_t)i * S_ * D_);
        ln_kernel<<<B_ * L_, 128>>>(seqin, nullptr, gm, bm, out, 1,
                                    ((i + 1) % 4) == 0 ? 1 : 0);

        if (((i + 1) % 4) == 0) {
            mma_gemm3<1><<<dim3(3 * D_ / 128, B_ * L_ / 128), 256>>>(
                (const __half*)pSEQh, (const __half*)pWqkvH,
                bqkv, nullptr, (__half*)pQKVh, B_ * L_, 3 * D_, D_);
            attn_mma_kernel<<<dim3(L_ / 64, H_, B_), 128, ATT_SMEM>>>();
            mma_gemm3<1><<<dim3(D_ / 128, B_ * L_ / 128), 256>>>(
                (const __half*)pATTh, (const __half*)pWoH,
                bo, (float*)pX, nullptr, B_ * L_, D_, D_);
            ln_kernel<<<B_ * L_, 128>>>(out, (const float*)pX, ga, ba, out, 0, 0);
        }
    }
}

// round 10
// speedup vs baseline: 1.5124x; 1.0806x over previous
#include <cuda_runtime.h>
#include <cuda_fp16.h>
#include <math.h>

#define B_   4
#define L_   2048
#define D_   512
#define S_   256
#define NL_  6
#define H_   8
#define DH_  64
#define WIN_ 256

// ---------------- scratch (device globals; no allocation) ----------------
__device__ float g_X[B_*L_*D_];         // out-proj fp32 scratch
__device__ float g_U[B_*L_*S_];         // mamba u (fp32)
__device__ float g_STATE[B_*D_];
__device__ float g_PART[64][B_][S_];

__device__ __half g_Xh[B_*L_*D_];       // conv+silu output (fp16)
__device__ __half g_SEQh[B_*L_*D_];     // ln output fp16 shadow (attn input)
__device__ __half g_QKVh[B_*L_*3*D_];   // qkv fp16
__device__ __half g_ATTh[B_*L_*D_];     // attention context fp16
__device__ __half g_WxH[NL_*D_*S_];     // [D][S]
__device__ __half g_WqkvH[3*D_*D_];     // [3D][D]
__device__ __half g_WoH[D_*D_];         // [D][D]

// ---------------- helpers ----------------
__device__ __forceinline__ void ldsm4(unsigned& r0, unsigned& r1, unsigned& r2, unsigned& r3, unsigned addr) {
    asm volatile("ldmatrix.sync.aligned.m8n8.x4.shared.b16 {%0,%1,%2,%3},[%4];"
                 : "=r"(r0), "=r"(r1), "=r"(r2), "=r"(r3) : "r"(addr));
}
__device__ __forceinline__ void ldsm4t(unsigned& r0, unsigned& r1, unsigned& r2, unsigned& r3, unsigned addr) {
    asm volatile("ldmatrix.sync.aligned.m8n8.x4.trans.shared.b16 {%0,%1,%2,%3},[%4];"
                 : "=r"(r0), "=r"(r1), "=r"(r2), "=r"(r3) : "r"(addr));
}
__device__ __forceinline__ void mma16816(float* c, const unsigned* a, const unsigned* b) {
    asm volatile("mma.sync.aligned.m16n8k16.row.col.f32.f16.f16.f32 "
                 "{%0,%1,%2,%3},{%4,%5,%6,%7},{%8,%9},{%0,%1,%2,%3};"
                 : "+f"(c[0]), "+f"(c[1]), "+f"(c[2]), "+f"(c[3])
                 : "r"(a[0]), "r"(a[1]), "r"(a[2]), "r"(a[3]), "r"(b[0]), "r"(b[1]));
}
__device__ __forceinline__ void cpa16(unsigned d, const void* s) {
    asm volatile("cp.async.cg.shared.global [%0],[%1],16;" :: "r"(d), "l"(s));
}
__device__ __forceinline__ void cpa_commit() {
    asm volatile("cp.async.commit_group;");
}
template <int N>
__device__ __forceinline__ void cpa_wait() {
    asm volatile("cp.async.wait_group %0;" :: "n"(N));
}

// ---------------- misc small kernels ----------------
__global__ void cvt_weight(const float* __restrict__ W, __half* __restrict__ Wh, int n) {
    int t = blockIdx.x * 256 + threadIdx.x;
    if (t < n) Wh[t] = __float2half_rn(W[t]);
}

// ---------------- conv (k=3, causal) + SiLU -> fp16 ----------------
__global__ void conv_silu_kernel(const float* __restrict__ seq,
                                 const float* __restrict__ cw) {
    int row = blockIdx.x;
    int l = row & (L_ - 1);
    int t = threadIdx.x;             // 128
    float4 z = make_float4(0.f, 0.f, 0.f, 0.f);
    float4 a0 = (l >= 2) ? ((const float4*)(seq + (size_t)(row - 2) * D_))[t] : z;
    float4 a1 = (l >= 1) ? ((const float4*)(seq + (size_t)(row - 1) * D_))[t] : z;
    float4 a2 = ((const float4*)(seq + (size_t)row * D_))[t];
    float4 w0 = ((const float4*)(cw        ))[t];
    float4 w1 = ((const float4*)(cw +   D_ ))[t];
    float4 w2 = ((const float4*)(cw + 2*D_ ))[t];
    float4 x;
    x.x = w0.x*a0.x + w1.x*a1.x + w2.x*a2.x;
    x.y = w0.y*a0.y + w1.y*a1.y + w2.y*a2.y;
    x.z = w0.z*a0.z + w1.z*a1.z + w2.z*a2.z;
    x.w = w0.w*a0.w + w1.w*a1.w + w2.w*a2.w;
    x.x = x.x / (1.f + __expf(-x.x));
    x.y = x.y / (1.f + __expf(-x.y));
    x.z = x.z / (1.f + __expf(-x.z));
    x.w = x.w / (1.f + __expf(-x.w));
    size_t o = (size_t)row * D_ + t * 4;
    *(__half2*)&g_Xh[o]     = __floats2half2_rn(x.x, x.y);
    *(__half2*)&g_Xh[o + 2] = __floats2half2_rn(x.z, x.w);
}

// ---------------- fp16 cp.async double-buffered GEMM, 128x128 tile ------
template <int TB>
__global__ void __launch_bounds__(256) mma_gemm3(const __half* __restrict__ A,
                                                 const __half* __restrict__ Bm,
                                                 const float* __restrict__ bias,
                                                 float* __restrict__ Cf,
                                                 __half* __restrict__ Ch,
                                                 int M, int N, int K) {
    __shared__ __half Ah[2][128][40];
    constexpr int BR = TB ? 128 : 32;
    constexpr int BSTR = TB ? 40 : 136;
    __shared__ __half Bh[2][BR][BSTR];

    int bm = blockIdx.y * 128, bn = blockIdx.x * 128;
    int tid = threadIdx.x;
    int lane = tid & 31, wid = tid >> 5;
    int wm = (wid & 3) * 32;
    int wn = (wid >> 2) * 64;

    float acc[2][8][4];
#pragma unroll
    for (int i = 0; i < 2; i++)
#pragma unroll
        for (int j = 0; j < 8; j++)
#pragma unroll
            for (int k = 0; k < 4; k++) acc[i][j][k] = 0.f;

    unsigned sA0 = (unsigned)__cvta_generic_to_shared(&Ah[0][0][0]);
    unsigned sA1 = (unsigned)__cvta_generic_to_shared(&Ah[1][0][0]);
    unsigned sB0 = (unsigned)__cvta_generic_to_shared(&Bh[0][0][0]);
    unsigned sB1 = (unsigned)__cvta_generic_to_shared(&Bh[1][0][0]);

    int nk = K >> 5;
    auto issue = [&](int kt) {
        unsigned sa = (kt & 1) ? sA1 : sA0;
        unsigned sb = (kt & 1) ? sB1 : sB0;
        int k0 = kt << 5;
#pragma unroll
        for (int j = 0; j < 2; j++) {
            int ch = tid + 256 * j;
            int r = ch >> 2, c8 = (ch & 3) * 8;
            cpa16(sa + (unsigned)(r * 40 + c8) * 2u,
                  A + (size_t)(bm + r) * K + k0 + c8);
        }
        if (TB == 1) {
#pragma unroll
            for (int j = 0; j < 2; j++) {
                int ch = tid + 256 * j;
                int r = ch >> 2, c8 = (ch & 3) * 8;
                cpa16(sb + (unsigned)(r * 40 + c8) * 2u,
                      Bm + (size_t)(bn + r) * K + k0 + c8);
            }
        } else {
#pragma unroll
            for (int j = 0; j < 2; j++) {
                int ch = tid + 256 * j;
                int r = ch >> 4, c8 = (ch & 15) * 8;
                cpa16(sb + (unsigned)(r * 136 + c8) * 2u,
                      Bm + (size_t)(k0 + r) * N + bn + c8);
            }
        }
        cpa_commit();
    };

    issue(0);
    for (int kt = 0; kt < nk; kt++) {
        if (kt + 1 < nk) { issue(kt + 1); cpa_wait<1>(); }
        else             { cpa_wait<0>(); }
        __syncthreads();

        unsigned sa = (kt & 1) ? sA1 : sA0;
        unsigned sb = (kt & 1) ? sB1 : sB0;
#pragma unroll
        for (int ks = 0; ks < 2; ks++) {
            unsigned af[2][4], bf[8][2];
#pragma unroll
            for (int mi = 0; mi < 2; mi++) {
                int row = wm + mi * 16 + (lane & 15);
                unsigned off = (unsigned)(row * 40 + ks * 16 + (lane >> 4) * 8) * 2u;
                ldsm4(af[mi][0], af[mi][1], af[mi][2], af[mi][3], sa + off);
            }
            if (TB == 1) {
#pragma unroll
                for (int nh = 0; nh < 4; nh++) {
                    int row = wn + nh * 16 + (lane & 15);
                    unsigned off = (unsigned)(row * 40 + ks * 16 + (lane >> 4) * 8) * 2u;
                    unsigned r0, r1, r2, r3;
                    ldsm4(r0, r1, r2, r3, sb + off);
                    bf[nh*2+0][0] = r0; bf[nh*2+0][1] = r2;
                    bf[nh*2+1][0] = r1; bf[nh*2+1][1] = r3;
                }
            } else {
#pragma unroll
                for (int nh = 0; nh < 4; nh++) {
                    int row = ks * 16 + (lane & 15);
                    unsigned off = (unsigned)(row * 136 + wn + nh * 16 + (lane >> 4) * 8) * 2u;
                    unsigned r0, r1, r2, r3;
                    ldsm4t(r0, r1, r2, r3, sb + off);
                    bf[nh*2+0][0] = r0; bf[nh*2+0][1] = r1;
                    bf[nh*2+1][0] = r2; bf[nh*2+1][1] = r3;
                }
            }
#pragma unroll
            for (int mi = 0; mi < 2; mi++)
#pragma unroll
                for (int ni = 0; ni < 8; ni++)
                    mma16816(acc[mi][ni], af[mi], bf[ni]);
        }
        __syncthreads();
    }

#pragma unroll
    for (int mi = 0; mi < 2; mi++)
#pragma unroll
        for (int ni = 0; ni < 8; ni++) {
            int r = bm + wm + mi * 16 + (lane >> 2);
            int c = bn + wn + ni * 8 + (lane & 3) * 2;
            float b0 = bias ? bias[c] : 0.f;
            float b1 = bias ? bias[c + 1] : 0.f;
            float v00 = acc[mi][ni][0] + b0, v01 = acc[mi][ni][1] + b1;
            float v10 = acc[mi][ni][2] + b0, v11 = acc[mi][ni][3] + b1;
            if (Ch) {
                *(__half2*)&Ch[(size_t)r * N + c]       = __floats2half2_rn(v00, v01);
                *(__half2*)&Ch[(size_t)(r + 8) * N + c] = __floats2half2_rn(v10, v11);
            } else {
                Cf[(size_t)r * N + c]           = v00;
                Cf[(size_t)r * N + c + 1]       = v01;
                Cf[(size_t)(r + 8) * N + c]     = v10;
                Cf[(size_t)(r + 8) * N + c + 1] = v11;
            }
        }
}

// ---------------- ssm chunked Horner with decay skip ----------------
__global__ void ht_part_kernel(const float* __restrict__ Aparam) {
    int b = blockIdx.x, c = blockIdx.y;   // 64 chunks of 32
    int s = threadIdx.x;                  // 256
    float a = 1.f / (1.f + expf(-Aparam[s]));
    float wt = powf(a, (float)(32 * (63 - c)));
    float wmax = wt;
    for (int off = 16; off; off >>= 1)
        wmax = fmaxf(wmax, __shfl_xor_sync(0xffffffffu, wmax, off));
    if (wmax < 1e-28f) { g_PART[c][b][s] = 0.f; return; }
    const float* base = g_U + ((size_t)(b * L_) + c * 32) * S_ + s;
    float p = 0.f;
#pragma unroll
    for (int j = 0; j < 32; j++) p = p * a + base[(size_t)j * S_];
    g_PART[c][b][s] = p * wt;
}

// ---------------- fused ht_combine + stateout ----------------
// grid = B_, 512 threads.  Phase 1 (256 threads): hT[s]; phase 2: STATE[d].
__global__ void __launch_bounds__(512) ht_fused_kernel(const float* __restrict__ Aparam,
                                                       const float* __restrict__ Wh,
                                                       const float* __restrict__ Wout,
                                                       int first) {
    __shared__ float sh_ht[S_];
    int b = blockIdx.x;
    int tid = threadIdx.x;
    if (tid < S_) {
        int s = tid;
        float a = 1.f / (1.f + expf(-Aparam[s]));
        float h0 = 0.f;
        if (!first) {
#pragma unroll 8
            for (int d = 0; d < D_; d++) h0 += g_STATE[b * D_ + d] * Wh[(size_t)d * S_ + s];
        }
        float sum = 0.f;
#pragma unroll
        for (int c = 0; c < 64; c++) sum += g_PART[c][b][s];
        sh_ht[s] = powf(a, (float)L_) * h0 + sum;
    }
    __syncthreads();
    int d = tid;
    float acc = 0.f;
#pragma unroll 8
    for (int s = 0; s < S_; s++) acc += sh_ht[s] * Wout[(size_t)s * D_ + d];
    g_STATE[b * D_ + d] = acc;
}

// ---------------- residual + LayerNorm (optional fp16 shadow) ------------
__global__ void ln_kernel(const float* __restrict__ seq, const float* __restrict__ add,
                          const float* __restrict__ gamma, const float* __restrict__ beta,
                          float* __restrict__ out, int bcast, int writeh) {
    __shared__ float red[4];
    __shared__ float stat;
    int row = blockIdx.x;
    int b = row >> 11;
    int t = threadIdx.x;   // 128
    float4 x = ((const float4*)(seq + (size_t)row * D_))[t];
    const float* ap = bcast ? (g_STATE + (size_t)b * D_) : (add + (size_t)row * D_);
    float4 a4 = ((const float4*)ap)[t];
    x.x += a4.x; x.y += a4.y; x.z += a4.z; x.w += a4.w;

    float sum = x.x + x.y + x.z + x.w;
    for (int off = 16; off; off >>= 1) sum += __shfl_xor_sync(0xffffffffu, sum, off);
    if ((t & 31) == 0) red[t >> 5] = sum;
    __syncthreads();
    if (t == 0) stat = (red[0] + red[1] + red[2] + red[3]) * (1.f / D_);
    __syncthreads();
    float mu = stat;
    float d0 = x.x - mu, d1 = x.y - mu, d2 = x.z - mu, d3 = x.w - mu;
    float sq = d0*d0 + d1*d1 + d2*d2 + d3*d3;
    for (int off = 16; off; off >>= 1) sq += __shfl_xor_sync(0xffffffffu, sq, off);
    if ((t & 31) == 0) red[t >> 5] = sq;
    __syncthreads();
    if (t == 0) stat = rsqrtf((red[0] + red[1] + red[2] + red[3]) * (1.f / D_) + 1e-5f);
    __syncthreads();
    float rs = stat;
    float4 g = ((const float4*)gamma)[t], be = ((const float4*)beta)[t];
    float4 y;
    y.x = d0 * rs * g.x + be.x;
    y.y = d1 * rs * g.y + be.y;
    y.z = d2 * rs * g.z + be.z;
    y.w = d3 * rs * g.w + be.w;
    ((float4*)(out + (size_t)row * D_))[t] = y;
    if (writeh) {
        size_t o = (size_t)row * D_ + t * 4;
        *(__half2*)&g_SEQh[o]     = __floats2half2_rn(y.x, y.y);
        *(__half2*)&g_SEQh[o + 2] = __floats2half2_rn(y.z, y.w);
    }
}

// ---------------- banded flash attention, fp16 MMA, cp.async K/V pipe ---
#define ATT_STR 72
#define ATT_T   (64 * ATT_STR)          // halfs per 64x64 tile buffer
extern __shared__ __half s_att[];

__global__ void __launch_bounds__(128) attn_mma_kernel() {
    // layout: Q | K0 V0 | K1 V1
    int b = blockIdx.z, h = blockIdx.y, q0 = blockIdx.x * 64;
    int tid = threadIdx.x, lane = tid & 31, w = tid >> 5;

    unsigned sQ = (unsigned)__cvta_generic_to_shared(s_att);

    int kstart = q0 - WIN_; if (kstart < 0) kstart = 0;
    int kend = q0 + 64 + WIN_; if (kend > L_) kend = L_;
    int nkt = (kend - kstart) >> 6;

    auto issue = [&](int t) {
        unsigned sk = sQ + (unsigned)(ATT_T * (1 + 2 * (t & 1))) * 2u;
        unsigned sv = sk + (unsigned)ATT_T * 2u;
        int k0 = kstart + t * 64;
#pragma unroll
        for (int j = 0; j < 4; j++) {
            int idx = tid + 128 * j;
            int r = idx >> 3, c = (idx & 7) * 8;
            size_t base = (size_t)(b * L_ + k0 + r) * (3 * D_) + h * DH_ + c;
            unsigned doff = (unsigned)(r * ATT_STR + c) * 2u;
            cpa16(sk + doff, g_QKVh + base + D_);
            cpa16(sv + doff, g_QKVh + base + 2 * D_);
        }
        cpa_commit();
    };

    issue(0);
    // load Q tile 64x64 fp16 (regular loads; overlaps with first cp.async)
#pragma unroll
    for (int j = 0; j < 4; j++) {
        int idx = tid + 128 * j;
        int r = idx >> 3, c = (idx & 7) * 8;
        *(uint4*)&s_att[r * ATT_STR + c] =
            *(const uint4*)(g_QKVh + (size_t)(b * L_ + q0 + r) * (3 * D_) + h * DH_ + c);
    }

    float m0 = -1e30f, m1 = -1e30f, l0s = 0.f, l1s = 0.f;
    float o[8][4];
#pragma unroll
    for (int j = 0; j < 8; j++)
#pragma unroll
        for (int r = 0; r < 4; r++) o[j][r] = 0.f;

    int qrow0 = 16 * w + (lane >> 2);

    for (int t = 0; t < nkt; t++) {
        if (t + 1 < nkt) { issue(t + 1); cpa_wait<1>(); }
        else             { cpa_wait<0>(); }
        __syncthreads();

        unsigned sK = sQ + (unsigned)(ATT_T * (1 + 2 * (t & 1))) * 2u;
        unsigned sV = sK + (unsigned)ATT_T * 2u;
        int k0 = kstart + t * 64;

        float sc[8][4];
#pragma unroll
        for (int j = 0; j < 8; j++)
#pragma unroll
            for (int r = 0; r < 4; r++) sc[j][r] = 0.f;

#pragma unroll
        for (int kk = 0; kk < 4; kk++) {
            unsigned aq[4];
            int qrow = 16 * w + (lane & 15);
            unsigned qoff = (unsigned)(qrow * ATT_STR + kk * 16 + (lane >> 4) * 8) * 2u;
            ldsm4(aq[0], aq[1], aq[2], aq[3], sQ + qoff);
#pragma unroll
            for (int nh = 0; nh < 4; nh++) {
                int krow = nh * 16 + (lane & 15);
                unsigned koff = (unsigned)(krow * ATT_STR + kk * 16 + (lane >> 4) * 8) * 2u;
                unsigned r0, r1, r2, r3;
                ldsm4(r0, r1, r2, r3, sK + koff);
                unsigned b0[2] = {r0, r2}, b1[2] = {r1, r3};
                mma16816(sc[2*nh],   aq, b0);
                mma16816(sc[2*nh+1], aq, b1);
            }
        }

        int q_a = q0 + qrow0, q_b = q_a + 8;
#pragma unroll
        for (int j = 0; j < 8; j++) {
#pragma unroll
            for (int r = 0; r < 4; r++) {
                int k = k0 + j * 8 + (lane & 3) * 2 + (r & 1);
                int q = (r < 2) ? q_a : q_b;
                int dlt = q - k; if (dlt < 0) dlt = -dlt;
                sc[j][r] = (dlt <= WIN_) ? sc[j][r] * 0.125f : -1e30f;
            }
        }
        float mx0 = -1e30f, mx1 = -1e30f;
#pragma unroll
        for (int j = 0; j < 8; j++) {
            mx0 = fmaxf(mx0, fmaxf(sc[j][0], sc[j][1]));
            mx1 = fmaxf(mx1, fmaxf(sc[j][2], sc[j][3]));
        }
        for (int off = 1; off < 4; off <<= 1) {
            mx0 = fmaxf(mx0, __shfl_xor_sync(0xffffffffu, mx0, off));
            mx1 = fmaxf(mx1, __shfl_xor_sync(0xffffffffu, mx1, off));
        }
        float mn0 = fmaxf(m0, mx0), mn1 = fmaxf(m1, mx1);
        float c0 = __expf(m0 - mn0), c1 = __expf(m1 - mn1);
        float rs0 = 0.f, rs1 = 0.f;
#pragma unroll
        for (int j = 0; j < 8; j++) {
            sc[j][0] = __expf(sc[j][0] - mn0);
            sc[j][1] = __expf(sc[j][1] - mn0);
            sc[j][2] = __expf(sc[j][2] - mn1);
            sc[j][3] = __expf(sc[j][3] - mn1);
            rs0 += sc[j][0] + sc[j][1];
            rs1 += sc[j][2] + sc[j][3];
        }
        for (int off = 1; off < 4; off <<= 1) {
            rs0 += __shfl_xor_sync(0xffffffffu, rs0, off);
            rs1 += __shfl_xor_sync(0xffffffffu, rs1, off);
        }
        l0s = l0s * c0 + rs0;
        l1s = l1s * c1 + rs1;
        m0 = mn0; m1 = mn1;
#pragma unroll
        for (int j = 0; j < 8; j++) {
            o[j][0] *= c0; o[j][1] *= c0;
            o[j][2] *= c1; o[j][3] *= c1;
        }

#pragma unroll
        for (int kc = 0; kc < 4; kc++) {
            unsigned ph[4];
            {
                __half2 p0 = __floats2half2_rn(sc[2*kc][0],   sc[2*kc][1]);
                __half2 p1 = __floats2half2_rn(sc[2*kc][2],   sc[2*kc][3]);
                __half2 p2 = __floats2half2_rn(sc[2*kc+1][0], sc[2*kc+1][1]);
                __half2 p3 = __floats2half2_rn(sc[2*kc+1][2], sc[2*kc+1][3]);
                ph[0] = *(unsigned*)&p0;
                ph[1] = *(unsigned*)&p1;
                ph[2] = *(unsigned*)&p2;
                ph[3] = *(unsigned*)&p3;
            }
#pragma unroll
            for (int nh = 0; nh < 4; nh++) {
                int vrow = kc * 16 + (lane & 15);
                unsigned voff = (unsigned)(vrow * ATT_STR + nh * 16 + (lane >> 4) * 8) * 2u;
                unsigned r0, r1, r2, r3;
                ldsm4t(r0, r1, r2, r3, sV + voff);
                unsigned b0[2] = {r0, r1}, b1[2] = {r2, r3};
                mma16816(o[2*nh],   ph, b0);
                mma16816(o[2*nh+1], ph, b1);
            }
        }
        __syncthreads();
    }

    // epilogue -> fp16 ATT
    float inv0 = 1.f / l0s, inv1 = 1.f / l1s;
    int qa = b * L_ + q0 + qrow0;
#pragma unroll
    for (int j = 0; j < 8; j++) {
        int c = h * DH_ + j * 8 + (lane & 3) * 2;
        *(__half2*)&g_ATTh[(size_t)qa * D_ + c] =
            __floats2half2_rn(o[j][0] * inv0, o[j][1] * inv0);
        *(__half2*)&g_ATTh[(size_t)(qa + 8) * D_ + c] =
            __floats2half2_rn(o[j][2] * inv1, o[j][3] * inv1);
    }
}

// ---------------- launcher ----------------
extern "C" void kernel_launch(void* const* d_in, const int* in_sizes, int n_in,
                              void* d_out, int out_size) {
    const float* context = (const float*)d_in[0];
    const float* conv_w  = (const float*)d_in[1];
    const float* Wx      = (const float*)d_in[2];
    const float* Wh      = (const float*)d_in[3];
    const float* Wout    = (const float*)d_in[4];
    const float* Aparam  = (const float*)d_in[5];
    const float* gm      = (const float*)d_in[6];
    const float* bm      = (const float*)d_in[7];
    const float* ga      = (const float*)d_in[8];
    const float* ba      = (const float*)d_in[9];
    const float* Wqkv    = (const float*)d_in[10];
    const float* bqkv    = (const float*)d_in[11];
    const float* Wo      = (const float*)d_in[12];
    const float* bo      = (const float*)d_in[13];
    float* out = (float*)d_out;

    static bool init = false;
    static void *pX, *pU, *pXh, *pSEQh, *pQKVh, *pATTh, *pWxH, *pWqkvH, *pWoH;
    if (!init) {
        cudaGetSymbolAddress(&pX, g_X);
        cudaGetSymbolAddress(&pU, g_U);
        cudaGetSymbolAddress(&pXh, g_Xh);
        cudaGetSymbolAddress(&pSEQh, g_SEQh);
        cudaGetSymbolAddress(&pQKVh, g_QKVh);
        cudaGetSymbolAddress(&pATTh, g_ATTh);
        cudaGetSymbolAddress(&pWxH, g_WxH);
        cudaGetSymbolAddress(&pWqkvH, g_WqkvH);
        cudaGetSymbolAddress(&pWoH, g_WoH);
        cudaFuncSetAttribute(attn_mma_kernel,
                             cudaFuncAttributeMaxDynamicSharedMemorySize,
                             5 * ATT_T * (int)sizeof(__half));
        init = true;
    }
    const int ATT_SMEM = 5 * ATT_T * (int)sizeof(__half);

    cvt_weight<<<(NL_ * D_ * S_ + 255) / 256, 256>>>(Wx, (__half*)pWxH, NL_ * D_ * S_);
    cvt_weight<<<(3 * D_ * D_ + 255) / 256, 256>>>(Wqkv, (__half*)pWqkvH, 3 * D_ * D_);
    cvt_weight<<<(D_ * D_ + 255) / 256, 256>>>(Wo, (__half*)pWoH, D_ * D_);

    for (int i = 0; i < NL_; i++) {
        const float* seqin = (i == 0) ? context : out;
        conv_silu_kernel<<<B_ * L_, 128>>>(seqin, conv_w + (size_t)i * 3 * D_);
        mma_gemm3<0><<<dim3(S_ / 128, B_ * L_ / 128), 256>>>(
            (const __half*)pXh, (const __half*)pWxH + (size_t)i * D_ * S_,
            nullptr, (float*)pU, nullptr, B_ * L_, S_, D_);
        ht_part_kernel<<<dim3(B_, 64), 256>>>(Aparam + (size_t)i * S_);
        ht_fused_kernel<<<B_, 512>>>(Aparam + (size_t)i * S_, Wh + (size_t)i * D_ * S_,
                                     Wout + (size_t)i * S_ * D_, i == 0 ? 1 : 0);
        ln_kernel<<<B_ * L_, 128>>>(seqin, nullptr, gm, bm, out, 1,
                                    ((i + 1) % 4) == 0 ? 1 : 0);

        if (((i + 1) % 4) == 0) {
            mma_gemm3<1><<<dim3(3 * D_ / 128, B_ * L_ / 128), 256>>>(
                (const __half*)pSEQh, (const __half*)pWqkvH,
                bqkv, nullptr, (__half*)pQKVh, B_ * L_, 3 * D_, D_);
            attn_mma_kernel<<<dim3(L_ / 64, H_, B_), 128, ATT_SMEM>>>();
            mma_gemm3<1><<<dim3(D_ / 128, B_ * L_ / 128), 256>>>(
                (const __half*)pATTh, (const __half*)pWoH,
                bo, (float*)pX, nullptr, B_ * L_, D_, D_);
            ln_kernel<<<B_ * L_, 128>>>(out, (const float*)pX, ga, ba, out, 0, 0);
        }
    }
}

// round 11
// speedup vs baseline: 1.6397x; 1.0841x over previous
#include <cuda_runtime.h>
#include <cuda_fp16.h>
#include <math.h>

#define B_   4
#define L_   2048
#define D_   512
#define S_   256
#define NL_  6
#define H_   8
#define DH_  64
#define WIN_ 256

// ---------------- scratch (device globals; no allocation) ----------------
__device__ float g_X[B_*L_*D_];         // out-proj fp32 scratch
__device__ float g_U[B_*L_*S_];         // mamba u (fp32)
__device__ float g_STATE[B_*D_];
__device__ float g_PART[128][B_][S_];

__device__ __half g_Xh[B_*L_*D_];       // conv+silu output (fp16)
__device__ __half g_SEQh[B_*L_*D_];     // ln output fp16 shadow
__device__ __half g_QKVh[B_*L_*3*D_];   // qkv fp16
__device__ __half g_ATTh[B_*L_*D_];     // attention context fp16
__device__ __half g_WxH[NL_*D_*S_];     // [D][S]
__device__ __half g_WqkvH[3*D_*D_];     // [3D][D]
__device__ __half g_WoH[D_*D_];         // [D][D]

// ---------------- helpers ----------------
__device__ __forceinline__ void ldsm4(unsigned& r0, unsigned& r1, unsigned& r2, unsigned& r3, unsigned addr) {
    asm volatile("ldmatrix.sync.aligned.m8n8.x4.shared.b16 {%0,%1,%2,%3},[%4];"
                 : "=r"(r0), "=r"(r1), "=r"(r2), "=r"(r3) : "r"(addr));
}
__device__ __forceinline__ void ldsm4t(unsigned& r0, unsigned& r1, unsigned& r2, unsigned& r3, unsigned addr) {
    asm volatile("ldmatrix.sync.aligned.m8n8.x4.trans.shared.b16 {%0,%1,%2,%3},[%4];"
                 : "=r"(r0), "=r"(r1), "=r"(r2), "=r"(r3) : "r"(addr));
}
__device__ __forceinline__ void mma16816(float* c, const unsigned* a, const unsigned* b) {
    asm volatile("mma.sync.aligned.m16n8k16.row.col.f32.f16.f16.f32 "
                 "{%0,%1,%2,%3},{%4,%5,%6,%7},{%8,%9},{%0,%1,%2,%3};"
                 : "+f"(c[0]), "+f"(c[1]), "+f"(c[2]), "+f"(c[3])
                 : "r"(a[0]), "r"(a[1]), "r"(a[2]), "r"(a[3]), "r"(b[0]), "r"(b[1]));
}
__device__ __forceinline__ void cpa16(unsigned d, const void* s) {
    asm volatile("cp.async.cg.shared.global [%0],[%1],16;" :: "r"(d), "l"(s));
}
__device__ __forceinline__ void cpa_commit() {
    asm volatile("cp.async.commit_group;");
}
template <int N>
__device__ __forceinline__ void cpa_wait() {
    asm volatile("cp.async.wait_group %0;" :: "n"(N));
}

// ---------------- misc small kernels ----------------
__global__ void cvt_weight(const float* __restrict__ W, __half* __restrict__ Wh, int n) {
    int t = blockIdx.x * 256 + threadIdx.x;
    if (t < n) Wh[t] = __float2half_rn(W[t]);
}

// ---------------- conv (k=3, causal) + SiLU -> fp16 ----------------
template <typename T>
__global__ void conv_silu_kernel(const T* __restrict__ seq,
                                 const float* __restrict__ cw) {
    int row = blockIdx.x;
    int l = row & (L_ - 1);
    int t = threadIdx.x;             // 128 threads, 4 elems each
    float a0[4] = {0.f, 0.f, 0.f, 0.f}, a1[4] = {0.f, 0.f, 0.f, 0.f}, a2[4];
#pragma unroll
    for (int j = 0; j < 4; j++) a2[j] = (float)seq[(size_t)row * D_ + t * 4 + j];
    if (l >= 1)
#pragma unroll
        for (int j = 0; j < 4; j++) a1[j] = (float)seq[(size_t)(row - 1) * D_ + t * 4 + j];
    if (l >= 2)
#pragma unroll
        for (int j = 0; j < 4; j++) a0[j] = (float)seq[(size_t)(row - 2) * D_ + t * 4 + j];
    float4 w0 = ((const float4*)(cw        ))[t];
    float4 w1 = ((const float4*)(cw +   D_ ))[t];
    float4 w2 = ((const float4*)(cw + 2*D_ ))[t];
    float x0 = w0.x*a0[0] + w1.x*a1[0] + w2.x*a2[0];
    float x1 = w0.y*a0[1] + w1.y*a1[1] + w2.y*a2[1];
    float x2 = w0.z*a0[2] + w1.z*a1[2] + w2.z*a2[2];
    float x3 = w0.w*a0[3] + w1.w*a1[3] + w2.w*a2[3];
    x0 = x0 / (1.f + __expf(-x0));
    x1 = x1 / (1.f + __expf(-x1));
    x2 = x2 / (1.f + __expf(-x2));
    x3 = x3 / (1.f + __expf(-x3));
    size_t o = (size_t)row * D_ + t * 4;
    *(__half2*)&g_Xh[o]     = __floats2half2_rn(x0, x1);
    *(__half2*)&g_Xh[o + 2] = __floats2half2_rn(x2, x3);
}

// ---------------- fp16 cp.async GEMM, 128x128 tile, K-chunk 64 ----------
// A fp16 [M][K]. TB=0: B fp16 [K][N].  TB=1: B fp16 [N][K].
#define GA_STR 72
#define GA_SZ  (128 * GA_STR)           // halfs per A stage
#define GB1_SZ (128 * GA_STR)           // B stage, TB=1
#define GB0_SZ (64 * 136)               // B stage, TB=0
extern __shared__ __half smg[];

template <int TB>
__global__ void __launch_bounds__(256) mma_gemm4(const __half* __restrict__ A,
                                                 const __half* __restrict__ Bm,
                                                 const float* __restrict__ bias,
                                                 float* __restrict__ Cf,
                                                 __half* __restrict__ Ch,
                                                 int M, int N, int K) {
    constexpr int BSZ = TB ? GB1_SZ : GB0_SZ;
    int bm = blockIdx.y * 128, bn = blockIdx.x * 128;
    int tid = threadIdx.x;
    int lane = tid & 31, wid = tid >> 5;
    int wm = (wid & 3) * 32;
    int wn = (wid >> 2) * 64;

    float acc[2][8][4];
#pragma unroll
    for (int i = 0; i < 2; i++)
#pragma unroll
        for (int j = 0; j < 8; j++)
#pragma unroll
            for (int k = 0; k < 4; k++) acc[i][j][k] = 0.f;

    unsigned sbase = (unsigned)__cvta_generic_to_shared(smg);
    // layout: A0 | A1 | B0 | B1

    int nk = K >> 6;
    auto issue = [&](int kt) {
        unsigned sa = sbase + (unsigned)((kt & 1) * GA_SZ) * 2u;
        unsigned sb = sbase + (unsigned)(2 * GA_SZ + (kt & 1) * BSZ) * 2u;
        int k0 = kt << 6;
#pragma unroll
        for (int j = 0; j < 4; j++) {
            int ch = tid + 256 * j;
            int r = ch >> 3, c8 = (ch & 7) * 8;
            cpa16(sa + (unsigned)(r * GA_STR + c8) * 2u,
                  A + (size_t)(bm + r) * K + k0 + c8);
        }
        if (TB == 1) {
#pragma unroll
            for (int j = 0; j < 4; j++) {
                int ch = tid + 256 * j;
                int r = ch >> 3, c8 = (ch & 7) * 8;
                cpa16(sb + (unsigned)(r * GA_STR + c8) * 2u,
                      Bm + (size_t)(bn + r) * K + k0 + c8);
            }
        } else {
#pragma unroll
            for (int j = 0; j < 4; j++) {
                int ch = tid + 256 * j;
                int r = ch >> 4, c8 = (ch & 15) * 8;
                cpa16(sb + (unsigned)(r * 136 + c8) * 2u,
                      Bm + (size_t)(k0 + r) * N + bn + c8);
            }
        }
        cpa_commit();
    };

    issue(0);
    for (int kt = 0; kt < nk; kt++) {
        if (kt + 1 < nk) { issue(kt + 1); cpa_wait<1>(); }
        else             { cpa_wait<0>(); }
        __syncthreads();

        unsigned sa = sbase + (unsigned)((kt & 1) * GA_SZ) * 2u;
        unsigned sb = sbase + (unsigned)(2 * GA_SZ + (kt & 1) * BSZ) * 2u;
#pragma unroll
        for (int ks = 0; ks < 4; ks++) {
            unsigned af[2][4], bf[8][2];
#pragma unroll
            for (int mi = 0; mi < 2; mi++) {
                int row = wm + mi * 16 + (lane & 15);
                unsigned off = (unsigned)(row * GA_STR + ks * 16 + (lane >> 4) * 8) * 2u;
                ldsm4(af[mi][0], af[mi][1], af[mi][2], af[mi][3], sa + off);
            }
            if (TB == 1) {
#pragma unroll
                for (int nh = 0; nh < 4; nh++) {
                    int row = wn + nh * 16 + (lane & 15);
                    unsigned off = (unsigned)(row * GA_STR + ks * 16 + (lane >> 4) * 8) * 2u;
                    unsigned r0, r1, r2, r3;
                    ldsm4(r0, r1, r2, r3, sb + off);
                    bf[nh*2+0][0] = r0; bf[nh*2+0][1] = r2;
                    bf[nh*2+1][0] = r1; bf[nh*2+1][1] = r3;
                }
            } else {
#pragma unroll
                for (int nh = 0; nh < 4; nh++) {
                    int row = ks * 16 + (lane & 15);
                    unsigned off = (unsigned)(row * 136 + wn + nh * 16 + (lane >> 4) * 8) * 2u;
                    unsigned r0, r1, r2, r3;
                    ldsm4t(r0, r1, r2, r3, sb + off);
                    bf[nh*2+0][0] = r0; bf[nh*2+0][1] = r1;
                    bf[nh*2+1][0] = r2; bf[nh*2+1][1] = r3;
                }
            }
#pragma unroll
            for (int mi = 0; mi < 2; mi++)
#pragma unroll
                for (int ni = 0; ni < 8; ni++)
                    mma16816(acc[mi][ni], af[mi], bf[ni]);
        }
        __syncthreads();
    }

#pragma unroll
    for (int mi = 0; mi < 2; mi++)
#pragma unroll
        for (int ni = 0; ni < 8; ni++) {
            int r = bm + wm + mi * 16 + (lane >> 2);
            int c = bn + wn + ni * 8 + (lane & 3) * 2;
            float b0 = bias ? bias[c] : 0.f;
            float b1 = bias ? bias[c + 1] : 0.f;
            float v00 = acc[mi][ni][0] + b0, v01 = acc[mi][ni][1] + b1;
            float v10 = acc[mi][ni][2] + b0, v11 = acc[mi][ni][3] + b1;
            if (Ch) {
                *(__half2*)&Ch[(size_t)r * N + c]       = __floats2half2_rn(v00, v01);
                *(__half2*)&Ch[(size_t)(r + 8) * N + c] = __floats2half2_rn(v10, v11);
            } else {
                Cf[(size_t)r * N + c]           = v00;
                Cf[(size_t)r * N + c + 1]       = v01;
                Cf[(size_t)(r + 8) * N + c]     = v10;
                Cf[(size_t)(r + 8) * N + c + 1] = v11;
            }
        }
}

// ---------------- ssm chunked Horner (chunks of 16) with decay skip ------
__global__ void ht_part_kernel(const float* __restrict__ Aparam) {
    int b = blockIdx.x, c = blockIdx.y;   // 128 chunks of 16
    int s = threadIdx.x;                  // 256
    float a = 1.f / (1.f + expf(-Aparam[s]));
    float wt = powf(a, (float)(16 * (127 - c)));
    float wmax = wt;
    for (int off = 16; off; off >>= 1)
        wmax = fmaxf(wmax, __shfl_xor_sync(0xffffffffu, wmax, off));
    if (wmax < 1e-28f) { g_PART[c][b][s] = 0.f; return; }
    const float* base = g_U + ((size_t)(b * L_) + c * 16) * S_ + s;
    float p = 0.f;
#pragma unroll
    for (int j = 0; j < 16; j++) p = p * a + base[(size_t)j * S_];
    g_PART[c][b][s] = p * wt;
}

// ---------------- fused ht_combine + stateout (split-half phase 1) -------
// grid = B_, 512 threads.
__global__ void __launch_bounds__(512) ht_fused_kernel(const float* __restrict__ Aparam,
                                                       const float* __restrict__ Wh,
                                                       const float* __restrict__ Wout,
                                                       int first) {
    __shared__ float sh_h0[2][S_];
    __shared__ float sh_ps[2][S_];
    __shared__ float sh_ht[S_];
    int b = blockIdx.x;
    int tid = threadIdx.x;
    int s = tid & 255, half = tid >> 8;
    {
        float h0 = 0.f;
        if (!first) {
            int d0 = half * 256;
#pragma unroll 8
            for (int d = d0; d < d0 + 256; d++)
                h0 += g_STATE[b * D_ + d] * Wh[(size_t)d * S_ + s];
        }
        float ps = 0.f;
        int c0 = half * 64;
#pragma unroll
        for (int c = 0; c < 64; c++) ps += g_PART[c0 + c][b][s];
        sh_h0[half][s] = h0;
        sh_ps[half][s] = ps;
    }
    __syncthreads();
    if (tid < S_) {
        float a = 1.f / (1.f + expf(-Aparam[s]));
        sh_ht[s] = powf(a, (float)L_) * (sh_h0[0][s] + sh_h0[1][s])
                 + sh_ps[0][s] + sh_ps[1][s];
    }
    __syncthreads();
    int d = tid;
    float acc = 0.f;
#pragma unroll 8
    for (int ss = 0; ss < S_; ss++) acc += sh_ht[ss] * Wout[(size_t)ss * D_ + d];
    g_STATE[b * D_ + d] = acc;
}

// ---------------- residual + LayerNorm (optional fp16 shadow) ------------
__global__ void ln_kernel(const float* __restrict__ seq, const float* __restrict__ add,
                          const float* __restrict__ gamma, const float* __restrict__ beta,
                          float* __restrict__ out, int bcast, int writeh) {
    __shared__ float red[4];
    __shared__ float stat;
    int row = blockIdx.x;
    int b = row >> 11;
    int t = threadIdx.x;   // 128
    float4 x = ((const float4*)(seq + (size_t)row * D_))[t];
    const float* ap = bcast ? (g_STATE + (size_t)b * D_) : (add + (size_t)row * D_);
    float4 a4 = ((const float4*)ap)[t];
    x.x += a4.x; x.y += a4.y; x.z += a4.z; x.w += a4.w;

    float sum = x.x + x.y + x.z + x.w;
    for (int off = 16; off; off >>= 1) sum += __shfl_xor_sync(0xffffffffu, sum, off);
    if ((t & 31) == 0) red[t >> 5] = sum;
    __syncthreads();
    if (t == 0) stat = (red[0] + red[1] + red[2] + red[3]) * (1.f / D_);
    __syncthreads();
    float mu = stat;
    float d0 = x.x - mu, d1 = x.y - mu, d2 = x.z - mu, d3 = x.w - mu;
    float sq = d0*d0 + d1*d1 + d2*d2 + d3*d3;
    for (int off = 16; off; off >>= 1) sq += __shfl_xor_sync(0xffffffffu, sq, off);
    if ((t & 31) == 0) red[t >> 5] = sq;
    __syncthreads();
    if (t == 0) stat = rsqrtf((red[0] + red[1] + red[2] + red[3]) * (1.f / D_) + 1e-5f);
    __syncthreads();
    float rs = stat;
    float4 g = ((const float4*)gamma)[t], be = ((const float4*)beta)[t];
    float4 y;
    y.x = d0 * rs * g.x + be.x;
    y.y = d1 * rs * g.y + be.y;
    y.z = d2 * rs * g.z + be.z;
    y.w = d3 * rs * g.w + be.w;
    ((float4*)(out + (size_t)row * D_))[t] = y;
    if (writeh) {
        size_t o = (size_t)row * D_ + t * 4;
        *(__half2*)&g_SEQh[o]     = __floats2half2_rn(y.x, y.y);
        *(__half2*)&g_SEQh[o + 2] = __floats2half2_rn(y.z, y.w);
    }
}

// ---------------- banded flash attention, fp16 MMA, cp.async K/V pipe ---
#define ATT_STR 72
#define ATT_T   (64 * ATT_STR)
extern __shared__ __half s_att[];

__global__ void __launch_bounds__(128) attn_mma_kernel() {
    int b = blockIdx.z, h = blockIdx.y, q0 = blockIdx.x * 64;
    int tid = threadIdx.x, lane = tid & 31, w = tid >> 5;

    unsigned sQ = (unsigned)__cvta_generic_to_shared(s_att);

    int kstart = q0 - WIN_; if (kstart < 0) kstart = 0;
    int kend = q0 + 64 + WIN_; if (kend > L_) kend = L_;
    int nkt = (kend - kstart) >> 6;

    auto issue = [&](int t) {
        unsigned sk = sQ + (unsigned)(ATT_T * (1 + 2 * (t & 1))) * 2u;
        unsigned sv = sk + (unsigned)ATT_T * 2u;
        int k0 = kstart + t * 64;
#pragma unroll
        for (int j = 0; j < 4; j++) {
            int idx = tid + 128 * j;
            int r = idx >> 3, c = (idx & 7) * 8;
            size_t base = (size_t)(b * L_ + k0 + r) * (3 * D_) + h * DH_ + c;
            unsigned doff = (unsigned)(r * ATT_STR + c) * 2u;
            cpa16(sk + doff, g_QKVh + base + D_);
            cpa16(sv + doff, g_QKVh + base + 2 * D_);
        }
        cpa_commit();
    };

    issue(0);
#pragma unroll
    for (int j = 0; j < 4; j++) {
        int idx = tid + 128 * j;
        int r = idx >> 3, c = (idx & 7) * 8;
        *(uint4*)&s_att[r * ATT_STR + c] =
            *(const uint4*)(g_QKVh + (size_t)(b * L_ + q0 + r) * (3 * D_) + h * DH_ + c);
    }

    float m0 = -1e30f, m1 = -1e30f, l0s = 0.f, l1s = 0.f;
    float o[8][4];
#pragma unroll
    for (int j = 0; j < 8; j++)
#pragma unroll
        for (int r = 0; r < 4; r++) o[j][r] = 0.f;

    int qrow0 = 16 * w + (lane >> 2);

    for (int t = 0; t < nkt; t++) {
        if (t + 1 < nkt) { issue(t + 1); cpa_wait<1>(); }
        else             { cpa_wait<0>(); }
        __syncthreads();

        unsigned sK = sQ + (unsigned)(ATT_T * (1 + 2 * (t & 1))) * 2u;
        unsigned sV = sK + (unsigned)ATT_T * 2u;
        int k0 = kstart + t * 64;

        float sc[8][4];
#pragma unroll
        for (int j = 0; j < 8; j++)
#pragma unroll
            for (int r = 0; r < 4; r++) sc[j][r] = 0.f;

#pragma unroll
        for (int kk = 0; kk < 4; kk++) {
            unsigned aq[4];
            int qrow = 16 * w + (lane & 15);
            unsigned qoff = (unsigned)(qrow * ATT_STR + kk * 16 + (lane >> 4) * 8) * 2u;
            ldsm4(aq[0], aq[1], aq[2], aq[3], sQ + qoff);
#pragma unroll
            for (int nh = 0; nh < 4; nh++) {
                int krow = nh * 16 + (lane & 15);
                unsigned koff = (unsigned)(krow * ATT_STR + kk * 16 + (lane >> 4) * 8) * 2u;
                unsigned r0, r1, r2, r3;
                ldsm4(r0, r1, r2, r3, sK + koff);
                unsigned b0[2] = {r0, r2}, b1[2] = {r1, r3};
                mma16816(sc[2*nh],   aq, b0);
                mma16816(sc[2*nh+1], aq, b1);
            }
        }

        int q_a = q0 + qrow0, q_b = q_a + 8;
#pragma unroll
        for (int j = 0; j < 8; j++) {
#pragma unroll
            for (int r = 0; r < 4; r++) {
                int k = k0 + j * 8 + (lane & 3) * 2 + (r & 1);
                int q = (r < 2) ? q_a : q_b;
                int dlt = q - k; if (dlt < 0) dlt = -dlt;
                sc[j][r] = (dlt <= WIN_) ? sc[j][r] * 0.125f : -1e30f;
            }
        }
        float mx0 = -1e30f, mx1 = -1e30f;
#pragma unroll
        for (int j = 0; j < 8; j++) {
            mx0 = fmaxf(mx0, fmaxf(sc[j][0], sc[j][1]));
            mx1 = fmaxf(mx1, fmaxf(sc[j][2], sc[j][3]));
        }
        for (int off = 1; off < 4; off <<= 1) {
            mx0 = fmaxf(mx0, __shfl_xor_sync(0xffffffffu, mx0, off));
            mx1 = fmaxf(mx1, __shfl_xor_sync(0xffffffffu, mx1, off));
        }
        float mn0 = fmaxf(m0, mx0), mn1 = fmaxf(m1, mx1);
        float c0 = __expf(m0 - mn0), c1 = __expf(m1 - mn1);
        float rs0 = 0.f, rs1 = 0.f;
#pragma unroll
        for (int j = 0; j < 8; j++) {
            sc[j][0] = __expf(sc[j][0] - mn0);
            sc[j][1] = __expf(sc[j][1] - mn0);
            sc[j][2] = __expf(sc[j][2] - mn1);
            sc[j][3] = __expf(sc[j][3] - mn1);
            rs0 += sc[j][0] + sc[j][1];
            rs1 += sc[j][2] + sc[j][3];
        }
        for (int off = 1; off < 4; off <<= 1) {
            rs0 += __shfl_xor_sync(0xffffffffu, rs0, off);
            rs1 += __shfl_xor_sync(0xffffffffu, rs1, off);
        }
        l0s = l0s * c0 + rs0;
        l1s = l1s * c1 + rs1;
        m0 = mn0; m1 = mn1;
#pragma unroll
        for (int j = 0; j < 8; j++) {
            o[j][0] *= c0; o[j][1] *= c0;
            o[j][2] *= c1; o[j][3] *= c1;
        }

#pragma unroll
        for (int kc = 0; kc < 4; kc++) {
            unsigned ph[4];
            {
                __half2 p0 = __floats2half2_rn(sc[2*kc][0],   sc[2*kc][1]);
                __half2 p1 = __floats2half2_rn(sc[2*kc][2],   sc[2*kc][3]);
                __half2 p2 = __floats2half2_rn(sc[2*kc+1][0], sc[2*kc+1][1]);
                __half2 p3 = __floats2half2_rn(sc[2*kc+1][2], sc[2*kc+1][3]);
                ph[0] = *(unsigned*)&p0;
                ph[1] = *(unsigned*)&p1;
                ph[2] = *(unsigned*)&p2;
                ph[3] = *(unsigned*)&p3;
            }
#pragma unroll
            for (int nh = 0; nh < 4; nh++) {
                int vrow = kc * 16 + (lane & 15);
                unsigned voff = (unsigned)(vrow * ATT_STR + nh * 16 + (lane >> 4) * 8) * 2u;
                unsigned r0, r1, r2, r3;
                ldsm4t(r0, r1, r2, r3, sV + voff);
                unsigned b0[2] = {r0, r1}, b1[2] = {r2, r3};
                mma16816(o[2*nh],   ph, b0);
                mma16816(o[2*nh+1], ph, b1);
            }
        }
        __syncthreads();
    }

    float inv0 = 1.f / l0s, inv1 = 1.f / l1s;
    int qa = b * L_ + q0 + qrow0;
#pragma unroll
    for (int j = 0; j < 8; j++) {
        int c = h * DH_ + j * 8 + (lane & 3) * 2;
        *(__half2*)&g_ATTh[(size_t)qa * D_ + c] =
            __floats2half2_rn(o[j][0] * inv0, o[j][1] * inv0);
        *(__half2*)&g_ATTh[(size_t)(qa + 8) * D_ + c] =
            __floats2half2_rn(o[j][2] * inv1, o[j][3] * inv1);
    }
}

// ---------------- launcher ----------------
extern "C" void kernel_launch(void* const* d_in, const int* in_sizes, int n_in,
                              void* d_out, int out_size) {
    const float* context = (const float*)d_in[0];
    const float* conv_w  = (const float*)d_in[1];
    const float* Wx      = (const float*)d_in[2];
    const float* Wh      = (const float*)d_in[3];
    const float* Wout    = (const float*)d_in[4];
    const float* Aparam  = (const float*)d_in[5];
    const float* gm      = (const float*)d_in[6];
    const float* bm      = (const float*)d_in[7];
    const float* ga      = (const float*)d_in[8];
    const float* ba      = (const float*)d_in[9];
    const float* Wqkv    = (const float*)d_in[10];
    const float* bqkv    = (const float*)d_in[11];
    const float* Wo      = (const float*)d_in[12];
    const float* bo      = (const float*)d_in[13];
    float* out = (float*)d_out;

    static bool init = false;
    static void *pX, *pU, *pXh, *pSEQh, *pQKVh, *pATTh, *pWxH, *pWqkvH, *pWoH;
    if (!init) {
        cudaGetSymbolAddress(&pX, g_X);
        cudaGetSymbolAddress(&pU, g_U);
        cudaGetSymbolAddress(&pXh, g_Xh);
        cudaGetSymbolAddress(&pSEQh, g_SEQh);
        cudaGetSymbolAddress(&pQKVh, g_QKVh);
        cudaGetSymbolAddress(&pATTh, g_ATTh);
        cudaGetSymbolAddress(&pWxH, g_WxH);
        cudaGetSymbolAddress(&pWqkvH, g_WqkvH);
        cudaGetSymbolAddress(&pWoH, g_WoH);
        cudaFuncSetAttribute(attn_mma_kernel,
                             cudaFuncAttributeMaxDynamicSharedMemorySize,
                             5 * ATT_T * (int)sizeof(__half));
        cudaFuncSetAttribute(mma_gemm4<0>,
                             cudaFuncAttributeMaxDynamicSharedMemorySize,
                             (2 * GA_SZ + 2 * GB0_SZ) * (int)sizeof(__half));
        cudaFuncSetAttribute(mma_gemm4<1>,
                             cudaFuncAttributeMaxDynamicSharedMemorySize,
                             (2 * GA_SZ + 2 * GB1_SZ) * (int)sizeof(__half));
        init = true;
    }
    const int ATT_SMEM = 5 * ATT_T * (int)sizeof(__half);
    const int G0_SMEM  = (2 * GA_SZ + 2 * GB0_SZ) * (int)sizeof(__half);
    const int G1_SMEM  = (2 * GA_SZ + 2 * GB1_SZ) * (int)sizeof(__half);

    cvt_weight<<<(NL_ * D_ * S_ + 255) / 256, 256>>>(Wx, (__half*)pWxH, NL_ * D_ * S_);
    cvt_weight<<<(3 * D_ * D_ + 255) / 256, 256>>>(Wqkv, (__half*)pWqkvH, 3 * D_ * D_);
    cvt_weight<<<(D_ * D_ + 255) / 256, 256>>>(Wo, (__half*)pWoH, D_ * D_);

    for (int i = 0; i < NL_; i++) {
        if (i == 0)
            conv_silu_kernel<float><<<B_ * L_, 128>>>(context, conv_w);
        else
            conv_silu_kernel<__half><<<B_ * L_, 128>>>((const __half*)pSEQh,
                                                       conv_w + (size_t)i * 3 * D_);
        mma_gemm4<0><<<dim3(S_ / 128, B_ * L_ / 128), 256, G0_SMEM>>>(
            (const __half*)pXh, (const __half*)pWxH + (size_t)i * D_ * S_,
            nullptr, (float*)pU, nullptr, B_ * L_, S_, D_);
        ht_part_kernel<<<dim3(B_, 128), 256>>>(Aparam + (size_t)i * S_);
        ht_fused_kernel<<<B_, 512>>>(Aparam + (size_t)i * S_, Wh + (size_t)i * D_ * S_,
                                     Wout + (size_t)i * S_ * D_, i == 0 ? 1 : 0);
        const float* seqin = (i == 0) ? context : out;
        ln_kernel<<<B_ * L_, 128>>>(seqin, nullptr, gm, bm, out, 1,
                                    i < 5 ? 1 : 0);

        if (((i + 1) % 4) == 0) {
            mma_gemm4<1><<<dim3(3 * D_ / 128, B_ * L_ / 128), 256, G1_SMEM>>>(
                (const __half*)pSEQh, (const __half*)pWqkvH,
                bqkv, nullptr, (__half*)pQKVh, B_ * L_, 3 * D_, D_);
            attn_mma_kernel<<<dim3(L_ / 64, H_, B_), 128, ATT_SMEM>>>();
            mma_gemm4<1><<<dim3(D_ / 128, B_ * L_ / 128), 256, G1_SMEM>>>(
                (const __half*)pATTh, (const __half*)pWoH,
                bo, (float*)pX, nullptr, B_ * L_, D_, D_);
            ln_kernel<<<B_ * L_, 128>>>(out, (const float*)pX, ga, ba, out, 0, 1);
        }
    }
}

// round 13
// speedup vs baseline: 1.6867x; 1.0287x over previous
#include <cuda_runtime.h>
#include <cuda_fp16.h>
#include <math.h>

#define B_   4
#define L_   2048
#define D_   512
#define S_   256
#define NL_  6
#define H_   8
#define DH_  64
#define WIN_ 256

// ---------------- scratch (device globals; no allocation) ----------------
__device__ float g_X[B_*L_*D_];         // out-proj fp32 scratch
__device__ float g_STATE[B_*D_];
__device__ float g_PART[128][B_][S_];

__device__ __half g_Uh[B_*L_*S_];       // mamba u (fp16)
__device__ __half g_Xh[B_*L_*D_];       // conv+silu output (fp16)
__device__ __half g_SEQh[B_*L_*D_];     // ln output fp16 shadow
__device__ __half g_QKVh[B_*L_*3*D_];   // qkv fp16
__device__ __half g_ATTh[B_*L_*D_];     // attention context fp16
__device__ __half g_WxH[NL_*D_*S_];     // [D][S]
__device__ __half g_WqkvH[3*D_*D_];     // [3D][D]
__device__ __half g_WoH[D_*D_];         // [D][D]

// ---------------- helpers ----------------
__device__ __forceinline__ void ldsm4(unsigned& r0, unsigned& r1, unsigned& r2, unsigned& r3, unsigned addr) {
    asm volatile("ldmatrix.sync.aligned.m8n8.x4.shared.b16 {%0,%1,%2,%3},[%4];"
                 : "=r"(r0), "=r"(r1), "=r"(r2), "=r"(r3) : "r"(addr));
}
__device__ __forceinline__ void ldsm4t(unsigned& r0, unsigned& r1, unsigned& r2, unsigned& r3, unsigned addr) {
    asm volatile("ldmatrix.sync.aligned.m8n8.x4.trans.shared.b16 {%0,%1,%2,%3},[%4];"
                 : "=r"(r0), "=r"(r1), "=r"(r2), "=r"(r3) : "r"(addr));
}
__device__ __forceinline__ void mma16816(float* c, const unsigned* a, const unsigned* b) {
    asm volatile("mma.sync.aligned.m16n8k16.row.col.f32.f16.f16.f32 "
                 "{%0,%1,%2,%3},{%4,%5,%6,%7},{%8,%9},{%0,%1,%2,%3};"
                 : "+f"(c[0]), "+f"(c[1]), "+f"(c[2]), "+f"(c[3])
                 : "r"(a[0]), "r"(a[1]), "r"(a[2]), "r"(a[3]), "r"(b[0]), "r"(b[1]));
}
__device__ __forceinline__ void cpa16(unsigned d, const void* s) {
    asm volatile("cp.async.cg.shared.global [%0],[%1],16;" :: "r"(d), "l"(s));
}
__device__ __forceinline__ void cpa_commit() {
    asm volatile("cp.async.commit_group;");
}
template <int N>
__device__ __forceinline__ void cpa_wait() {
    asm volatile("cp.async.wait_group %0;" :: "n"(N));
}

// ---------------- merged weight conversion ----------------
#define NWX (NL_*D_*S_)
#define NWQ (3*D_*D_)
#define NWO (D_*D_)
__global__ void cvt_weights_all(const float* __restrict__ Wx,
                                const float* __restrict__ Wqkv,
                                const float* __restrict__ Wo) {
    int t = blockIdx.x * 256 + threadIdx.x;
    if (t < NWX) {
        g_WxH[t] = __float2half_rn(Wx[t]);
    } else if (t < NWX + NWQ) {
        int u = t - NWX;
        g_WqkvH[u] = __float2half_rn(Wqkv[u]);
    } else if (t < NWX + NWQ + NWO) {
        int u = t - NWX - NWQ;
        g_WoH[u] = __float2half_rn(Wo[u]);
    }
}

// ---------------- conv (k=3, causal) + SiLU -> fp16 ----------------
// fp32 input (layer 0): 128 threads, float4 each
__global__ void conv_silu_f32(const float* __restrict__ seq,
                              const float* __restrict__ cw) {
    int row = blockIdx.x;
    int l = row & (L_ - 1);
    int t = threadIdx.x;
    float4 z = make_float4(0.f, 0.f, 0.f, 0.f);
    float4 a0 = (l >= 2) ? ((const float4*)(seq + (size_t)(row - 2) * D_))[t] : z;
    float4 a1 = (l >= 1) ? ((const float4*)(seq + (size_t)(row - 1) * D_))[t] : z;
    float4 a2 = ((const float4*)(seq + (size_t)row * D_))[t];
    float4 w0 = ((const float4*)(cw        ))[t];
    float4 w1 = ((const float4*)(cw +   D_ ))[t];
    float4 w2 = ((const float4*)(cw + 2*D_ ))[t];
    float x0 = w0.x*a0.x + w1.x*a1.x + w2.x*a2.x;
    float x1 = w0.y*a0.y + w1.y*a1.y + w2.y*a2.y;
    float x2 = w0.z*a0.z + w1.z*a1.z + w2.z*a2.z;
    float x3 = w0.w*a0.w + w1.w*a1.w + w2.w*a2.w;
    x0 = x0 / (1.f + __expf(-x0));
    x1 = x1 / (1.f + __expf(-x1));
    x2 = x2 / (1.f + __expf(-x2));
    x3 = x3 / (1.f + __expf(-x3));
    size_t o = (size_t)row * D_ + t * 4;
    *(__half2*)&g_Xh[o]     = __floats2half2_rn(x0, x1);
    *(__half2*)&g_Xh[o + 2] = __floats2half2_rn(x2, x3);
}

// fp16 input (layers 1-5): 128 threads = 2 rows x 64 lanes, uint4 (8 halfs) each
__global__ void conv_silu_f16(const __half* __restrict__ seq,
                              const float* __restrict__ cw) {
    int t = threadIdx.x;
    int row = blockIdx.x * 2 + (t >> 6);
    int tt = t & 63;
    int l = row & (L_ - 1);
    size_t base = (size_t)row * D_ + tt * 8;
    uint4 z4 = make_uint4(0u, 0u, 0u, 0u);
    uint4 v2 = *(const uint4*)(seq + base);
    uint4 v1 = (l >= 1) ? *(const uint4*)(seq + base - D_) : z4;
    uint4 v0 = (l >= 2) ? *(const uint4*)(seq + base - 2 * D_) : z4;
    float4 wa0 = ((const float4*)(cw        ))[tt * 2];
    float4 wb0 = ((const float4*)(cw        ))[tt * 2 + 1];
    float4 wa1 = ((const float4*)(cw +   D_ ))[tt * 2];
    float4 wb1 = ((const float4*)(cw +   D_ ))[tt * 2 + 1];
    float4 wa2 = ((const float4*)(cw + 2*D_ ))[tt * 2];
    float4 wb2 = ((const float4*)(cw + 2*D_ ))[tt * 2 + 1];
    float w0[8] = {wa0.x, wa0.y, wa0.z, wa0.w, wb0.x, wb0.y, wb0.z, wb0.w};
    float w1[8] = {wa1.x, wa1.y, wa1.z, wa1.w, wb1.x, wb1.y, wb1.z, wb1.w};
    float w2[8] = {wa2.x, wa2.y, wa2.z, wa2.w, wb2.x, wb2.y, wb2.z, wb2.w};
    const __half2* h0 = (const __half2*)&v0;
    const __half2* h1 = (const __half2*)&v1;
    const __half2* h2 = (const __half2*)&v2;
    uint4 outv;
    __half2* ov = (__half2*)&outv;
#pragma unroll
    for (int j = 0; j < 4; j++) {
        float2 f0 = __half22float2(h0[j]);
        float2 f1 = __half22float2(h1[j]);
        float2 f2 = __half22float2(h2[j]);
        float xa = w0[2*j]   * f0.x + w1[2*j]   * f1.x + w2[2*j]   * f2.x;
        float xb = w0[2*j+1] * f0.y + w1[2*j+1] * f1.y + w2[2*j+1] * f2.y;
        xa = xa / (1.f + __expf(-xa));
        xb = xb / (1.f + __expf(-xb));
        ov[j] = __floats2half2_rn(xa, xb);
    }
    *(uint4*)&g_Xh[base] = outv;
}

// ---------------- fp16 cp.async GEMM, 128x128 tile, K-chunk 64 ----------
#define GA_STR 72
#define GA_SZ  (128 * GA_STR)
#define GB1_SZ (128 * GA_STR)
#define GB0_SZ (64 * 136)
extern __shared__ __half smg[];

template <int TB>
__global__ void __launch_bounds__(256) mma_gemm4(const __half* __restrict__ A,
                                                 const __half* __restrict__ Bm,
                                                 const float* __restrict__ bias,
                                                 float* __restrict__ Cf,
                                                 __half* __restrict__ Ch,
                                                 int M, int N, int K) {
    constexpr int BSZ = TB ? GB1_SZ : GB0_SZ;
    int bm = blockIdx.y * 128, bn = blockIdx.x * 128;
    int tid = threadIdx.x;
    int lane = tid & 31, wid = tid >> 5;
    int wm = (wid & 3) * 32;
    int wn = (wid >> 2) * 64;

    float acc[2][8][4];
#pragma unroll
    for (int i = 0; i < 2; i++)
#pragma unroll
        for (int j = 0; j < 8; j++)
#pragma unroll
            for (int k = 0; k < 4; k++) acc[i][j][k] = 0.f;

    unsigned sbase = (unsigned)__cvta_generic_to_shared(smg);

    int nk = K >> 6;
    auto issue = [&](int kt) {
        unsigned sa = sbase + (unsigned)((kt & 1) * GA_SZ) * 2u;
        unsigned sb = sbase + (unsigned)(2 * GA_SZ + (kt & 1) * BSZ) * 2u;
        int k0 = kt << 6;
#pragma unroll
        for (int j = 0; j < 4; j++) {
            int ch = tid + 256 * j;
            int r = ch >> 3, c8 = (ch & 7) * 8;
            cpa16(sa + (unsigned)(r * GA_STR + c8) * 2u,
                  A + (size_t)(bm + r) * K + k0 + c8);
        }
        if (TB == 1) {
#pragma unroll
            for (int j = 0; j < 4; j++) {
                int ch = tid + 256 * j;
                int r = ch >> 3, c8 = (ch & 7) * 8;
                cpa16(sb + (unsigned)(r * GA_STR + c8) * 2u,
                      Bm + (size_t)(bn + r) * K + k0 + c8);
            }
        } else {
#pragma unroll
            for (int j = 0; j < 4; j++) {
                int ch = tid + 256 * j;
                int r = ch >> 4, c8 = (ch & 15) * 8;
                cpa16(sb + (unsigned)(r * 136 + c8) * 2u,
                      Bm + (size_t)(k0 + r) * N + bn + c8);
            }
        }
        cpa_commit();
    };

    issue(0);
    for (int kt = 0; kt < nk; kt++) {
        if (kt + 1 < nk) { issue(kt + 1); cpa_wait<1>(); }
        else             { cpa_wait<0>(); }
        __syncthreads();

        unsigned sa = sbase + (unsigned)((kt & 1) * GA_SZ) * 2u;
        unsigned sb = sbase + (unsigned)(2 * GA_SZ + (kt & 1) * BSZ) * 2u;
#pragma unroll
        for (int ks = 0; ks < 4; ks++) {
            unsigned af[2][4], bf[8][2];
#pragma unroll
            for (int mi = 0; mi < 2; mi++) {
                int row = wm + mi * 16 + (lane & 15);
                unsigned off = (unsigned)(row * GA_STR + ks * 16 + (lane >> 4) * 8) * 2u;
                ldsm4(af[mi][0], af[mi][1], af[mi][2], af[mi][3], sa + off);
            }
            if (TB == 1) {
#pragma unroll
                for (int nh = 0; nh < 4; nh++) {
                    int row = wn + nh * 16 + (lane & 15);
                    unsigned off = (unsigned)(row * GA_STR + ks * 16 + (lane >> 4) * 8) * 2u;
                    unsigned r0, r1, r2, r3;
                    ldsm4(r0, r1, r2, r3, sb + off);
                    bf[nh*2+0][0] = r0; bf[nh*2+0][1] = r2;
                    bf[nh*2+1][0] = r1; bf[nh*2+1][1] = r3;
                }
            } else {
#pragma unroll
                for (int nh = 0; nh < 4; nh++) {
                    int row = ks * 16 + (lane & 15);
                    unsigned off = (unsigned)(row * 136 + wn + nh * 16 + (lane >> 4) * 8) * 2u;
                    unsigned r0, r1, r2, r3;
                    ldsm4t(r0, r1, r2, r3, sb + off);
                    bf[nh*2+0][0] = r0; bf[nh*2+0][1] = r1;
                    bf[nh*2+1][0] = r2; bf[nh*2+1][1] = r3;
                }
            }
#pragma unroll
            for (int mi = 0; mi < 2; mi++)
#pragma unroll
                for (int ni = 0; ni < 8; ni++)
                    mma16816(acc[mi][ni], af[mi], bf[ni]);
        }
        __syncthreads();
    }

#pragma unroll
    for (int mi = 0; mi < 2; mi++)
#pragma unroll
        for (int ni = 0; ni < 8; ni++) {
            int r = bm + wm + mi * 16 + (lane >> 2);
            int c = bn + wn + ni * 8 + (lane & 3) * 2;
            float b0 = bias ? bias[c] : 0.f;
            float b1 = bias ? bias[c + 1] : 0.f;
            float v00 = acc[mi][ni][0] + b0, v01 = acc[mi][ni][1] + b1;
            float v10 = acc[mi][ni][2] + b0, v11 = acc[mi][ni][3] + b1;
            if (Ch) {
                *(__half2*)&Ch[(size_t)r * N + c]       = __floats2half2_rn(v00, v01);
                *(__half2*)&Ch[(size_t)(r + 8) * N + c] = __floats2half2_rn(v10, v11);
            } else {
                Cf[(size_t)r * N + c]           = v00;
                Cf[(size_t)r * N + c + 1]       = v01;
                Cf[(size_t)(r + 8) * N + c]     = v10;
                Cf[(size_t)(r + 8) * N + c + 1] = v11;
            }
        }
}

// ---------------- ssm chunked Horner (chunks of 16, fp16 U) -------------
__global__ void ht_part_kernel(const float* __restrict__ Aparam) {
    int b = blockIdx.x, c = blockIdx.y;   // 128 chunks of 16
    int s = threadIdx.x;                  // 256
    float a = 1.f / (1.f + expf(-Aparam[s]));
    float wt = powf(a, (float)(16 * (127 - c)));
    float wmax = wt;
    for (int off = 16; off; off >>= 1)
        wmax = fmaxf(wmax, __shfl_xor_sync(0xffffffffu, wmax, off));
    if (wmax < 1e-28f) { g_PART[c][b][s] = 0.f; return; }
    const __half* base = g_Uh + ((size_t)(b * L_) + c * 16) * S_ + s;
    float p = 0.f;
#pragma unroll
    for (int j = 0; j < 16; j++) p = p * a + __half2float(base[(size_t)j * S_]);
    g_PART[c][b][s] = p * wt;
}

// ---------------- fused ht_combine + stateout (split-half phase 1) -------
__global__ void __launch_bounds__(512) ht_fused_kernel(const float* __restrict__ Aparam,
                                                       const float* __restrict__ Wh,
                                                       const float* __restrict__ Wout,
                                                       int first) {
    __shared__ float sh_h0[2][S_];
    __shared__ float sh_ps[2][S_];
    __shared__ float sh_ht[S_];
    int b = blockIdx.x;
    int tid = threadIdx.x;
    int s = tid & 255, half = tid >> 8;
    {
        float h0 = 0.f;
        if (!first) {
            int d0 = half * 256;
#pragma unroll 8
            for (int d = d0; d < d0 + 256; d++)
                h0 += g_STATE[b * D_ + d] * Wh[(size_t)d * S_ + s];
        }
        float ps = 0.f;
        int c0 = half * 64;
#pragma unroll
        for (int c = 0; c < 64; c++) ps += g_PART[c0 + c][b][s];
        sh_h0[half][s] = h0;
        sh_ps[half][s] = ps;
    }
    __syncthreads();
    if (tid < S_) {
        float a = 1.f / (1.f + expf(-Aparam[s]));
        sh_ht[s] = powf(a, (float)L_) * (sh_h0[0][s] + sh_h0[1][s])
                 + sh_ps[0][s] + sh_ps[1][s];
    }
    __syncthreads();
    int d = tid;
    float acc = 0.f;
#pragma unroll 8
    for (int ss = 0; ss < S_; ss++) acc += sh_ht[ss] * Wout[(size_t)ss * D_ + d];
    g_STATE[b * D_ + d] = acc;
}

// ---------------- residual + LayerNorm (optional fp16 shadow) ------------
__global__ void ln_kernel(const float* __restrict__ seq, const float* __restrict__ add,
                          const float* __restrict__ gamma, const float* __restrict__ beta,
                          float* __restrict__ out, int bcast, int writeh) {
    __shared__ float red[4];
    __shared__ float stat;
    int row = blockIdx.x;
    int b = row >> 11;
    int t = threadIdx.x;   // 128
    float4 x = ((const float4*)(seq + (size_t)row * D_))[t];
    const float* ap = bcast ? (g_STATE + (size_t)b * D_) : (add + (size_t)row * D_);
    float4 a4 = ((const float4*)ap)[t];
    x.x += a4.x; x.y += a4.y; x.z += a4.z; x.w += a4.w;

    float sum = x.x + x.y + x.z + x.w;
    for (int off = 16; off; off >>= 1) sum += __shfl_xor_sync(0xffffffffu, sum, off);
    if ((t & 31) == 0) red[t >> 5] = sum;
    __syncthreads();
    if (t == 0) stat = (red[0] + red[1] + red[2] + red[3]) * (1.f / D_);
    __syncthreads();
    float mu = stat;
    float d0 = x.x - mu, d1 = x.y - mu, d2 = x.z - mu, d3 = x.w - mu;
    float sq = d0*d0 + d1*d1 + d2*d2 + d3*d3;
    for (int off = 16; off; off >>= 1) sq += __shfl_xor_sync(0xffffffffu, sq, off);
    if ((t & 31) == 0) red[t >> 5] = sq;
    __syncthreads();
    if (t == 0) stat = rsqrtf((red[0] + red[1] + red[2] + red[3]) * (1.f / D_) + 1e-5f);
    __syncthreads();
    float rs = stat;
    float4 g = ((const float4*)gamma)[t], be = ((const float4*)beta)[t];
    float4 y;
    y.x = d0 * rs * g.x + be.x;
    y.y = d1 * rs * g.y + be.y;
    y.z = d2 * rs * g.z + be.z;
    y.w = d3 * rs * g.w + be.w;
    ((float4*)(out + (size_t)row * D_))[t] = y;
    if (writeh) {
        size_t o = (size_t)row * D_ + t * 4;
        *(__half2*)&g_SEQh[o]     = __floats2half2_rn(y.x, y.y);
        *(__half2*)&g_SEQh[o + 2] = __floats2half2_rn(y.z, y.w);
    }
}

// ---------------- banded flash attention, fp16 MMA, cp.async K/V pipe ---
#define ATT_STR 72
#define ATT_T   (64 * ATT_STR)
extern __shared__ __half s_att[];

__global__ void __launch_bounds__(128) attn_mma_kernel() {
    int b = blockIdx.z, h = blockIdx.y, q0 = blockIdx.x * 64;
    int tid = threadIdx.x, lane = tid & 31, w = tid >> 5;

    unsigned sQ = (unsigned)__cvta_generic_to_shared(s_att);

    int kstart = q0 - WIN_; if (kstart < 0) kstart = 0;
    int kend = q0 + 64 + WIN_; if (kend > L_) kend = L_;
    int nkt = (kend - kstart) >> 6;

    auto issue = [&](int t) {
        unsigned sk = sQ + (unsigned)(ATT_T * (1 + 2 * (t & 1))) * 2u;
        unsigned sv = sk + (unsigned)ATT_T * 2u;
        int k0 = kstart + t * 64;
#pragma unroll
        for (int j = 0; j < 4; j++) {
            int idx = tid + 128 * j;
            int r = idx >> 3, c = (idx & 7) * 8;
            size_t base = (size_t)(b * L_ + k0 + r) * (3 * D_) + h * DH_ + c;
            unsigned doff = (unsigned)(r * ATT_STR + c) * 2u;
            cpa16(sk + doff, g_QKVh + base + D_);
            cpa16(sv + doff, g_QKVh + base + 2 * D_);
        }
        cpa_commit();
    };

    issue(0);
#pragma unroll
    for (int j = 0; j < 4; j++) {
        int idx = tid + 128 * j;
        int r = idx >> 3, c = (idx & 7) * 8;
        *(uint4*)&s_att[r * ATT_STR + c] =
            *(const uint4*)(g_QKVh + (size_t)(b * L_ + q0 + r) * (3 * D_) + h * DH_ + c);
    }

    float m0 = -1e30f, m1 = -1e30f, l0s = 0.f, l1s = 0.f;
    float o[8][4];
#pragma unroll
    for (int j = 0; j < 8; j++)
#pragma unroll
        for (int r = 0; r < 4; r++) o[j][r] = 0.f;

    int qrow0 = 16 * w + (lane >> 2);

    for (int t = 0; t < nkt; t++) {
        if (t + 1 < nkt) { issue(t + 1); cpa_wait<1>(); }
        else             { cpa_wait<0>(); }
        __syncthreads();

        unsigned sK = sQ + (unsigned)(ATT_T * (1 + 2 * (t & 1))) * 2u;
        unsigned sV = sK + (unsigned)ATT_T * 2u;
        int k0 = kstart + t * 64;

        float sc[8][4];
#pragma unroll
        for (int j = 0; j < 8; j++)
#pragma unroll
            for (int r = 0; r < 4; r++) sc[j][r] = 0.f;

#pragma unroll
        for (int kk = 0; kk < 4; kk++) {
            unsigned aq[4];
            int qrow = 16 * w + (lane & 15);
            unsigned qoff = (unsigned)(qrow * ATT_STR + kk * 16 + (lane >> 4) * 8) * 2u;
            ldsm4(aq[0], aq[1], aq[2], aq[3], sQ + qoff);
#pragma unroll
            for (int nh = 0; nh < 4; nh++) {
                int krow = nh * 16 + (lane & 15);
                unsigned koff = (unsigned)(krow * ATT_STR + kk * 16 + (lane >> 4) * 8) * 2u;
                unsigned r0, r1, r2, r3;
                ldsm4(r0, r1, r2, r3, sK + koff);
                unsigned b0[2] = {r0, r2}, b1[2] = {r1, r3};
                mma16816(sc[2*nh],   aq, b0);
                mma16816(sc[2*nh+1], aq, b1);
            }
        }

        int q_a = q0 + qrow0, q_b = q_a + 8;
#pragma unroll
        for (int j = 0; j < 8; j++) {
#pragma unroll
            for (int r = 0; r < 4; r++) {
                int k = k0 + j * 8 + (lane & 3) * 2 + (r & 1);
                int q = (r < 2) ? q_a : q_b;
                int dlt = q - k; if (dlt < 0) dlt = -dlt;
                sc[j][r] = (dlt <= WIN_) ? sc[j][r] * 0.125f : -1e30f;
            }
        }
        float mx0 = -1e30f, mx1 = -1e30f;
#pragma unroll
        for (int j = 0; j < 8; j++) {
            mx0 = fmaxf(mx0, fmaxf(sc[j][0], sc[j][1]));
            mx1 = fmaxf(mx1, fmaxf(sc[j][2], sc[j][3]));
        }
        for (int off = 1; off < 4; off <<= 1) {
            mx0 = fmaxf(mx0, __shfl_xor_sync(0xffffffffu, mx0, off));
            mx1 = fmaxf(mx1, __shfl_xor_sync(0xffffffffu, mx1, off));
        }
        float mn0 = fmaxf(m0, mx0), mn1 = fmaxf(m1, mx1);
        float c0 = __expf(m0 - mn0), c1 = __expf(m1 - mn1);
        float rs0 = 0.f, rs1 = 0.f;
#pragma unroll
        for (int j = 0; j < 8; j++) {
            sc[j][0] = __expf(sc[j][0] - mn0);
            sc[j][1] = __expf(sc[j][1] - mn0);
            sc[j][2] = __expf(sc[j][2] - mn1);
            sc[j][3] = __expf(sc[j][3] - mn1);
            rs0 += sc[j][0] + sc[j][1];
            rs1 += sc[j][2] + sc[j][3];
        }
        for (int off = 1; off < 4; off <<= 1) {
            rs0 += __shfl_xor_sync(0xffffffffu, rs0, off);
            rs1 += __shfl_xor_sync(0xffffffffu, rs1, off);
        }
        l0s = l0s * c0 + rs0;
        l1s = l1s * c1 + rs1;
        m0 = mn0; m1 = mn1;
#pragma unroll
        for (int j = 0; j < 8; j++) {
            o[j][0] *= c0; o[j][1] *= c0;
            o[j][2] *= c1; o[j][3] *= c1;
        }

#pragma unroll
        for (int kc = 0; kc < 4; kc++) {
            unsigned ph[4];
            {
                __half2 p0 = __floats2half2_rn(sc[2*kc][0],   sc[2*kc][1]);
                __half2 p1 = __floats2half2_rn(sc[2*kc][2],   sc[2*kc][3]);
                __half2 p2 = __floats2half2_rn(sc[2*kc+1][0], sc[2*kc+1][1]);
                __half2 p3 = __floats2half2_rn(sc[2*kc+1][2], sc[2*kc+1][3]);
                ph[0] = *(unsigned*)&p0;
                ph[1] = *(unsigned*)&p1;
                ph[2] = *(unsigned*)&p2;
                ph[3] = *(unsigned*)&p3;
            }
#pragma unroll
            for (int nh = 0; nh < 4; nh++) {
                int vrow = kc * 16 + (lane & 15);
                unsigned voff = (unsigned)(vrow * ATT_STR + nh * 16 + (lane >> 4) * 8) * 2u;
                unsigned r0, r1, r2, r3;
                ldsm4t(r0, r1, r2, r3, sV + voff);
                unsigned b0[2] = {r0, r1}, b1[2] = {r2, r3};
                mma16816(o[2*nh],   ph, b0);
                mma16816(o[2*nh+1], ph, b1);
            }
        }
        __syncthreads();
    }

    float inv0 = 1.f / l0s, inv1 = 1.f / l1s;
    int qa = b * L_ + q0 + qrow0;
#pragma unroll
    for (int j = 0; j < 8; j++) {
        int c = h * DH_ + j * 8 + (lane & 3) * 2;
        *(__half2*)&g_ATTh[(size_t)qa * D_ + c] =
            __floats2half2_rn(o[j][0] * inv0, o[j][1] * inv0);
        *(__half2*)&g_ATTh[(size_t)(qa + 8) * D_ + c] =
            __floats2half2_rn(o[j][2] * inv1, o[j][3] * inv1);
    }
}

// ---------------- launcher ----------------
extern "C" void kernel_launch(void* const* d_in, const int* in_sizes, int n_in,
                              void* d_out, int out_size) {
    const float* context = (const float*)d_in[0];
    const float* conv_w  = (const float*)d_in[1];
    const float* Wx      = (const float*)d_in[2];
    const float* Wh      = (const float*)d_in[3];
    const float* Wout    = (const float*)d_in[4];
    const float* Aparam  = (const float*)d_in[5];
    const float* gm      = (const float*)d_in[6];
    const float* bm      = (const float*)d_in[7];
    const float* ga      = (const float*)d_in[8];
    const float* ba      = (const float*)d_in[9];
    const float* Wqkv    = (const float*)d_in[10];
    const float* bqkv    = (const float*)d_in[11];
    const float* Wo      = (const float*)d_in[12];
    const float* bo      = (const float*)d_in[13];
    float* out = (float*)d_out;

    static bool init = false;
    static void *pX, *pUh, *pXh, *pSEQh, *pQKVh, *pATTh, *pWxH, *pWqkvH, *pWoH;
    if (!init) {
        cudaGetSymbolAddress(&pX, g_X);
        cudaGetSymbolAddress(&pUh, g_Uh);
        cudaGetSymbolAddress(&pXh, g_Xh);
        cudaGetSymbolAddress(&pSEQh, g_SEQh);
        cudaGetSymbolAddress(&pQKVh, g_QKVh);
        cudaGetSymbolAddress(&pATTh, g_ATTh);
        cudaGetSymbolAddress(&pWxH, g_WxH);
        cudaGetSymbolAddress(&pWqkvH, g_WqkvH);
        cudaGetSymbolAddress(&pWoH, g_WoH);
        cudaFuncSetAttribute(attn_mma_kernel,
                             cudaFuncAttributeMaxDynamicSharedMemorySize,
                             5 * ATT_T * (int)sizeof(__half));
        cudaFuncSetAttribute(mma_gemm4<0>,
                             cudaFuncAttributeMaxDynamicSharedMemorySize,
                             (2 * GA_SZ + 2 * GB0_SZ) * (int)sizeof(__half));
        cudaFuncSetAttribute(mma_gemm4<1>,
                             cudaFuncAttributeMaxDynamicSharedMemorySize,
                             (2 * GA_SZ + 2 * GB1_SZ) * (int)sizeof(__half));
        init = true;
    }
    const int ATT_SMEM = 5 * ATT_T * (int)sizeof(__half);
    const int G0_SMEM  = (2 * GA_SZ + 2 * GB0_SZ) * (int)sizeof(__half);
    const int G1_SMEM  = (2 * GA_SZ + 2 * GB1_SZ) * (int)sizeof(__half);

    cvt_weights_all<<<(NWX + NWQ + NWO + 255) / 256, 256>>>(Wx, Wqkv, Wo);

    for (int i = 0; i < NL_; i++) {
        if (i == 0)
            conv_silu_f32<<<B_ * L_, 128>>>(context, conv_w);
        else
            conv_silu_f16<<<B_ * L_ / 2, 128>>>((const __half*)pSEQh,
                                                conv_w + (size_t)i * 3 * D_);
        mma_gemm4<0><<<dim3(S_ / 128, B_ * L_ / 128), 256, G0_SMEM>>>(
            (const __half*)pXh, (const __half*)pWxH + (size_t)i * D_ * S_,
            nullptr, nullptr, (__half*)pUh, B_ * L_, S_, D_);
        ht_part_kernel<<<dim3(B_, 128), 256>>>(Aparam + (size_t)i * S_);
        ht_fused_kernel<<<B_, 512>>>(Aparam + (size_t)i * S_, Wh + (size_t)i * D_ * S_,
                                     Wout + (size_t)i * S_ * D_, i == 0 ? 1 : 0);
        const float* seqin = (i == 0) ? context : out;
        ln_kernel<<<B_ * L_, 128>>>(seqin, nullptr, gm, bm, out, 1,
                                    i < 5 ? 1 : 0);

        if (((i + 1) % 4) == 0) {
            mma_gemm4<1><<<dim3(3 * D_ / 128, B_ * L_ / 128), 256, G1_SMEM>>>(
                (const __half*)pSEQh, (const __half*)pWqkvH,
                bqkv, nullptr, (__half*)pQKVh, B_ * L_, 3 * D_, D_);
            attn_mma_kernel<<<dim3(L_ / 64, H_, B_), 128, ATT_SMEM>>>();
            mma_gemm4<1><<<dim3(D_ / 128, B_ * L_ / 128), 256, G1_SMEM>>>(
                (const __half*)pATTh, (const __half*)pWoH,
                bo, (float*)pX, nullptr, B_ * L_, D_, D_);
            ln_kernel<<<B_ * L_, 128>>>(out, (const float*)pX, ga, ba, out, 0, 1);
        }
    }
}

// round 14
// speedup vs baseline: 1.7352x; 1.0287x over previous
#include <cuda_runtime.h>
#include <cuda_fp16.h>
#include <math.h>

#define B_   4
#define L_   2048
#define D_   512
#define S_   256
#define NL_  6
#define H_   8
#define DH_  64
#define WIN_ 256

// ---------------- scratch (device globals; no allocation) ----------------
__device__ float g_X[B_*L_*D_];         // out-proj fp32 scratch
__device__ float g_STATE[B_*D_];
__device__ float g_PART[128][B_][S_];

__device__ __half g_Uh[B_*L_*S_];       // mamba u (fp16)
__device__ __half g_Xh[B_*L_*D_];       // conv+silu output (fp16)
__device__ __half g_SEQh[B_*L_*D_];     // ln output fp16 shadow
__device__ __half g_QKVh[B_*L_*3*D_];   // qkv fp16
__device__ __half g_ATTh[B_*L_*D_];     // attention context fp16
__device__ __half g_WxH[NL_*D_*S_];     // [D][S]
__device__ __half g_WqkvH[3*D_*D_];     // [3D][D]
__device__ __half g_WoH[D_*D_];         // [D][D]

// ---------------- helpers ----------------
__device__ __forceinline__ void gds() {
    asm volatile("griddepcontrol.wait;" ::: "memory");
}
__device__ __forceinline__ void ldsm4(unsigned& r0, unsigned& r1, unsigned& r2, unsigned& r3, unsigned addr) {
    asm volatile("ldmatrix.sync.aligned.m8n8.x4.shared.b16 {%0,%1,%2,%3},[%4];"
                 : "=r"(r0), "=r"(r1), "=r"(r2), "=r"(r3) : "r"(addr));
}
__device__ __forceinline__ void ldsm4t(unsigned& r0, unsigned& r1, unsigned& r2, unsigned& r3, unsigned addr) {
    asm volatile("ldmatrix.sync.aligned.m8n8.x4.trans.shared.b16 {%0,%1,%2,%3},[%4];"
                 : "=r"(r0), "=r"(r1), "=r"(r2), "=r"(r3) : "r"(addr));
}
__device__ __forceinline__ void mma16816(float* c, const unsigned* a, const unsigned* b) {
    asm volatile("mma.sync.aligned.m16n8k16.row.col.f32.f16.f16.f32 "
                 "{%0,%1,%2,%3},{%4,%5,%6,%7},{%8,%9},{%0,%1,%2,%3};"
                 : "+f"(c[0]), "+f"(c[1]), "+f"(c[2]), "+f"(c[3])
                 : "r"(a[0]), "r"(a[1]), "r"(a[2]), "r"(a[3]), "r"(b[0]), "r"(b[1]));
}
__device__ __forceinline__ void cpa16(unsigned d, const void* s) {
    asm volatile("cp.async.cg.shared.global [%0],[%1],16;" :: "r"(d), "l"(s));
}
__device__ __forceinline__ void cpa_commit() {
    asm volatile("cp.async.commit_group;");
}
template <int N>
__device__ __forceinline__ void cpa_wait() {
    asm volatile("cp.async.wait_group %0;" :: "n"(N));
}

// ---------------- merged weight conversion ----------------
#define NWX (NL_*D_*S_)
#define NWQ (3*D_*D_)
#define NWO (D_*D_)
__global__ void cvt_weights_all(const float* __restrict__ Wx,
                                const float* __restrict__ Wqkv,
                                const float* __restrict__ Wo) {
    gds();
    int t = blockIdx.x * 256 + threadIdx.x;
    if (t < NWX) {
        g_WxH[t] = __float2half_rn(Wx[t]);
    } else if (t < NWX + NWQ) {
        int u = t - NWX;
        g_WqkvH[u] = __float2half_rn(Wqkv[u]);
    } else if (t < NWX + NWQ + NWO) {
        int u = t - NWX - NWQ;
        g_WoH[u] = __float2half_rn(Wo[u]);
    }
}

// ---------------- conv (k=3, causal) + SiLU -> fp16 ----------------
__global__ void conv_silu_f32(const float* __restrict__ seq,
                              const float* __restrict__ cw) {
    gds();
    int row = blockIdx.x;
    int l = row & (L_ - 1);
    int t = threadIdx.x;
    float4 z = make_float4(0.f, 0.f, 0.f, 0.f);
    float4 a0 = (l >= 2) ? ((const float4*)(seq + (size_t)(row - 2) * D_))[t] : z;
    float4 a1 = (l >= 1) ? ((const float4*)(seq + (size_t)(row - 1) * D_))[t] : z;
    float4 a2 = ((const float4*)(seq + (size_t)row * D_))[t];
    float4 w0 = ((const float4*)(cw        ))[t];
    float4 w1 = ((const float4*)(cw +   D_ ))[t];
    float4 w2 = ((const float4*)(cw + 2*D_ ))[t];
    float x0 = w0.x*a0.x + w1.x*a1.x + w2.x*a2.x;
    float x1 = w0.y*a0.y + w1.y*a1.y + w2.y*a2.y;
    float x2 = w0.z*a0.z + w1.z*a1.z + w2.z*a2.z;
    float x3 = w0.w*a0.w + w1.w*a1.w + w2.w*a2.w;
    x0 = x0 / (1.f + __expf(-x0));
    x1 = x1 / (1.f + __expf(-x1));
    x2 = x2 / (1.f + __expf(-x2));
    x3 = x3 / (1.f + __expf(-x3));
    size_t o = (size_t)row * D_ + t * 4;
    *(__half2*)&g_Xh[o]     = __floats2half2_rn(x0, x1);
    *(__half2*)&g_Xh[o + 2] = __floats2half2_rn(x2, x3);
}

__global__ void conv_silu_f16(const __half* __restrict__ seq,
                              const float* __restrict__ cw) {
    gds();
    int t = threadIdx.x;
    int row = blockIdx.x * 2 + (t >> 6);
    int tt = t & 63;
    int l = row & (L_ - 1);
    size_t base = (size_t)row * D_ + tt * 8;
    uint4 z4 = make_uint4(0u, 0u, 0u, 0u);
    uint4 v2 = *(const uint4*)(seq + base);
    uint4 v1 = (l >= 1) ? *(const uint4*)(seq + base - D_) : z4;
    uint4 v0 = (l >= 2) ? *(const uint4*)(seq + base - 2 * D_) : z4;
    float4 wa0 = ((const float4*)(cw        ))[tt * 2];
    float4 wb0 = ((const float4*)(cw        ))[tt * 2 + 1];
    float4 wa1 = ((const float4*)(cw +   D_ ))[tt * 2];
    float4 wb1 = ((const float4*)(cw +   D_ ))[tt * 2 + 1];
    float4 wa2 = ((const float4*)(cw + 2*D_ ))[tt * 2];
    float4 wb2 = ((const float4*)(cw + 2*D_ ))[tt * 2 + 1];
    float w0[8] = {wa0.x, wa0.y, wa0.z, wa0.w, wb0.x, wb0.y, wb0.z, wb0.w};
    float w1[8] = {wa1.x, wa1.y, wa1.z, wa1.w, wb1.x, wb1.y, wb1.z, wb1.w};
    float w2[8] = {wa2.x, wa2.y, wa2.z, wa2.w, wb2.x, wb2.y, wb2.z, wb2.w};
    const __half2* h0 = (const __half2*)&v0;
    const __half2* h1 = (const __half2*)&v1;
    const __half2* h2 = (const __half2*)&v2;
    uint4 outv;
    __half2* ov = (__half2*)&outv;
#pragma unroll
    for (int j = 0; j < 4; j++) {
        float2 f0 = __half22float2(h0[j]);
        float2 f1 = __half22float2(h1[j]);
        float2 f2 = __half22float2(h2[j]);
        float xa = w0[2*j]   * f0.x + w1[2*j]   * f1.x + w2[2*j]   * f2.x;
        float xb = w0[2*j+1] * f0.y + w1[2*j+1] * f1.y + w2[2*j+1] * f2.y;
        xa = xa / (1.f + __expf(-xa));
        xb = xb / (1.f + __expf(-xb));
        ov[j] = __floats2half2_rn(xa, xb);
    }
    *(uint4*)&g_Xh[base] = outv;
}

// ---------------- fp16 cp.async GEMM, 128x128 tile, K-chunk 64 ----------
#define GA_STR 72
#define GA_SZ  (128 * GA_STR)
#define GB1_SZ (128 * GA_STR)
#define GB0_SZ (64 * 136)
extern __shared__ __half smg[];

template <int TB>
__global__ void __launch_bounds__(256) mma_gemm4(const __half* __restrict__ A,
                                                 const __half* __restrict__ Bm,
                                                 const float* __restrict__ bias,
                                                 float* __restrict__ Cf,
                                                 __half* __restrict__ Ch,
                                                 int M, int N, int K) {
    gds();
    constexpr int BSZ = TB ? GB1_SZ : GB0_SZ;
    int bm = blockIdx.y * 128, bn = blockIdx.x * 128;
    int tid = threadIdx.x;
    int lane = tid & 31, wid = tid >> 5;
    int wm = (wid & 3) * 32;
    int wn = (wid >> 2) * 64;

    float acc[2][8][4];
#pragma unroll
    for (int i = 0; i < 2; i++)
#pragma unroll
        for (int j = 0; j < 8; j++)
#pragma unroll
            for (int k = 0; k < 4; k++) acc[i][j][k] = 0.f;

    unsigned sbase = (unsigned)__cvta_generic_to_shared(smg);

    int nk = K >> 6;
    auto issue = [&](int kt) {
        unsigned sa = sbase + (unsigned)((kt & 1) * GA_SZ) * 2u;
        unsigned sb = sbase + (unsigned)(2 * GA_SZ + (kt & 1) * BSZ) * 2u;
        int k0 = kt << 6;
#pragma unroll
        for (int j = 0; j < 4; j++) {
            int ch = tid + 256 * j;
            int r = ch >> 3, c8 = (ch & 7) * 8;
            cpa16(sa + (unsigned)(r * GA_STR + c8) * 2u,
                  A + (size_t)(bm + r) * K + k0 + c8);
        }
        if (TB == 1) {
#pragma unroll
            for (int j = 0; j < 4; j++) {
                int ch = tid + 256 * j;
                int r = ch >> 3, c8 = (ch & 7) * 8;
                cpa16(sb + (unsigned)(r * GA_STR + c8) * 2u,
                      Bm + (size_t)(bn + r) * K + k0 + c8);
            }
        } else {
#pragma unroll
            for (int j = 0; j < 4; j++) {
                int ch = tid + 256 * j;
                int r = ch >> 4, c8 = (ch & 15) * 8;
                cpa16(sb + (unsigned)(r * 136 + c8) * 2u,
                      Bm + (size_t)(k0 + r) * N + bn + c8);
            }
        }
        cpa_commit();
    };

    issue(0);
    for (int kt = 0; kt < nk; kt++) {
        if (kt + 1 < nk) { issue(kt + 1); cpa_wait<1>(); }
        else             { cpa_wait<0>(); }
        __syncthreads();

        unsigned sa = sbase + (unsigned)((kt & 1) * GA_SZ) * 2u;
        unsigned sb = sbase + (unsigned)(2 * GA_SZ + (kt & 1) * BSZ) * 2u;
#pragma unroll
        for (int ks = 0; ks < 4; ks++) {
            unsigned af[2][4], bf[8][2];
#pragma unroll
            for (int mi = 0; mi < 2; mi++) {
                int row = wm + mi * 16 + (lane & 15);
                unsigned off = (unsigned)(row * GA_STR + ks * 16 + (lane >> 4) * 8) * 2u;
                ldsm4(af[mi][0], af[mi][1], af[mi][2], af[mi][3], sa + off);
            }
            if (TB == 1) {
#pragma unroll
                for (int nh = 0; nh < 4; nh++) {
                    int row = wn + nh * 16 + (lane & 15);
                    unsigned off = (unsigned)(row * GA_STR + ks * 16 + (lane >> 4) * 8) * 2u;
                    unsigned r0, r1, r2, r3;
                    ldsm4(r0, r1, r2, r3, sb + off);
                    bf[nh*2+0][0] = r0; bf[nh*2+0][1] = r2;
                    bf[nh*2+1][0] = r1; bf[nh*2+1][1] = r3;
                }
            } else {
#pragma unroll
                for (int nh = 0; nh < 4; nh++) {
                    int row = ks * 16 + (lane & 15);
                    unsigned off = (unsigned)(row * 136 + wn + nh * 16 + (lane >> 4) * 8) * 2u;
                    unsigned r0, r1, r2, r3;
                    ldsm4t(r0, r1, r2, r3, sb + off);
                    bf[nh*2+0][0] = r0; bf[nh*2+0][1] = r1;
                    bf[nh*2+1][0] = r2; bf[nh*2+1][1] = r3;
                }
            }
#pragma unroll
            for (int mi = 0; mi < 2; mi++)
#pragma unroll
                for (int ni = 0; ni < 8; ni++)
                    mma16816(acc[mi][ni], af[mi], bf[ni]);
        }
        __syncthreads();
    }

#pragma unroll
    for (int mi = 0; mi < 2; mi++)
#pragma unroll
        for (int ni = 0; ni < 8; ni++) {
            int r = bm + wm + mi * 16 + (lane >> 2);
            int c = bn + wn + ni * 8 + (lane & 3) * 2;
            float b0 = bias ? bias[c] : 0.f;
            float b1 = bias ? bias[c + 1] : 0.f;
            float v00 = acc[mi][ni][0] + b0, v01 = acc[mi][ni][1] + b1;
            float v10 = acc[mi][ni][2] + b0, v11 = acc[mi][ni][3] + b1;
            if (Ch) {
                *(__half2*)&Ch[(size_t)r * N + c]       = __floats2half2_rn(v00, v01);
                *(__half2*)&Ch[(size_t)(r + 8) * N + c] = __floats2half2_rn(v10, v11);
            } else {
                Cf[(size_t)r * N + c]           = v00;
                Cf[(size_t)r * N + c + 1]       = v01;
                Cf[(size_t)(r + 8) * N + c]     = v10;
                Cf[(size_t)(r + 8) * N + c + 1] = v11;
            }
        }
}

// ---------------- ssm chunked Horner (chunks of 16, fp16 U) -------------
__global__ void ht_part_kernel(const float* __restrict__ Aparam) {
    gds();
    int b = blockIdx.x, c = blockIdx.y;   // 128 chunks of 16
    int s = threadIdx.x;                  // 256
    float a = 1.f / (1.f + expf(-Aparam[s]));
    float wt = powf(a, (float)(16 * (127 - c)));
    float wmax = wt;
    for (int off = 16; off; off >>= 1)
        wmax = fmaxf(wmax, __shfl_xor_sync(0xffffffffu, wmax, off));
    if (wmax < 1e-28f) { g_PART[c][b][s] = 0.f; return; }
    const __half* base = g_Uh + ((size_t)(b * L_) + c * 16) * S_ + s;
    float p = 0.f;
#pragma unroll
    for (int j = 0; j < 16; j++) p = p * a + __half2float(base[(size_t)j * S_]);
    g_PART[c][b][s] = p * wt;
}

// ---------------- fused ht_combine + stateout (split-half phase 1) -------
__global__ void __launch_bounds__(512) ht_fused_kernel(const float* __restrict__ Aparam,
                                                       const float* __restrict__ Wh,
                                                       const float* __restrict__ Wout,
                                                       int first) {
    gds();
    __shared__ float sh_h0[2][S_];
    __shared__ float sh_ps[2][S_];
    __shared__ float sh_ht[S_];
    int b = blockIdx.x;
    int tid = threadIdx.x;
    int s = tid & 255, half = tid >> 8;
    {
        float h0 = 0.f;
        if (!first) {
            int d0 = half * 256;
#pragma unroll 8
            for (int d = d0; d < d0 + 256; d++)
                h0 += g_STATE[b * D_ + d] * Wh[(size_t)d * S_ + s];
        }
        float ps = 0.f;
        int c0 = half * 64;
#pragma unroll
        for (int c = 0; c < 64; c++) ps += g_PART[c0 + c][b][s];
        sh_h0[half][s] = h0;
        sh_ps[half][s] = ps;
    }
    __syncthreads();
    if (tid < S_) {
        float a = 1.f / (1.f + expf(-Aparam[s]));
        sh_ht[s] = powf(a, (float)L_) * (sh_h0[0][s] + sh_h0[1][s])
                 + sh_ps[0][s] + sh_ps[1][s];
    }
    __syncthreads();
    int d = tid;
    float acc = 0.f;
#pragma unroll 8
    for (int ss = 0; ss < S_; ss++) acc += sh_ht[ss] * Wout[(size_t)ss * D_ + d];
    g_STATE[b * D_ + d] = acc;
}

// ---------------- residual + LayerNorm (optional fp16 shadow) ------------
__global__ void ln_kernel(const float* __restrict__ seq, const float* __restrict__ add,
                          const float* __restrict__ gamma, const float* __restrict__ beta,
                          float* __restrict__ out, int bcast, int writeh) {
    gds();
    __shared__ float red[4];
    __shared__ float stat;
    int row = blockIdx.x;
    int b = row >> 11;
    int t = threadIdx.x;   // 128
    float4 x = ((const float4*)(seq + (size_t)row * D_))[t];
    const float* ap = bcast ? (g_STATE + (size_t)b * D_) : (add + (size_t)row * D_);
    float4 a4 = ((const float4*)ap)[t];
    x.x += a4.x; x.y += a4.y; x.z += a4.z; x.w += a4.w;

    float sum = x.x + x.y + x.z + x.w;
    for (int off = 16; off; off >>= 1) sum += __shfl_xor_sync(0xffffffffu, sum, off);
    if ((t & 31) == 0) red[t >> 5] = sum;
    __syncthreads();
    if (t == 0) stat = (red[0] + red[1] + red[2] + red[3]) * (1.f / D_);
    __syncthreads();
    float mu = stat;
    float d0 = x.x - mu, d1 = x.y - mu, d2 = x.z - mu, d3 = x.w - mu;
    float sq = d0*d0 + d1*d1 + d2*d2 + d3*d3;
    for (int off = 16; off; off >>= 1) sq += __shfl_xor_sync(0xffffffffu, sq, off);
    if ((t & 31) == 0) red[t >> 5] = sq;
    __syncthreads();
    if (t == 0) stat = rsqrtf((red[0] + red[1] + red[2] + red[3]) * (1.f / D_) + 1e-5f);
    __syncthreads();
    float rs = stat;
    float4 g = ((const float4*)gamma)[t], be = ((const float4*)beta)[t];
    float4 y;
    y.x = d0 * rs * g.x + be.x;
    y.y = d1 * rs * g.y + be.y;
    y.z = d2 * rs * g.z + be.z;
    y.w = d3 * rs * g.w + be.w;
    ((float4*)(out + (size_t)row * D_))[t] = y;
    if (writeh) {
        size_t o = (size_t)row * D_ + t * 4;
        *(__half2*)&g_SEQh[o]     = __floats2half2_rn(y.x, y.y);
        *(__half2*)&g_SEQh[o + 2] = __floats2half2_rn(y.z, y.w);
    }
}

// ---------------- banded flash attention, fp16 MMA, cp.async K/V pipe ---
#define ATT_STR 72
#define ATT_T   (64 * ATT_STR)
extern __shared__ __half s_att[];

__global__ void __launch_bounds__(128) attn_mma_kernel() {
    gds();
    int b = blockIdx.z, h = blockIdx.y, q0 = blockIdx.x * 64;
    int tid = threadIdx.x, lane = tid & 31, w = tid >> 5;

    unsigned sQ = (unsigned)__cvta_generic_to_shared(s_att);

    int kstart = q0 - WIN_; if (kstart < 0) kstart = 0;
    int kend = q0 + 64 + WIN_; if (kend > L_) kend = L_;
    int nkt = (kend - kstart) >> 6;

    auto issue = [&](int t) {
        unsigned sk = sQ + (unsigned)(ATT_T * (1 + 2 * (t & 1))) * 2u;
        unsigned sv = sk + (unsigned)ATT_T * 2u;
        int k0 = kstart + t * 64;
#pragma unroll
        for (int j = 0; j < 4; j++) {
            int idx = tid + 128 * j;
            int r = idx >> 3, c = (idx & 7) * 8;
            size_t base = (size_t)(b * L_ + k0 + r) * (3 * D_) + h * DH_ + c;
            unsigned doff = (unsigned)(r * ATT_STR + c) * 2u;
            cpa16(sk + doff, g_QKVh + base + D_);
            cpa16(sv + doff, g_QKVh + base + 2 * D_);
        }
        cpa_commit();
    };

    issue(0);
#pragma unroll
    for (int j = 0; j < 4; j++) {
        int idx = tid + 128 * j;
        int r = idx >> 3, c = (idx & 7) * 8;
        *(uint4*)&s_att[r * ATT_STR + c] =
            *(const uint4*)(g_QKVh + (size_t)(b * L_ + q0 + r) * (3 * D_) + h * DH_ + c);
    }

    float m0 = -1e30f, m1 = -1e30f, l0s = 0.f, l1s = 0.f;
    float o[8][4];
#pragma unroll
    for (int j = 0; j < 8; j++)
#pragma unroll
        for (int r = 0; r < 4; r++) o[j][r] = 0.f;

    int qrow0 = 16 * w + (lane >> 2);

    for (int t = 0; t < nkt; t++) {
        if (t + 1 < nkt) { issue(t + 1); cpa_wait<1>(); }
        else             { cpa_wait<0>(); }
        __syncthreads();

        unsigned sK = sQ + (unsigned)(ATT_T * (1 + 2 * (t & 1))) * 2u;
        unsigned sV = sK + (unsigned)ATT_T * 2u;
        int k0 = kstart + t * 64;

        float sc[8][4];
#pragma unroll
        for (int j = 0; j < 8; j++)
#pragma unroll
            for (int r = 0; r < 4; r++) sc[j][r] = 0.f;

#pragma unroll
        for (int kk = 0; kk < 4; kk++) {
            unsigned aq[4];
            int qrow = 16 * w + (lane & 15);
            unsigned qoff = (unsigned)(qrow * ATT_STR + kk * 16 + (lane >> 4) * 8) * 2u;
            ldsm4(aq[0], aq[1], aq[2], aq[3], sQ + qoff);
#pragma unroll
            for (int nh = 0; nh < 4; nh++) {
                int krow = nh * 16 + (lane & 15);
                unsigned koff = (unsigned)(krow * ATT_STR + kk * 16 + (lane >> 4) * 8) * 2u;
                unsigned r0, r1, r2, r3;
                ldsm4(r0, r1, r2, r3, sK + koff);
                unsigned b0[2] = {r0, r2}, b1[2] = {r1, r3};
                mma16816(sc[2*nh],   aq, b0);
                mma16816(sc[2*nh+1], aq, b1);
            }
        }

        int q_a = q0 + qrow0, q_b = q_a + 8;
#pragma unroll
        for (int j = 0; j < 8; j++) {
#pragma unroll
            for (int r = 0; r < 4; r++) {
                int k = k0 + j * 8 + (lane & 3) * 2 + (r & 1);
                int q = (r < 2) ? q_a : q_b;
                int dlt = q - k; if (dlt < 0) dlt = -dlt;
                sc[j][r] = (dlt <= WIN_) ? sc[j][r] * 0.125f : -1e30f;
            }
        }
        float mx0 = -1e30f, mx1 = -1e30f;
#pragma unroll
        for (int j = 0; j < 8; j++) {
            mx0 = fmaxf(mx0, fmaxf(sc[j][0], sc[j][1]));
            mx1 = fmaxf(mx1, fmaxf(sc[j][2], sc[j][3]));
        }
        for (int off = 1; off < 4; off <<= 1) {
            mx0 = fmaxf(mx0, __shfl_xor_sync(0xffffffffu, mx0, off));
            mx1 = fmaxf(mx1, __shfl_xor_sync(0xffffffffu, mx1, off));
        }
        float mn0 = fmaxf(m0, mx0), mn1 = fmaxf(m1, mx1);
        float c0 = __expf(m0 - mn0), c1 = __expf(m1 - mn1);
        float rs0 = 0.f, rs1 = 0.f;
#pragma unroll
        for (int j = 0; j < 8; j++) {
            sc[j][0] = __expf(sc[j][0] - mn0);
            sc[j][1] = __expf(sc[j][1] - mn0);
            sc[j][2] = __expf(sc[j][2] - mn1);
            sc[j][3] = __expf(sc[j][3] - mn1);
            rs0 += sc[j][0] + sc[j][1];
            rs1 += sc[j][2] + sc[j][3];
        }
        for (int off = 1; off < 4; off <<= 1) {
            rs0 += __shfl_xor_sync(0xffffffffu, rs0, off);
            rs1 += __shfl_xor_sync(0xffffffffu, rs1, off);
        }
        l0s = l0s * c0 + rs0;
        l1s = l1s * c1 + rs1;
        m0 = mn0; m1 = mn1;
#pragma unroll
        for (int j = 0; j < 8; j++) {
            o[j][0] *= c0; o[j][1] *= c0;
            o[j][2] *= c1; o[j][3] *= c1;
        }

#pragma unroll
        for (int kc = 0; kc < 4; kc++) {
            unsigned ph[4];
            {
                __half2 p0 = __floats2half2_rn(sc[2*kc][0],   sc[2*kc][1]);
                __half2 p1 = __floats2half2_rn(sc[2*kc][2],   sc[2*kc][3]);
                __half2 p2 = __floats2half2_rn(sc[2*kc+1][0], sc[2*kc+1][1]);
                __half2 p3 = __floats2half2_rn(sc[2*kc+1][2], sc[2*kc+1][3]);
                ph[0] = *(unsigned*)&p0;
                ph[1] = *(unsigned*)&p1;
                ph[2] = *(unsigned*)&p2;
                ph[3] = *(unsigned*)&p3;
            }
#pragma unroll
            for (int nh = 0; nh < 4; nh++) {
                int vrow = kc * 16 + (lane & 15);
                unsigned voff = (unsigned)(vrow * ATT_STR + nh * 16 + (lane >> 4) * 8) * 2u;
                unsigned r0, r1, r2, r3;
                ldsm4t(r0, r1, r2, r3, sV + voff);
                unsigned b0[2] = {r0, r1}, b1[2] = {r2, r3};
                mma16816(o[2*nh],   ph, b0);
                mma16816(o[2*nh+1], ph, b1);
            }
        }
        __syncthreads();
    }

    float inv0 = 1.f / l0s, inv1 = 1.f / l1s;
    int qa = b * L_ + q0 + qrow0;
#pragma unroll
    for (int j = 0; j < 8; j++) {
        int c = h * DH_ + j * 8 + (lane & 3) * 2;
        *(__half2*)&g_ATTh[(size_t)qa * D_ + c] =
            __floats2half2_rn(o[j][0] * inv0, o[j][1] * inv0);
        *(__half2*)&g_ATTh[(size_t)(qa + 8) * D_ + c] =
            __floats2half2_rn(o[j][2] * inv1, o[j][3] * inv1);
    }
}

// ---------------- PDL launch helper ----------------
#define PDL_LAUNCH(kern, grid, block, smem, ...) do {                         \
    cudaLaunchConfig_t _cfg = {};                                             \
    _cfg.gridDim = (grid); _cfg.blockDim = (block);                           \
    _cfg.dynamicSmemBytes = (smem);                                           \
    cudaLaunchAttribute _at[1];                                               \
    _at[0].id = cudaLaunchAttributeProgrammaticStreamSerialization;           \
    _at[0].val.programmaticStreamSerializationAllowed = 1;                    \
    _cfg.attrs = _at; _cfg.numAttrs = 1;                                      \
    cudaLaunchKernelEx(&_cfg, kern, ##__VA_ARGS__);                           \
} while (0)

// ---------------- launcher ----------------
extern "C" void kernel_launch(void* const* d_in, const int* in_sizes, int n_in,
                              void* d_out, int out_size) {
    const float* context = (const float*)d_in[0];
    const float* conv_w  = (const float*)d_in[1];
    const float* Wx      = (const float*)d_in[2];
    const float* Wh      = (const float*)d_in[3];
    const float* Wout    = (const float*)d_in[4];
    const float* Aparam  = (const float*)d_in[5];
    const float* gm      = (const float*)d_in[6];
    const float* bm      = (const float*)d_in[7];
    const float* ga      = (const float*)d_in[8];
    const float* ba      = (const float*)d_in[9];
    const float* Wqkv    = (const float*)d_in[10];
    const float* bqkv    = (const float*)d_in[11];
    const float* Wo      = (const float*)d_in[12];
    const float* bo      = (const float*)d_in[13];
    float* out = (float*)d_out;

    static bool init = false;
    static void *pX, *pUh, *pXh, *pSEQh, *pQKVh, *pATTh, *pWxH, *pWqkvH, *pWoH;
    if (!init) {
        cudaGetSymbolAddress(&pX, g_X);
        cudaGetSymbolAddress(&pUh, g_Uh);
        cudaGetSymbolAddress(&pXh, g_Xh);
        cudaGetSymbolAddress(&pSEQh, g_SEQh);
        cudaGetSymbolAddress(&pQKVh, g_QKVh);
        cudaGetSymbolAddress(&pATTh, g_ATTh);
        cudaGetSymbolAddress(&pWxH, g_WxH);
        cudaGetSymbolAddress(&pWqkvH, g_WqkvH);
        cudaGetSymbolAddress(&pWoH, g_WoH);
        cudaFuncSetAttribute(attn_mma_kernel,
                             cudaFuncAttributeMaxDynamicSharedMemorySize,
                             5 * ATT_T * (int)sizeof(__half));
        cudaFuncSetAttribute(mma_gemm4<0>,
                             cudaFuncAttributeMaxDynamicSharedMemorySize,
                             (2 * GA_SZ + 2 * GB0_SZ) * (int)sizeof(__half));
        cudaFuncSetAttribute(mma_gemm4<1>,
                             cudaFuncAttributeMaxDynamicSharedMemorySize,
                             (2 * GA_SZ + 2 * GB1_SZ) * (int)sizeof(__half));
        init = true;
    }
    const size_t ATT_SMEM = 5 * ATT_T * sizeof(__half);
    const size_t G0_SMEM  = (2 * GA_SZ + 2 * GB0_SZ) * sizeof(__half);
    const size_t G1_SMEM  = (2 * GA_SZ + 2 * GB1_SZ) * sizeof(__half);

    PDL_LAUNCH(cvt_weights_all, dim3((NWX + NWQ + NWO + 255) / 256), dim3(256), 0,
               Wx, Wqkv, Wo);

    for (int i = 0; i < NL_; i++) {
        if (i == 0)
            PDL_LAUNCH(conv_silu_f32, dim3(B_ * L_), dim3(128), 0, context, conv_w);
        else
            PDL_LAUNCH(conv_silu_f16, dim3(B_ * L_ / 2), dim3(128), 0,
                       (const __half*)pSEQh, conv_w + (size_t)i * 3 * D_);
        PDL_LAUNCH(mma_gemm4<0>, dim3(S_ / 128, B_ * L_ / 128), dim3(256), G0_SMEM,
                   (const __half*)pXh, (const __half*)pWxH + (size_t)i * D_ * S_,
                   (const float*)nullptr, (float*)nullptr, (__half*)pUh,
                   B_ * L_, S_, D_);
        PDL_LAUNCH(ht_part_kernel, dim3(B_, 128), dim3(256), 0,
                   Aparam + (size_t)i * S_);
        PDL_LAUNCH(ht_fused_kernel, dim3(B_), dim3(512), 0,
                   Aparam + (size_t)i * S_, Wh + (size_t)i * D_ * S_,
                   Wout + (size_t)i * S_ * D_, i == 0 ? 1 : 0);
        const float* seqin = (i == 0) ? context : out;
        PDL_LAUNCH(ln_kernel, dim3(B_ * L_), dim3(128), 0,
                   seqin, (const float*)nullptr, gm, bm, out, 1, i < 5 ? 1 : 0);

        if (((i + 1) % 4) == 0) {
            PDL_LAUNCH(mma_gemm4<1>, dim3(3 * D_ / 128, B_ * L_ / 128), dim3(256), G1_SMEM,
                       (const __half*)pSEQh, (const __half*)pWqkvH,
                       bqkv, (float*)nullptr, (__half*)pQKVh, B_ * L_, 3 * D_, D_);
            PDL_LAUNCH(attn_mma_kernel, dim3(L_ / 64, H_, B_), dim3(128), ATT_SMEM);
            PDL_LAUNCH(mma_gemm4<1>, dim3(D_ / 128, B_ * L_ / 128), dim3(256), G1_SMEM,
                       (const __half*)pATTh, (const __half*)pWoH,
                       bo, (float*)pX, (__half*)nullptr, B_ * L_, D_, D_);
            PDL_LAUNCH(ln_kernel, dim3(B_ * L_), dim3(128), 0,
                       out, (const float*)pX, ga, ba, out, 0, 1);
        }
    }
}